// round 1
// baseline (speedup 1.0000x reference)
#include <cuda_runtime.h>
#include <math.h>

// Problem constants
#define B_    2
#define D_    8
#define H_    64
#define W_    128   /* unused name guard */
#define WIMG  64
#define C_    128
#define NH_   8
#define HD_   16
#define NTOK  65536        // B*D*H*W
#define NWIN  512          // B * (D/2)*(H/8)*(W/8) = 2*256
#define NPW   256          // windows per batch
#define NN_   128          // tokens per window
#define MLPH  512

// ---------------- scratch (device globals; no runtime allocation) -----------
__device__ float g_win[NWIN * NN_ * C_];        // LN1(shifted x), window layout
__device__ float g_qkv[(long)NWIN * NN_ * 3 * C_];
__device__ float g_bias[NH_ * NN_ * NN_];       // rel-pos bias table
__device__ float g_attnout[NWIN * NN_ * C_];
__device__ float g_projout[NWIN * NN_ * C_];
__device__ float g_x1[NTOK * C_];
__device__ float g_xn2[NTOK * C_];
__device__ float g_hid[(long)NTOK * MLPH];

__device__ __forceinline__ float gelu_exact(float x) {
    return 0.5f * x * (1.0f + erff(x * 0.70710678118654752f));
}

// ---------------- K1: LN1 + cyclic shift + window partition (gather) --------
// one warp per output token (bw, n)
__global__ void ln_gather_kernel(const float* __restrict__ x,
                                 const float* __restrict__ g,
                                 const float* __restrict__ b) {
    int warp = (blockIdx.x * blockDim.x + threadIdx.x) >> 5;
    int lane = threadIdx.x & 31;
    if (warp >= NWIN * NN_) return;
    int bw = warp >> 7;
    int n  = warp & 127;
    int bb = bw >> 8;
    int wi = bw & 255;
    int wd = wi >> 6, wh = (wi >> 3) & 7, ww = wi & 7;
    int td = n >> 6,  th = (n >> 3) & 7, tw = n & 7;
    int gd = (wd * 2 + td + 1) & 7;       // roll by -1 on D
    int gh = (wh * 8 + th + 4) & 63;      // roll by -4 on H
    int gw = (ww * 8 + tw + 4) & 63;      // roll by -4 on W
    long src = (((long)(bb * D_ + gd) * 64 + gh) * 64 + gw) * C_;

    float4 v = *(const float4*)(x + src + lane * 4);
    float s  = v.x + v.y + v.z + v.w;
    float sq = v.x * v.x + v.y * v.y + v.z * v.z + v.w * v.w;
#pragma unroll
    for (int o = 16; o > 0; o >>= 1) {
        s  += __shfl_xor_sync(0xffffffffu, s, o);
        sq += __shfl_xor_sync(0xffffffffu, sq, o);
    }
    float mean = s * (1.0f / C_);
    float var  = sq * (1.0f / C_) - mean * mean;
    float inv  = rsqrtf(var + 1e-5f);
    float4 gg = *(const float4*)(g + lane * 4);
    float4 bv = *(const float4*)(b + lane * 4);
    float4 o4;
    o4.x = (v.x - mean) * inv * gg.x + bv.x;
    o4.y = (v.y - mean) * inv * gg.y + bv.y;
    o4.z = (v.z - mean) * inv * gg.z + bv.z;
    o4.w = (v.w - mean) * inv * gg.w + bv.w;
    *(float4*)(g_win + (long)warp * C_ + lane * 4) = o4;
}

// ---------------- K2: relative position bias table ---------------------------
__global__ void bias_kernel(const float* __restrict__ rpb) {
    int n = blockIdx.x;
    int m = threadIdx.x;
    int nd = n >> 6, nh = (n >> 3) & 7, nw = n & 7;
    int md = m >> 6, mh = (m >> 3) & 7, mw = m & 7;
    int rpi = (nd - md + 1) * 225 + (nh - mh + 7) * 15 + (nw - mw + 7);
#pragma unroll
    for (int h = 0; h < NH_; h++)
        g_bias[((long)h * NN_ + n) * NN_ + m] = rpb[rpi * NH_ + h];
}

// ---------------- K3: attention per (window, head) ---------------------------
// 128 threads; thread n owns query row n. k/v in smem, probs in padded smem.
__global__ void attn_kernel() {
    extern __shared__ float sm[];
    float* k_s = sm;                 // 128*16
    float* v_s = sm + 2048;          // 128*16
    float* p   = sm + 4096;          // 128*129
    int*   lab = (int*)(sm + 4096 + 128 * 129);

    int bw = blockIdx.x >> 3;
    int h  = blockIdx.x & 7;
    int n  = threadIdx.x;

    long base = ((long)bw * NN_ + n) * 384;
    const float* qp = g_qkv + base + h * 16;
    float4 q0 = *(const float4*)(qp + 0);
    float4 q1 = *(const float4*)(qp + 4);
    float4 q2 = *(const float4*)(qp + 8);
    float4 q3 = *(const float4*)(qp + 12);

#pragma unroll
    for (int j = 0; j < 4; j++) {
        ((float4*)k_s)[n * 4 + j] = *(const float4*)(g_qkv + base + 128 + h * 16 + j * 4);
        ((float4*)v_s)[n * 4 + j] = *(const float4*)(g_qkv + base + 256 + h * 16 + j * 4);
    }
    // region label for the shift-mask (analytic)
    {
        int wi = bw & 255;
        int sd = (wi >> 6) * 2 + (n >> 6);
        int sh = ((wi >> 3) & 7) * 8 + ((n >> 3) & 7);
        int sw = (wi & 7) * 8 + (n & 7);
        int ld = sd < 6 ? 0 : (sd < 7 ? 1 : 2);
        int lh = sh < 56 ? 0 : (sh < 60 ? 1 : 2);
        int lw = sw < 56 ? 0 : (sw < 60 ? 1 : 2);
        lab[n] = ld * 9 + lh * 3 + lw;
    }
    __syncthreads();

    const float* brow = g_bias + ((long)h * NN_ + n) * NN_;
    int myl = lab[n];
    float* prow = p + n * 129;
    float mx = -1e30f;
#pragma unroll 4
    for (int m = 0; m < NN_; m++) {
        float4 k0 = ((const float4*)k_s)[m * 4 + 0];
        float4 k1 = ((const float4*)k_s)[m * 4 + 1];
        float4 k2 = ((const float4*)k_s)[m * 4 + 2];
        float4 k3 = ((const float4*)k_s)[m * 4 + 3];
        float s = q0.x * k0.x + q0.y * k0.y + q0.z * k0.z + q0.w * k0.w
                + q1.x * k1.x + q1.y * k1.y + q1.z * k1.z + q1.w * k1.w
                + q2.x * k2.x + q2.y * k2.y + q2.z * k2.z + q2.w * k2.w
                + q3.x * k3.x + q3.y * k3.y + q3.z * k3.z + q3.w * k3.w;
        s = s * 0.25f + brow[m];
        if (lab[m] != myl) s -= 100.0f;
        prow[m] = s;
        mx = fmaxf(mx, s);
    }
    float sum = 0.0f;
#pragma unroll 4
    for (int m = 0; m < NN_; m++) {
        float e = __expf(prow[m] - mx);
        prow[m] = e;
        sum += e;
    }
    float rs = 1.0f / sum;

    float acc[16];
#pragma unroll
    for (int j = 0; j < 16; j++) acc[j] = 0.0f;
#pragma unroll 4
    for (int m = 0; m < NN_; m++) {
        float pm = prow[m];
        float4 v0 = ((const float4*)v_s)[m * 4 + 0];
        float4 v1 = ((const float4*)v_s)[m * 4 + 1];
        float4 v2 = ((const float4*)v_s)[m * 4 + 2];
        float4 v3 = ((const float4*)v_s)[m * 4 + 3];
        acc[0]  += pm * v0.x; acc[1]  += pm * v0.y; acc[2]  += pm * v0.z; acc[3]  += pm * v0.w;
        acc[4]  += pm * v1.x; acc[5]  += pm * v1.y; acc[6]  += pm * v1.z; acc[7]  += pm * v1.w;
        acc[8]  += pm * v2.x; acc[9]  += pm * v2.y; acc[10] += pm * v2.z; acc[11] += pm * v2.w;
        acc[12] += pm * v3.x; acc[13] += pm * v3.y; acc[14] += pm * v3.z; acc[15] += pm * v3.w;
    }
    float* op = g_attnout + ((long)bw * NN_ + n) * C_ + h * 16;
#pragma unroll
    for (int j = 0; j < 4; j++) {
        float4 o4;
        o4.x = acc[j * 4 + 0] * rs;
        o4.y = acc[j * 4 + 1] * rs;
        o4.z = acc[j * 4 + 2] * rs;
        o4.w = acc[j * 4 + 3] * rs;
        *(float4*)(op + j * 4) = o4;
    }
}

// ---------------- generic SGEMM: C = act(A @ W^T + bias) (+ res) -------------
// A (M,K) row-major, W (N,K) row-major. BM=128 BN=64 BK=16, 256 thr, 8x4 uTile.
template <int ACT, bool RES>
__global__ void __launch_bounds__(256)
gemm_kernel(const float* __restrict__ A, const float* __restrict__ Wt,
            const float* __restrict__ bias, const float* __restrict__ res,
            float* __restrict__ C, int M, int N, int K) {
    __shared__ float As[16][128];
    __shared__ float Ws[16][64];
    int tid = threadIdx.x;
    int m0 = blockIdx.y * 128;
    int n0 = blockIdx.x * 64;
    int tn = tid & 15, tm = tid >> 4;

    float acc[8][4];
#pragma unroll
    for (int i = 0; i < 8; i++)
#pragma unroll
        for (int j = 0; j < 4; j++) acc[i][j] = 0.0f;

    for (int k0 = 0; k0 < K; k0 += 16) {
#pragma unroll
        for (int it = 0; it < 2; it++) {
            int lin = tid + it * 256;
            int m = lin >> 2;
            int kk = (lin & 3) * 4;
            float4 v = *(const float4*)(A + (long)(m0 + m) * K + k0 + kk);
            As[kk + 0][m] = v.x; As[kk + 1][m] = v.y;
            As[kk + 2][m] = v.z; As[kk + 3][m] = v.w;
        }
        {
            int nn = tid >> 2;
            int kk = (tid & 3) * 4;
            float4 v = *(const float4*)(Wt + (long)(n0 + nn) * K + k0 + kk);
            Ws[kk + 0][nn] = v.x; Ws[kk + 1][nn] = v.y;
            Ws[kk + 2][nn] = v.z; Ws[kk + 3][nn] = v.w;
        }
        __syncthreads();
#pragma unroll
        for (int k = 0; k < 16; k++) {
            float4 a0 = *(const float4*)(&As[k][tm * 8]);
            float4 a1 = *(const float4*)(&As[k][tm * 8 + 4]);
            float4 b0 = *(const float4*)(&Ws[k][tn * 4]);
            float av[8] = {a0.x, a0.y, a0.z, a0.w, a1.x, a1.y, a1.z, a1.w};
            float bv[4] = {b0.x, b0.y, b0.z, b0.w};
#pragma unroll
            for (int i = 0; i < 8; i++)
#pragma unroll
                for (int j = 0; j < 4; j++)
                    acc[i][j] = fmaf(av[i], bv[j], acc[i][j]);
        }
        __syncthreads();
    }

    float4 bz = *(const float4*)(bias + n0 + tn * 4);
#pragma unroll
    for (int i = 0; i < 8; i++) {
        int cm = m0 + tm * 8 + i;
        float4 o;
        o.x = acc[i][0] + bz.x;
        o.y = acc[i][1] + bz.y;
        o.z = acc[i][2] + bz.z;
        o.w = acc[i][3] + bz.w;
        if (ACT == 1) {
            o.x = gelu_exact(o.x); o.y = gelu_exact(o.y);
            o.z = gelu_exact(o.z); o.w = gelu_exact(o.w);
        }
        if (RES) {
            float4 r = *(const float4*)(res + (long)cm * N + n0 + tn * 4);
            o.x += r.x; o.y += r.y; o.z += r.z; o.w += r.w;
        }
        *(float4*)(C + (long)cm * N + n0 + tn * 4) = o;
    }
}

// -------- K6: window-reverse + roll + residual + LN2 (warp per token) --------
__global__ void scatter_ln2_kernel(const float* __restrict__ x,
                                   const float* __restrict__ g2,
                                   const float* __restrict__ b2) {
    int t = (blockIdx.x * blockDim.x + threadIdx.x) >> 5;
    int lane = threadIdx.x & 31;
    if (t >= NTOK) return;
    int w = t & 63, h = (t >> 6) & 63, d = (t >> 12) & 7, bb = t >> 15;
    int sd = (d + 7) & 7;     // roll back by +1
    int sh = (h + 60) & 63;   // roll back by +4
    int sw = (w + 60) & 63;
    int bw = bb * 256 + (sd >> 1) * 64 + (sh >> 3) * 8 + (sw >> 3);
    int n  = (sd & 1) * 64 + (sh & 7) * 8 + (sw & 7);

    float4 xv = *(const float4*)(x + (long)t * C_ + lane * 4);
    float4 pv = *(const float4*)(g_projout + ((long)bw * NN_ + n) * C_ + lane * 4);
    float4 s1;
    s1.x = xv.x + pv.x; s1.y = xv.y + pv.y;
    s1.z = xv.z + pv.z; s1.w = xv.w + pv.w;
    *(float4*)(g_x1 + (long)t * C_ + lane * 4) = s1;

    float s  = s1.x + s1.y + s1.z + s1.w;
    float sq = s1.x * s1.x + s1.y * s1.y + s1.z * s1.z + s1.w * s1.w;
#pragma unroll
    for (int o = 16; o > 0; o >>= 1) {
        s  += __shfl_xor_sync(0xffffffffu, s, o);
        sq += __shfl_xor_sync(0xffffffffu, sq, o);
    }
    float mean = s * (1.0f / C_);
    float var  = sq * (1.0f / C_) - mean * mean;
    float inv  = rsqrtf(var + 1e-5f);
    float4 gg = *(const float4*)(g2 + lane * 4);
    float4 bv = *(const float4*)(b2 + lane * 4);
    float4 o4;
    o4.x = (s1.x - mean) * inv * gg.x + bv.x;
    o4.y = (s1.y - mean) * inv * gg.y + bv.y;
    o4.z = (s1.z - mean) * inv * gg.z + bv.z;
    o4.w = (s1.w - mean) * inv * gg.w + bv.w;
    *(float4*)(g_xn2 + (long)t * C_ + lane * 4) = o4;
}

// ---------------------------------------------------------------------------
extern "C" void kernel_launch(void* const* d_in, const int* in_sizes, int n_in,
                              void* d_out, int out_size) {
    const float* x      = (const float*)d_in[0];
    const float* qkv_w  = (const float*)d_in[1];
    const float* qkv_b  = (const float*)d_in[2];
    const float* proj_w = (const float*)d_in[3];
    const float* proj_b = (const float*)d_in[4];
    const float* rpb    = (const float*)d_in[5];
    const float* ln1_g  = (const float*)d_in[6];
    const float* ln1_b  = (const float*)d_in[7];
    const float* ln2_g  = (const float*)d_in[8];
    const float* ln2_b  = (const float*)d_in[9];
    const float* fc1_w  = (const float*)d_in[10];
    const float* fc1_b  = (const float*)d_in[11];
    const float* fc2_w  = (const float*)d_in[12];
    const float* fc2_b  = (const float*)d_in[13];
    float* out = (float*)d_out;

    float *p_win, *p_qkv, *p_attnout, *p_projout, *p_x1, *p_xn2, *p_hid;
    cudaGetSymbolAddress((void**)&p_win,     g_win);
    cudaGetSymbolAddress((void**)&p_qkv,     g_qkv);
    cudaGetSymbolAddress((void**)&p_attnout, g_attnout);
    cudaGetSymbolAddress((void**)&p_projout, g_projout);
    cudaGetSymbolAddress((void**)&p_x1,      g_x1);
    cudaGetSymbolAddress((void**)&p_xn2,     g_xn2);
    cudaGetSymbolAddress((void**)&p_hid,     g_hid);

    const int ATTN_SMEM = (2048 + 2048 + 128 * 129 + 128) * 4;  // 82944 B
    cudaFuncSetAttribute(attn_kernel, cudaFuncAttributeMaxDynamicSharedMemorySize,
                         ATTN_SMEM);

    // 1) LN1 + shift + partition
    ln_gather_kernel<<<8192, 256>>>(x, ln1_g, ln1_b);
    // 2) QKV GEMM (65536 x 384 x 128)
    gemm_kernel<0, false><<<dim3(384 / 64, NTOK / 128), 256>>>(
        p_win, qkv_w, qkv_b, nullptr, p_qkv, NTOK, 384, 128);
    // 3) bias table
    bias_kernel<<<128, 128>>>(rpb);
    // 4) attention (window, head)
    attn_kernel<<<NWIN * NH_, 128, ATTN_SMEM>>>();
    // 5) proj GEMM (65536 x 128 x 128)
    gemm_kernel<0, false><<<dim3(128 / 64, NTOK / 128), 256>>>(
        p_attnout, proj_w, proj_b, nullptr, p_projout, NTOK, 128, 128);
    // 6) reverse + roll + residual + LN2
    scatter_ln2_kernel<<<8192, 256>>>(x, ln2_g, ln2_b);
    // 7) fc1 + GELU (65536 x 512 x 128)
    gemm_kernel<1, false><<<dim3(512 / 64, NTOK / 128), 256>>>(
        p_xn2, fc1_w, fc1_b, nullptr, p_hid, NTOK, 512, 128);
    // 8) fc2 + residual -> out (65536 x 128 x 512)
    gemm_kernel<0, true><<<dim3(128 / 64, NTOK / 128), 256>>>(
        p_hid, fc2_w, fc2_b, p_x1, out, NTOK, 128, 512);
}

// round 2
// speedup vs baseline: 1.4116x; 1.4116x over previous
#include <cuda_runtime.h>
#include <math.h>

typedef unsigned long long ull;

// Problem constants
#define B_    2
#define D_    8
#define C_    128
#define NH_   8
#define NTOK  65536        // B*D*H*W
#define NWIN  512
#define NN_   128          // tokens per window
#define MLPH  512

// ---------------- scratch (device globals) -----------------------------------
__device__ float g_win[NWIN * NN_ * C_];
__device__ float g_qkv[(long)NWIN * NN_ * 3 * C_];
__device__ float g_bias[NH_ * NN_ * NN_];       // layout [h][m(key)][n(query)]
__device__ float g_attnout[NWIN * NN_ * C_];
__device__ float g_projout[NWIN * NN_ * C_];
__device__ float g_x1[NTOK * C_];
__device__ float g_xn2[NTOK * C_];
__device__ float g_hid[(long)NTOK * MLPH];

__device__ __forceinline__ float gelu_exact(float x) {
    return 0.5f * x * (1.0f + erff(x * 0.70710678118654752f));
}

// ---- f32x2 packed helpers (sm_100+) ------------------------------------------
__device__ __forceinline__ ull ffma2(ull a, ull b, ull c) {
    ull d;
    asm("fma.rn.f32x2 %0, %1, %2, %3;" : "=l"(d) : "l"(a), "l"(b), "l"(c));
    return d;
}
__device__ __forceinline__ ull fmul2(ull a, ull b) {
    ull d;
    asm("mul.rn.f32x2 %0, %1, %2;" : "=l"(d) : "l"(a), "l"(b));
    return d;
}
__device__ __forceinline__ ull dup2(float x) {
    ull d;
    asm("mov.b64 %0, {%1, %1};" : "=l"(d) : "f"(x));
    return d;
}
__device__ __forceinline__ float2 unpack2(ull v) {
    float2 r;
    asm("mov.b64 {%0, %1}, %2;" : "=f"(r.x), "=f"(r.y) : "l"(v));
    return r;
}
__device__ __forceinline__ ull pack2(float lo, float hi) {
    ull d;
    asm("mov.b64 %0, {%1, %2};" : "=l"(d) : "f"(lo), "f"(hi));
    return d;
}

// ---------------- K1: LN1 + cyclic shift + window partition ------------------
__global__ void ln_gather_kernel(const float* __restrict__ x,
                                 const float* __restrict__ g,
                                 const float* __restrict__ b) {
    int warp = (blockIdx.x * blockDim.x + threadIdx.x) >> 5;
    int lane = threadIdx.x & 31;
    if (warp >= NWIN * NN_) return;
    int bw = warp >> 7;
    int n  = warp & 127;
    int bb = bw >> 8;
    int wi = bw & 255;
    int wd = wi >> 6, wh = (wi >> 3) & 7, ww = wi & 7;
    int td = n >> 6,  th = (n >> 3) & 7, tw = n & 7;
    int gd = (wd * 2 + td + 1) & 7;
    int gh = (wh * 8 + th + 4) & 63;
    int gw = (ww * 8 + tw + 4) & 63;
    long src = (((long)(bb * D_ + gd) * 64 + gh) * 64 + gw) * C_;

    float4 v = *(const float4*)(x + src + lane * 4);
    float s  = v.x + v.y + v.z + v.w;
    float sq = v.x * v.x + v.y * v.y + v.z * v.z + v.w * v.w;
#pragma unroll
    for (int o = 16; o > 0; o >>= 1) {
        s  += __shfl_xor_sync(0xffffffffu, s, o);
        sq += __shfl_xor_sync(0xffffffffu, sq, o);
    }
    float mean = s * (1.0f / C_);
    float var  = sq * (1.0f / C_) - mean * mean;
    float inv  = rsqrtf(var + 1e-5f);
    float4 gg = *(const float4*)(g + lane * 4);
    float4 bv = *(const float4*)(b + lane * 4);
    float4 o4;
    o4.x = (v.x - mean) * inv * gg.x + bv.x;
    o4.y = (v.y - mean) * inv * gg.y + bv.y;
    o4.z = (v.z - mean) * inv * gg.z + bv.z;
    o4.w = (v.w - mean) * inv * gg.w + bv.w;
    *(float4*)(g_win + (long)warp * C_ + lane * 4) = o4;
}

// ---------------- K2: relative position bias table (transposed) --------------
__global__ void bias_kernel(const float* __restrict__ rpb) {
    int n = blockIdx.x;    // query
    int m = threadIdx.x;   // key
    int nd = n >> 6, nh = (n >> 3) & 7, nw = n & 7;
    int md = m >> 6, mh = (m >> 3) & 7, mw = m & 7;
    int rpi = (nd - md + 1) * 225 + (nh - mh + 7) * 15 + (nw - mw + 7);
#pragma unroll
    for (int h = 0; h < NH_; h++)
        g_bias[((long)h * NN_ + m) * NN_ + n] = rpb[rpi * NH_ + h];
}

// ---------------- K3: attention per (window, head), online softmax -----------
__global__ void __launch_bounds__(128) attn_kernel() {
    __shared__ float k_s[NN_ * 16];
    __shared__ float v_s[NN_ * 16];
    __shared__ int   lab[NN_];

    int bw = blockIdx.x >> 3;
    int h  = blockIdx.x & 7;
    int n  = threadIdx.x;

    long base = ((long)bw * NN_ + n) * 384;
    const float* qp = g_qkv + base + h * 16;
    // q * SCALE folded in, packed as 8 f32x2
    ull q2[8];
#pragma unroll
    for (int j = 0; j < 4; j++) {
        float4 qv = *(const float4*)(qp + j * 4);
        q2[j * 2 + 0] = pack2(qv.x * 0.25f, qv.y * 0.25f);
        q2[j * 2 + 1] = pack2(qv.z * 0.25f, qv.w * 0.25f);
    }
#pragma unroll
    for (int j = 0; j < 4; j++) {
        ((float4*)k_s)[n * 4 + j] = *(const float4*)(g_qkv + base + 128 + h * 16 + j * 4);
        ((float4*)v_s)[n * 4 + j] = *(const float4*)(g_qkv + base + 256 + h * 16 + j * 4);
    }
    {
        int wi = bw & 255;
        int sd = (wi >> 6) * 2 + (n >> 6);
        int sh = ((wi >> 3) & 7) * 8 + ((n >> 3) & 7);
        int sw = (wi & 7) * 8 + (n & 7);
        int ld = sd < 6 ? 0 : (sd < 7 ? 1 : 2);
        int lh = sh < 56 ? 0 : (sh < 60 ? 1 : 2);
        int lw = sw < 56 ? 0 : (sw < 60 ? 1 : 2);
        lab[n] = ld * 9 + lh * 3 + lw;
    }
    __syncthreads();

    const float* bcol = g_bias + (long)h * NN_ * NN_ + n;   // [h][m][n], stride NN_
    int myl = lab[n];
    float sum = 0.0f;
    ull acc2[8];
#pragma unroll
    for (int j = 0; j < 8; j++) acc2[j] = 0ull;

#pragma unroll 4
    for (int m = 0; m < NN_; m++) {
        const ulonglong2* kr = (const ulonglong2*)(k_s + m * 16);
        ulonglong2 k01 = kr[0], k23 = kr[1], k45 = kr[2], k67 = kr[3];
        ull t = fmul2(q2[0], k01.x);
        t = ffma2(q2[1], k01.y, t);
        t = ffma2(q2[2], k23.x, t);
        t = ffma2(q2[3], k23.y, t);
        t = ffma2(q2[4], k45.x, t);
        t = ffma2(q2[5], k45.y, t);
        t = ffma2(q2[6], k67.x, t);
        t = ffma2(q2[7], k67.y, t);
        float2 tt = unpack2(t);
        float s = tt.x + tt.y + bcol[(long)m * NN_];
        if (lab[m] != myl) s -= 100.0f;
        float e = __expf(s);     // no max-subtract: scores bounded, exp(-100)->0 exact
        sum += e;
        ull e2 = dup2(e);
        const ulonglong2* vr = (const ulonglong2*)(v_s + m * 16);
        ulonglong2 v01 = vr[0], v23 = vr[1], v45 = vr[2], v67 = vr[3];
        acc2[0] = ffma2(e2, v01.x, acc2[0]);
        acc2[1] = ffma2(e2, v01.y, acc2[1]);
        acc2[2] = ffma2(e2, v23.x, acc2[2]);
        acc2[3] = ffma2(e2, v23.y, acc2[3]);
        acc2[4] = ffma2(e2, v45.x, acc2[4]);
        acc2[5] = ffma2(e2, v45.y, acc2[5]);
        acc2[6] = ffma2(e2, v67.x, acc2[6]);
        acc2[7] = ffma2(e2, v67.y, acc2[7]);
    }
    float rs = 1.0f / sum;
    float* op = g_attnout + ((long)bw * NN_ + n) * C_ + h * 16;
#pragma unroll
    for (int j = 0; j < 4; j++) {
        float2 a = unpack2(acc2[j * 2 + 0]);
        float2 b = unpack2(acc2[j * 2 + 1]);
        float4 o4;
        o4.x = a.x * rs; o4.y = a.y * rs;
        o4.z = b.x * rs; o4.w = b.y * rs;
        *(float4*)(op + j * 4) = o4;
    }
}

// ---------------- SGEMM with FFMA2 + double buffering -------------------------
// C = act(A @ Wt^T + bias) (+res). A (M,K), Wt (N,K) row-major.
// BM=128, BN=64, BK=16, 256 threads, microtile 8m x 4n (2 f32x2 pairs along n).
template <int ACT, bool RES>
__global__ void __launch_bounds__(256)
gemm2_kernel(const float* __restrict__ A, const float* __restrict__ Wt,
             const float* __restrict__ bias, const float* __restrict__ res,
             float* __restrict__ C, int M, int N, int K) {
    __shared__ float As[2][16][128];
    __shared__ float Bs[2][16][64];
    int tid = threadIdx.x;
    int m0 = blockIdx.y * 128;
    int n0 = blockIdx.x * 64;
    int tx = tid & 15, ty = tid >> 4;

    ull acc[8][2];
#pragma unroll
    for (int i = 0; i < 8; i++) { acc[i][0] = 0ull; acc[i][1] = 0ull; }

    const int KT = K >> 4;
    float4 pa[2], pb;
    // A tile: 128 rows x 16k = 512 float4 -> 2/thread. idx=tid*2+it, row=idx>>2, kq=idx&3
    // B tile: 64 rows x 16k = 256 float4 -> 1/thread. row=tid>>2, kq=tid&3
    {
#pragma unroll
        for (int it = 0; it < 2; it++) {
            int idx = tid * 2 + it, row = idx >> 2, kq = idx & 3;
            pa[it] = *(const float4*)(A + (long)(m0 + row) * K + kq * 4);
        }
        int row = tid >> 2, kq = tid & 3;
        pb = *(const float4*)(Wt + (long)(n0 + row) * K + kq * 4);
    }
    {
#pragma unroll
        for (int it = 0; it < 2; it++) {
            int idx = tid * 2 + it, row = idx >> 2, kq = idx & 3;
            As[0][kq * 4 + 0][row] = pa[it].x;
            As[0][kq * 4 + 1][row] = pa[it].y;
            As[0][kq * 4 + 2][row] = pa[it].z;
            As[0][kq * 4 + 3][row] = pa[it].w;
        }
        int row = tid >> 2, kq = tid & 3;
        Bs[0][kq * 4 + 0][row] = pb.x;
        Bs[0][kq * 4 + 1][row] = pb.y;
        Bs[0][kq * 4 + 2][row] = pb.z;
        Bs[0][kq * 4 + 3][row] = pb.w;
    }
    __syncthreads();

    for (int kt = 0; kt < KT; kt++) {
        int cur = kt & 1;
        if (kt + 1 < KT) {
            int kb = (kt + 1) * 16;
#pragma unroll
            for (int it = 0; it < 2; it++) {
                int idx = tid * 2 + it, row = idx >> 2, kq = idx & 3;
                pa[it] = *(const float4*)(A + (long)(m0 + row) * K + kb + kq * 4);
            }
            int row = tid >> 2, kq = tid & 3;
            pb = *(const float4*)(Wt + (long)(n0 + row) * K + kb + kq * 4);
        }
#pragma unroll
        for (int k = 0; k < 16; k++) {
            float4 a0 = *(const float4*)&As[cur][k][ty * 8];
            float4 a1 = *(const float4*)&As[cur][k][ty * 8 + 4];
            ulonglong2 bp = *(const ulonglong2*)&Bs[cur][k][tx * 4];
            ull ad[8];
            ad[0] = dup2(a0.x); ad[1] = dup2(a0.y);
            ad[2] = dup2(a0.z); ad[3] = dup2(a0.w);
            ad[4] = dup2(a1.x); ad[5] = dup2(a1.y);
            ad[6] = dup2(a1.z); ad[7] = dup2(a1.w);
#pragma unroll
            for (int i = 0; i < 8; i++) {
                acc[i][0] = ffma2(ad[i], bp.x, acc[i][0]);
                acc[i][1] = ffma2(ad[i], bp.y, acc[i][1]);
            }
        }
        if (kt + 1 < KT) {
            int nxt = cur ^ 1;
#pragma unroll
            for (int it = 0; it < 2; it++) {
                int idx = tid * 2 + it, row = idx >> 2, kq = idx & 3;
                As[nxt][kq * 4 + 0][row] = pa[it].x;
                As[nxt][kq * 4 + 1][row] = pa[it].y;
                As[nxt][kq * 4 + 2][row] = pa[it].z;
                As[nxt][kq * 4 + 3][row] = pa[it].w;
            }
            int row = tid >> 2, kq = tid & 3;
            Bs[nxt][kq * 4 + 0][row] = pb.x;
            Bs[nxt][kq * 4 + 1][row] = pb.y;
            Bs[nxt][kq * 4 + 2][row] = pb.z;
            Bs[nxt][kq * 4 + 3][row] = pb.w;
        }
        __syncthreads();
    }

    float4 bz = *(const float4*)(bias + n0 + tx * 4);
    float bb4[4] = {bz.x, bz.y, bz.z, bz.w};
#pragma unroll
    for (int i = 0; i < 8; i++) {
        int cm = m0 + ty * 8 + i;
        float2 p0 = unpack2(acc[i][0]);
        float2 p1 = unpack2(acc[i][1]);
        float4 o;
        o.x = p0.x + bb4[0];
        o.y = p0.y + bb4[1];
        o.z = p1.x + bb4[2];
        o.w = p1.y + bb4[3];
        if (ACT == 1) {
            o.x = gelu_exact(o.x); o.y = gelu_exact(o.y);
            o.z = gelu_exact(o.z); o.w = gelu_exact(o.w);
        }
        if (RES) {
            float4 r = *(const float4*)(res + (long)cm * N + n0 + tx * 4);
            o.x += r.x; o.y += r.y; o.z += r.z; o.w += r.w;
        }
        *(float4*)(C + (long)cm * N + n0 + tx * 4) = o;
    }
}

// -------- K6: window-reverse + roll + residual + LN2 --------------------------
__global__ void scatter_ln2_kernel(const float* __restrict__ x,
                                   const float* __restrict__ g2,
                                   const float* __restrict__ b2) {
    int t = (blockIdx.x * blockDim.x + threadIdx.x) >> 5;
    int lane = threadIdx.x & 31;
    if (t >= NTOK) return;
    int w = t & 63, h = (t >> 6) & 63, d = (t >> 12) & 7, bb = t >> 15;
    int sd = (d + 7) & 7;
    int sh = (h + 60) & 63;
    int sw = (w + 60) & 63;
    int bw = bb * 256 + (sd >> 1) * 64 + (sh >> 3) * 8 + (sw >> 3);
    int n  = (sd & 1) * 64 + (sh & 7) * 8 + (sw & 7);

    float4 xv = *(const float4*)(x + (long)t * C_ + lane * 4);
    float4 pv = *(const float4*)(g_projout + ((long)bw * NN_ + n) * C_ + lane * 4);
    float4 s1;
    s1.x = xv.x + pv.x; s1.y = xv.y + pv.y;
    s1.z = xv.z + pv.z; s1.w = xv.w + pv.w;
    *(float4*)(g_x1 + (long)t * C_ + lane * 4) = s1;

    float s  = s1.x + s1.y + s1.z + s1.w;
    float sq = s1.x * s1.x + s1.y * s1.y + s1.z * s1.z + s1.w * s1.w;
#pragma unroll
    for (int o = 16; o > 0; o >>= 1) {
        s  += __shfl_xor_sync(0xffffffffu, s, o);
        sq += __shfl_xor_sync(0xffffffffu, sq, o);
    }
    float mean = s * (1.0f / C_);
    float var  = sq * (1.0f / C_) - mean * mean;
    float inv  = rsqrtf(var + 1e-5f);
    float4 gg = *(const float4*)(g2 + lane * 4);
    float4 bv = *(const float4*)(b2 + lane * 4);
    float4 o4;
    o4.x = (s1.x - mean) * inv * gg.x + bv.x;
    o4.y = (s1.y - mean) * inv * gg.y + bv.y;
    o4.z = (s1.z - mean) * inv * gg.z + bv.z;
    o4.w = (s1.w - mean) * inv * gg.w + bv.w;
    *(float4*)(g_xn2 + (long)t * C_ + lane * 4) = o4;
}

// ---------------------------------------------------------------------------
extern "C" void kernel_launch(void* const* d_in, const int* in_sizes, int n_in,
                              void* d_out, int out_size) {
    const float* x      = (const float*)d_in[0];
    const float* qkv_w  = (const float*)d_in[1];
    const float* qkv_b  = (const float*)d_in[2];
    const float* proj_w = (const float*)d_in[3];
    const float* proj_b = (const float*)d_in[4];
    const float* rpb    = (const float*)d_in[5];
    const float* ln1_g  = (const float*)d_in[6];
    const float* ln1_b  = (const float*)d_in[7];
    const float* ln2_g  = (const float*)d_in[8];
    const float* ln2_b  = (const float*)d_in[9];
    const float* fc1_w  = (const float*)d_in[10];
    const float* fc1_b  = (const float*)d_in[11];
    const float* fc2_w  = (const float*)d_in[12];
    const float* fc2_b  = (const float*)d_in[13];
    float* out = (float*)d_out;

    float *p_win, *p_qkv, *p_attnout, *p_projout, *p_x1, *p_xn2, *p_hid;
    cudaGetSymbolAddress((void**)&p_win,     g_win);
    cudaGetSymbolAddress((void**)&p_qkv,     g_qkv);
    cudaGetSymbolAddress((void**)&p_attnout, g_attnout);
    cudaGetSymbolAddress((void**)&p_projout, g_projout);
    cudaGetSymbolAddress((void**)&p_x1,      g_x1);
    cudaGetSymbolAddress((void**)&p_xn2,     g_xn2);
    cudaGetSymbolAddress((void**)&p_hid,     g_hid);

    // 1) LN1 + shift + partition
    ln_gather_kernel<<<8192, 256>>>(x, ln1_g, ln1_b);
    // 2) QKV GEMM (65536 x 384 x 128)
    gemm2_kernel<0, false><<<dim3(384 / 64, NTOK / 128), 256>>>(
        p_win, qkv_w, qkv_b, nullptr, p_qkv, NTOK, 384, 128);
    // 3) bias table (transposed)
    bias_kernel<<<128, 128>>>(rpb);
    // 4) attention
    attn_kernel<<<NWIN * NH_, 128>>>();
    // 5) proj GEMM (65536 x 128 x 128)
    gemm2_kernel<0, false><<<dim3(128 / 64, NTOK / 128), 256>>>(
        p_attnout, proj_w, proj_b, nullptr, p_projout, NTOK, 128, 128);
    // 6) reverse + roll + residual + LN2
    scatter_ln2_kernel<<<8192, 256>>>(x, ln2_g, ln2_b);
    // 7) fc1 + GELU (65536 x 512 x 128)
    gemm2_kernel<1, false><<<dim3(512 / 64, NTOK / 128), 256>>>(
        p_xn2, fc1_w, fc1_b, nullptr, p_hid, NTOK, 512, 128);
    // 8) fc2 + residual -> out (65536 x 128 x 512)
    gemm2_kernel<0, true><<<dim3(128 / 64, NTOK / 128), 256>>>(
        p_hid, fc2_w, fc2_b, p_x1, out, NTOK, 128, 512);
}

// round 4
// speedup vs baseline: 1.7728x; 1.2559x over previous
#include <cuda_runtime.h>
#include <cuda_bf16.h>
#include <math.h>
#include <stdint.h>

typedef unsigned long long ull;

// Problem constants
#define B_    2
#define D_    8
#define C_    128
#define NH_   8
#define NTOK  65536
#define NWIN  512
#define NN_   128
#define MLPH  512

// ---------------- scratch (device globals) -----------------------------------
__device__ float g_win[NTOK * C_];
__device__ float g_qkv[(long)NTOK * 3 * C_];
__device__ float g_bias[NH_ * NN_ * NN_];       // [h][m(key)][n(query)]
__device__ float g_attnout[NTOK * C_];
__device__ float g_projout[NTOK * C_];
__device__ float g_x1[NTOK * C_];
__device__ float g_xn2[NTOK * C_];
__device__ float g_hid[(long)NTOK * MLPH];

__device__ __forceinline__ float gelu_exact(float x) {
    return 0.5f * x * (1.0f + erff(x * 0.70710678118654752f));
}

// ---- f32x2 packed helpers ------------------------------------------------------
__device__ __forceinline__ ull ffma2(ull a, ull b, ull c) {
    ull d; asm("fma.rn.f32x2 %0, %1, %2, %3;" : "=l"(d) : "l"(a), "l"(b), "l"(c));
    return d;
}
__device__ __forceinline__ ull fmul2(ull a, ull b) {
    ull d; asm("mul.rn.f32x2 %0, %1, %2;" : "=l"(d) : "l"(a), "l"(b));
    return d;
}
__device__ __forceinline__ ull dup2(float x) {
    ull d; asm("mov.b64 %0, {%1, %1};" : "=l"(d) : "f"(x));
    return d;
}
__device__ __forceinline__ float2 unpack2(ull v) {
    float2 r; asm("mov.b64 {%0, %1}, %2;" : "=f"(r.x), "=f"(r.y) : "l"(v));
    return r;
}
__device__ __forceinline__ ull pack2(float lo, float hi) {
    ull d; asm("mov.b64 %0, {%1, %2};" : "=l"(d) : "f"(lo), "f"(hi));
    return d;
}

// ---- bf16 split helper ----------------------------------------------------------
__device__ __forceinline__ void split2(float v, __nv_bfloat16* h, __nv_bfloat16* l) {
    __nv_bfloat16 hh = __float2bfloat16(v);
    *h = hh;
    *l = __float2bfloat16(v - __bfloat162float(hh));
}

// ---- mma.sync m16n8k16 bf16 (baseline PTX, works at compute_103) -----------------
#define MMA(d, a, b)                                                            \
    asm volatile("mma.sync.aligned.m16n8k16.row.col.f32.bf16.bf16.f32 "         \
        "{%0,%1,%2,%3}, {%4,%5,%6,%7}, {%8,%9}, {%0,%1,%2,%3};"                 \
        : "+f"((d)[0]), "+f"((d)[1]), "+f"((d)[2]), "+f"((d)[3])                \
        : "r"((a)[0]), "r"((a)[1]), "r"((a)[2]), "r"((a)[3]),                    \
          "r"((b)[0]), "r"((b)[1]))

// ==================  tensor-core GEMM via mma.sync  ===============================
// C[M,N] = act(A[M,K] @ W[N,K]^T + bias) (+ res). fp32 I/O; bf16 3-term split inside.
// BM=128, BN=128, BK=32, 256 threads, warp tile 64x32.
#define PADK 40

template <int ACT, bool RES>
__global__ void __launch_bounds__(256)
mma_gemm(const float* __restrict__ A, const float* __restrict__ W,
         const float* __restrict__ bias, const float* __restrict__ res,
         float* __restrict__ C, int N, int K) {
    __shared__ __nv_bfloat16 sAh[128 * PADK], sAl[128 * PADK];
    __shared__ __nv_bfloat16 sWh[128 * PADK], sWl[128 * PADK];

    int tid = threadIdx.x, wid = tid >> 5, lane = tid & 31;
    int g = lane >> 2, t = lane & 3;
    int m0 = blockIdx.y * 128, n0 = blockIdx.x * 128;
    int wm = (wid & 1) * 64, wn = (wid >> 1) * 32;

    float acc[4][4][4];
#pragma unroll
    for (int i = 0; i < 4; i++)
#pragma unroll
        for (int j = 0; j < 4; j++)
#pragma unroll
            for (int c = 0; c < 4; c++) acc[i][j][c] = 0.0f;

    int row = tid >> 3;            // 0..31
    int kq  = (tid & 7) * 4;       // 0..28

    float4 pa[4], pw[4];
#pragma unroll
    for (int i = 0; i < 4; i++) {
        pa[i] = *(const float4*)(A + (long)(m0 + row + i * 32) * K + kq);
        pw[i] = *(const float4*)(W + (long)(n0 + row + i * 32) * K + kq);
    }

    int nch = K >> 5;
    for (int c = 0; c < nch; c++) {
        // store prefetched chunk into smem as hi/lo bf16
#pragma unroll
        for (int i = 0; i < 4; i++) {
            int r = row + i * 32;
            split2(pa[i].x, &sAh[r * PADK + kq + 0], &sAl[r * PADK + kq + 0]);
            split2(pa[i].y, &sAh[r * PADK + kq + 1], &sAl[r * PADK + kq + 1]);
            split2(pa[i].z, &sAh[r * PADK + kq + 2], &sAl[r * PADK + kq + 2]);
            split2(pa[i].w, &sAh[r * PADK + kq + 3], &sAl[r * PADK + kq + 3]);
            split2(pw[i].x, &sWh[r * PADK + kq + 0], &sWl[r * PADK + kq + 0]);
            split2(pw[i].y, &sWh[r * PADK + kq + 1], &sWl[r * PADK + kq + 1]);
            split2(pw[i].z, &sWh[r * PADK + kq + 2], &sWl[r * PADK + kq + 2]);
            split2(pw[i].w, &sWh[r * PADK + kq + 3], &sWl[r * PADK + kq + 3]);
        }
        __syncthreads();
        if (c + 1 < nch) {
            int kc = (c + 1) << 5;
#pragma unroll
            for (int i = 0; i < 4; i++) {
                pa[i] = *(const float4*)(A + (long)(m0 + row + i * 32) * K + kc + kq);
                pw[i] = *(const float4*)(W + (long)(n0 + row + i * 32) * K + kc + kq);
            }
        }
#pragma unroll
        for (int ks = 0; ks < 2; ks++) {
            int kb = ks * 16 + 2 * t;
            uint32_t fah[4][4], fal[4][4], fbh[4][2], fbl[4][2];
#pragma unroll
            for (int mi = 0; mi < 4; mi++) {
                int base = (wm + mi * 16 + g) * PADK + kb;
                fah[mi][0] = *(const uint32_t*)&sAh[base];
                fah[mi][1] = *(const uint32_t*)&sAh[base + 8 * PADK];
                fah[mi][2] = *(const uint32_t*)&sAh[base + 8];
                fah[mi][3] = *(const uint32_t*)&sAh[base + 8 * PADK + 8];
                fal[mi][0] = *(const uint32_t*)&sAl[base];
                fal[mi][1] = *(const uint32_t*)&sAl[base + 8 * PADK];
                fal[mi][2] = *(const uint32_t*)&sAl[base + 8];
                fal[mi][3] = *(const uint32_t*)&sAl[base + 8 * PADK + 8];
            }
#pragma unroll
            for (int nj = 0; nj < 4; nj++) {
                int base = (wn + nj * 8 + g) * PADK + kb;
                fbh[nj][0] = *(const uint32_t*)&sWh[base];
                fbh[nj][1] = *(const uint32_t*)&sWh[base + 8];
                fbl[nj][0] = *(const uint32_t*)&sWl[base];
                fbl[nj][1] = *(const uint32_t*)&sWl[base + 8];
            }
#pragma unroll
            for (int mi = 0; mi < 4; mi++)
#pragma unroll
                for (int nj = 0; nj < 4; nj++)
                    MMA(acc[mi][nj], fah[mi], fbh[nj]);
#pragma unroll
            for (int mi = 0; mi < 4; mi++)
#pragma unroll
                for (int nj = 0; nj < 4; nj++)
                    MMA(acc[mi][nj], fah[mi], fbl[nj]);
#pragma unroll
            for (int mi = 0; mi < 4; mi++)
#pragma unroll
                for (int nj = 0; nj < 4; nj++)
                    MMA(acc[mi][nj], fal[mi], fbh[nj]);
        }
        __syncthreads();
    }

    // epilogue
#pragma unroll
    for (int mi = 0; mi < 4; mi++) {
#pragma unroll
        for (int cr = 0; cr < 2; cr++) {
            int m = m0 + wm + mi * 16 + g + cr * 8;
#pragma unroll
            for (int nj = 0; nj < 4; nj++) {
                int n = n0 + wn + nj * 8 + 2 * t;
                float2 bb = *(const float2*)(bias + n);
                float v0 = acc[mi][nj][cr * 2 + 0] + bb.x;
                float v1 = acc[mi][nj][cr * 2 + 1] + bb.y;
                if (ACT == 1) { v0 = gelu_exact(v0); v1 = gelu_exact(v1); }
                if (RES) {
                    float2 r = *(const float2*)(res + (long)m * N + n);
                    v0 += r.x; v1 += r.y;
                }
                float2 o; o.x = v0; o.y = v1;
                *(float2*)(C + (long)m * N + n) = o;
            }
        }
    }
}

// ---------------- K1: LN1 + cyclic shift + window partition ------------------
__global__ void ln_gather_kernel(const float* __restrict__ x,
                                 const float* __restrict__ g,
                                 const float* __restrict__ b) {
    int warp = (blockIdx.x * blockDim.x + threadIdx.x) >> 5;
    int lane = threadIdx.x & 31;
    if (warp >= NWIN * NN_) return;
    int bw = warp >> 7;
    int n  = warp & 127;
    int bb = bw >> 8;
    int wi = bw & 255;
    int wd = wi >> 6, wh = (wi >> 3) & 7, ww = wi & 7;
    int td = n >> 6,  th = (n >> 3) & 7, tw = n & 7;
    int gd = (wd * 2 + td + 1) & 7;
    int gh = (wh * 8 + th + 4) & 63;
    int gw = (ww * 8 + tw + 4) & 63;
    long src = (((long)(bb * D_ + gd) * 64 + gh) * 64 + gw) * C_;

    float4 v = *(const float4*)(x + src + lane * 4);
    float s  = v.x + v.y + v.z + v.w;
    float sq = v.x * v.x + v.y * v.y + v.z * v.z + v.w * v.w;
#pragma unroll
    for (int o = 16; o > 0; o >>= 1) {
        s  += __shfl_xor_sync(0xffffffffu, s, o);
        sq += __shfl_xor_sync(0xffffffffu, sq, o);
    }
    float mean = s * (1.0f / C_);
    float var  = sq * (1.0f / C_) - mean * mean;
    float inv  = rsqrtf(var + 1e-5f);
    float4 gg = *(const float4*)(g + lane * 4);
    float4 bv = *(const float4*)(b + lane * 4);
    float4 o4;
    o4.x = (v.x - mean) * inv * gg.x + bv.x;
    o4.y = (v.y - mean) * inv * gg.y + bv.y;
    o4.z = (v.z - mean) * inv * gg.z + bv.z;
    o4.w = (v.w - mean) * inv * gg.w + bv.w;
    *(float4*)(g_win + (long)warp * C_ + lane * 4) = o4;
}

// ---------------- K2: relative position bias table ----------------------------
__global__ void bias_kernel(const float* __restrict__ rpb) {
    int n = blockIdx.x;    // query
    int m = threadIdx.x;   // key
    int nd = n >> 6, nh = (n >> 3) & 7, nw = n & 7;
    int md = m >> 6, mh = (m >> 3) & 7, mw = m & 7;
    int rpi = (nd - md + 1) * 225 + (nh - mh + 7) * 15 + (nw - mw + 7);
#pragma unroll
    for (int h = 0; h < NH_; h++)
        g_bias[((long)h * NN_ + m) * NN_ + n] = rpb[rpi * NH_ + h];
}

// ---------------- K3: attention per (window, head) -----------------------------
__global__ void __launch_bounds__(128) attn_kernel() {
    __shared__ float k_s[NN_ * 16];
    __shared__ float v_s[NN_ * 16];
    __shared__ int   lab[NN_];

    int bw = blockIdx.x >> 3;
    int h  = blockIdx.x & 7;
    int n  = threadIdx.x;

    long base = ((long)bw * NN_ + n) * 384;
    const float* qp = g_qkv + base + h * 16;
    ull q2[8];
#pragma unroll
    for (int j = 0; j < 4; j++) {
        float4 qv = *(const float4*)(qp + j * 4);
        q2[j * 2 + 0] = pack2(qv.x * 0.25f, qv.y * 0.25f);
        q2[j * 2 + 1] = pack2(qv.z * 0.25f, qv.w * 0.25f);
    }
#pragma unroll
    for (int j = 0; j < 4; j++) {
        ((float4*)k_s)[n * 4 + j] = *(const float4*)(g_qkv + base + 128 + h * 16 + j * 4);
        ((float4*)v_s)[n * 4 + j] = *(const float4*)(g_qkv + base + 256 + h * 16 + j * 4);
    }
    {
        int wi = bw & 255;
        int sd = (wi >> 6) * 2 + (n >> 6);
        int sh = ((wi >> 3) & 7) * 8 + ((n >> 3) & 7);
        int sw = (wi & 7) * 8 + (n & 7);
        int ld = sd < 6 ? 0 : (sd < 7 ? 1 : 2);
        int lh = sh < 56 ? 0 : (sh < 60 ? 1 : 2);
        int lw = sw < 56 ? 0 : (sw < 60 ? 1 : 2);
        lab[n] = ld * 9 + lh * 3 + lw;
    }
    __syncthreads();

    const float* bcol = g_bias + (long)h * NN_ * NN_ + n;
    int myl = lab[n];
    float sum = 0.0f;
    ull acc2[8];
#pragma unroll
    for (int j = 0; j < 8; j++) acc2[j] = 0ull;

#pragma unroll 4
    for (int m = 0; m < NN_; m++) {
        const ulonglong2* kr = (const ulonglong2*)(k_s + m * 16);
        ulonglong2 k01 = kr[0], k23 = kr[1], k45 = kr[2], k67 = kr[3];
        ull tt0 = fmul2(q2[0], k01.x);
        tt0 = ffma2(q2[1], k01.y, tt0);
        tt0 = ffma2(q2[2], k23.x, tt0);
        tt0 = ffma2(q2[3], k23.y, tt0);
        tt0 = ffma2(q2[4], k45.x, tt0);
        tt0 = ffma2(q2[5], k45.y, tt0);
        tt0 = ffma2(q2[6], k67.x, tt0);
        tt0 = ffma2(q2[7], k67.y, tt0);
        float2 tt = unpack2(tt0);
        float s = tt.x + tt.y + bcol[(long)m * NN_];
        if (lab[m] != myl) s -= 100.0f;
        float e = __expf(s);
        sum += e;
        ull e2 = dup2(e);
        const ulonglong2* vr = (const ulonglong2*)(v_s + m * 16);
        ulonglong2 v01 = vr[0], v23 = vr[1], v45 = vr[2], v67 = vr[3];
        acc2[0] = ffma2(e2, v01.x, acc2[0]);
        acc2[1] = ffma2(e2, v01.y, acc2[1]);
        acc2[2] = ffma2(e2, v23.x, acc2[2]);
        acc2[3] = ffma2(e2, v23.y, acc2[3]);
        acc2[4] = ffma2(e2, v45.x, acc2[4]);
        acc2[5] = ffma2(e2, v45.y, acc2[5]);
        acc2[6] = ffma2(e2, v67.x, acc2[6]);
        acc2[7] = ffma2(e2, v67.y, acc2[7]);
    }
    float rs = 1.0f / sum;
    float* op = g_attnout + ((long)bw * NN_ + n) * C_ + h * 16;
#pragma unroll
    for (int j = 0; j < 4; j++) {
        float2 a = unpack2(acc2[j * 2 + 0]);
        float2 b = unpack2(acc2[j * 2 + 1]);
        float4 o4;
        o4.x = a.x * rs; o4.y = a.y * rs;
        o4.z = b.x * rs; o4.w = b.y * rs;
        *(float4*)(op + j * 4) = o4;
    }
}

// -------- K6: window-reverse + roll + residual + LN2 --------------------------
__global__ void scatter_ln2_kernel(const float* __restrict__ x,
                                   const float* __restrict__ g2,
                                   const float* __restrict__ b2) {
    int t = (blockIdx.x * blockDim.x + threadIdx.x) >> 5;
    int lane = threadIdx.x & 31;
    if (t >= NTOK) return;
    int w = t & 63, h = (t >> 6) & 63, d = (t >> 12) & 7, bb = t >> 15;
    int sd = (d + 7) & 7;
    int sh = (h + 60) & 63;
    int sw = (w + 60) & 63;
    int bw = bb * 256 + (sd >> 1) * 64 + (sh >> 3) * 8 + (sw >> 3);
    int n  = (sd & 1) * 64 + (sh & 7) * 8 + (sw & 7);

    float4 xv = *(const float4*)(x + (long)t * C_ + lane * 4);
    float4 pv = *(const float4*)(g_projout + ((long)bw * NN_ + n) * C_ + lane * 4);
    float4 s1;
    s1.x = xv.x + pv.x; s1.y = xv.y + pv.y;
    s1.z = xv.z + pv.z; s1.w = xv.w + pv.w;
    *(float4*)(g_x1 + (long)t * C_ + lane * 4) = s1;

    float s  = s1.x + s1.y + s1.z + s1.w;
    float sq = s1.x * s1.x + s1.y * s1.y + s1.z * s1.z + s1.w * s1.w;
#pragma unroll
    for (int o = 16; o > 0; o >>= 1) {
        s  += __shfl_xor_sync(0xffffffffu, s, o);
        sq += __shfl_xor_sync(0xffffffffu, sq, o);
    }
    float mean = s * (1.0f / C_);
    float var  = sq * (1.0f / C_) - mean * mean;
    float inv  = rsqrtf(var + 1e-5f);
    float4 gg = *(const float4*)(g2 + lane * 4);
    float4 bv = *(const float4*)(b2 + lane * 4);
    float4 o4;
    o4.x = (s1.x - mean) * inv * gg.x + bv.x;
    o4.y = (s1.y - mean) * inv * gg.y + bv.y;
    o4.z = (s1.z - mean) * inv * gg.z + bv.z;
    o4.w = (s1.w - mean) * inv * gg.w + bv.w;
    *(float4*)(g_xn2 + (long)t * C_ + lane * 4) = o4;
}

// ---------------------------------------------------------------------------
extern "C" void kernel_launch(void* const* d_in, const int* in_sizes, int n_in,
                              void* d_out, int out_size) {
    const float* x      = (const float*)d_in[0];
    const float* qkv_w  = (const float*)d_in[1];
    const float* qkv_b  = (const float*)d_in[2];
    const float* proj_w = (const float*)d_in[3];
    const float* proj_b = (const float*)d_in[4];
    const float* rpb    = (const float*)d_in[5];
    const float* ln1_g  = (const float*)d_in[6];
    const float* ln1_b  = (const float*)d_in[7];
    const float* ln2_g  = (const float*)d_in[8];
    const float* ln2_b  = (const float*)d_in[9];
    const float* fc1_w  = (const float*)d_in[10];
    const float* fc1_b  = (const float*)d_in[11];
    const float* fc2_w  = (const float*)d_in[12];
    const float* fc2_b  = (const float*)d_in[13];
    float* out = (float*)d_out;

    float *p_win, *p_qkv, *p_attnout, *p_projout, *p_x1, *p_xn2, *p_hid;
    cudaGetSymbolAddress((void**)&p_win,     g_win);
    cudaGetSymbolAddress((void**)&p_qkv,     g_qkv);
    cudaGetSymbolAddress((void**)&p_attnout, g_attnout);
    cudaGetSymbolAddress((void**)&p_projout, g_projout);
    cudaGetSymbolAddress((void**)&p_x1,      g_x1);
    cudaGetSymbolAddress((void**)&p_xn2,     g_xn2);
    cudaGetSymbolAddress((void**)&p_hid,     g_hid);

    // 1) LN1 + shift + partition
    ln_gather_kernel<<<8192, 256>>>(x, ln1_g, ln1_b);
    // 2) QKV GEMM (65536 x 384 x 128)
    mma_gemm<0, false><<<dim3(3, 512), 256>>>(p_win, qkv_w, qkv_b, nullptr,
                                              p_qkv, 384, 128);
    // 3) bias table
    bias_kernel<<<128, 128>>>(rpb);
    // 4) attention
    attn_kernel<<<NWIN * NH_, 128>>>();
    // 5) proj GEMM (65536 x 128 x 128)
    mma_gemm<0, false><<<dim3(1, 512), 256>>>(p_attnout, proj_w, proj_b, nullptr,
                                              p_projout, 128, 128);
    // 6) reverse + roll + residual + LN2
    scatter_ln2_kernel<<<8192, 256>>>(x, ln2_g, ln2_b);
    // 7) fc1 + GELU (65536 x 512 x 128)
    mma_gemm<1, false><<<dim3(4, 512), 256>>>(p_xn2, fc1_w, fc1_b, nullptr,
                                              p_hid, 512, 128);
    // 8) fc2 + residual -> out (65536 x 128 x 512)
    mma_gemm<0, true><<<dim3(1, 512), 256>>>(p_hid, fc2_w, fc2_b, p_x1,
                                             out, 128, 512);
}

// round 5
// speedup vs baseline: 1.8491x; 1.0430x over previous
#include <cuda_runtime.h>
#include <cuda_bf16.h>
#include <math.h>
#include <stdint.h>

typedef __nv_bfloat16 bf16;
typedef __nv_bfloat162 bf162;

// Problem constants
#define B_    2
#define D_    8
#define C_    128
#define NH_   8
#define NTOK  65536
#define NWIN  512
#define NN_   128
#define MLPH  512

// ---------------- scratch (device globals) -----------------------------------
__device__ bf16  g_win_h[NTOK * C_],  g_win_l[NTOK * C_];
__device__ bf16  g_qkv_h[(long)NTOK * 384], g_qkv_l[(long)NTOK * 384];
__device__ float g_bias[NH_ * NN_ * NN_];     // [h][n(query)][m(key)]
__device__ bf16  g_attn_h[NTOK * C_], g_attn_l[NTOK * C_];
__device__ float g_projout[NTOK * C_];
__device__ float g_x1[NTOK * C_];
__device__ bf16  g_xn2_h[NTOK * C_],  g_xn2_l[NTOK * C_];
__device__ bf16  g_hid_h[(long)NTOK * MLPH], g_hid_l[(long)NTOK * MLPH];
// split weights
__device__ bf16  g_qkvw_h[384 * C_],  g_qkvw_l[384 * C_];
__device__ bf16  g_projw_h[C_ * C_],  g_projw_l[C_ * C_];
__device__ bf16  g_fc1w_h[MLPH * C_], g_fc1w_l[MLPH * C_];
__device__ bf16  g_fc2w_h[C_ * MLPH], g_fc2w_l[C_ * MLPH];

__device__ __forceinline__ float gelu_exact(float x) {
    return 0.5f * x * (1.0f + erff(x * 0.70710678118654752f));
}

__device__ __forceinline__ void split_pair(float v0, float v1, bf16* hp, bf16* lp) {
    bf16 h0 = __float2bfloat16(v0), h1 = __float2bfloat16(v1);
    bf16 l0 = __float2bfloat16(v0 - __bfloat162float(h0));
    bf16 l1 = __float2bfloat16(v1 - __bfloat162float(h1));
    *(bf162*)hp = bf162(h0, h1);
    *(bf162*)lp = bf162(l0, l1);
}

// ---- mma.sync m16n8k16 bf16 -----------------------------------------------------
#define MMA(d, a, b)                                                            \
    asm volatile("mma.sync.aligned.m16n8k16.row.col.f32.bf16.bf16.f32 "         \
        "{%0,%1,%2,%3}, {%4,%5,%6,%7}, {%8,%9}, {%0,%1,%2,%3};"                 \
        : "+f"((d)[0]), "+f"((d)[1]), "+f"((d)[2]), "+f"((d)[3])                \
        : "r"((a)[0]), "r"((a)[1]), "r"((a)[2]), "r"((a)[3]),                    \
          "r"((b)[0]), "r"((b)[1]))

__device__ __forceinline__ uint32_t pack_hi_bf16x2(float v0, float v1) {
    bf162 h = bf162(__float2bfloat16(v0), __float2bfloat16(v1));
    return *(uint32_t*)&h;
}

// ==================  GEMM: pre-split bf16 inputs, mma.sync  =======================
// C[M,N] = act( (Ah+Al) @ (Wh+Wl)^T + bias ) (+res). BM=128 BN=128 BK=32.
#define PADK 40

template <int ACT, bool RES, bool OSPLIT>
__global__ void __launch_bounds__(256)
mma_gemm(const bf16* __restrict__ Ah, const bf16* __restrict__ Al,
         const bf16* __restrict__ Wh, const bf16* __restrict__ Wl,
         const float* __restrict__ bias, const float* __restrict__ res,
         float* __restrict__ Cf, bf16* __restrict__ Ch, bf16* __restrict__ Cl,
         int N, int K, int qlim) {
    __shared__ bf16 sAh[128 * PADK], sAl[128 * PADK];
    __shared__ bf16 sWh[128 * PADK], sWl[128 * PADK];

    int tid = threadIdx.x, wid = tid >> 5, lane = tid & 31;
    int g = lane >> 2, t = lane & 3;
    int m0 = blockIdx.y * 128, n0 = blockIdx.x * 128;
    int wm = (wid & 1) * 64, wn = (wid >> 1) * 32;

    float acc[4][4][4];
#pragma unroll
    for (int i = 0; i < 4; i++)
#pragma unroll
        for (int j = 0; j < 4; j++)
#pragma unroll
            for (int c = 0; c < 4; c++) acc[i][j][c] = 0.0f;

    // copy mapping: 512 uint4 per array per chunk -> 2 per thread
    int crow0 = tid >> 2, cseg0 = (tid & 3) * 8;           // idx = tid
    int crow1 = (tid + 256) >> 2, cseg1 = cseg0;           // idx = tid + 256

    uint4 pah0, pah1, pal0, pal1, pwh0, pwh1, pwl0, pwl1;
    pah0 = *(const uint4*)(Ah + (long)(m0 + crow0) * K + cseg0);
    pah1 = *(const uint4*)(Ah + (long)(m0 + crow1) * K + cseg1);
    pal0 = *(const uint4*)(Al + (long)(m0 + crow0) * K + cseg0);
    pal1 = *(const uint4*)(Al + (long)(m0 + crow1) * K + cseg1);
    pwh0 = *(const uint4*)(Wh + (long)(n0 + crow0) * K + cseg0);
    pwh1 = *(const uint4*)(Wh + (long)(n0 + crow1) * K + cseg1);
    pwl0 = *(const uint4*)(Wl + (long)(n0 + crow0) * K + cseg0);
    pwl1 = *(const uint4*)(Wl + (long)(n0 + crow1) * K + cseg1);

    int nch = K >> 5;
    for (int c = 0; c < nch; c++) {
        *(uint4*)(sAh + crow0 * PADK + cseg0) = pah0;
        *(uint4*)(sAh + crow1 * PADK + cseg1) = pah1;
        *(uint4*)(sAl + crow0 * PADK + cseg0) = pal0;
        *(uint4*)(sAl + crow1 * PADK + cseg1) = pal1;
        *(uint4*)(sWh + crow0 * PADK + cseg0) = pwh0;
        *(uint4*)(sWh + crow1 * PADK + cseg1) = pwh1;
        *(uint4*)(sWl + crow0 * PADK + cseg0) = pwl0;
        *(uint4*)(sWl + crow1 * PADK + cseg1) = pwl1;
        __syncthreads();
        if (c + 1 < nch) {
            int kc = (c + 1) << 5;
            pah0 = *(const uint4*)(Ah + (long)(m0 + crow0) * K + kc + cseg0);
            pah1 = *(const uint4*)(Ah + (long)(m0 + crow1) * K + kc + cseg1);
            pal0 = *(const uint4*)(Al + (long)(m0 + crow0) * K + kc + cseg0);
            pal1 = *(const uint4*)(Al + (long)(m0 + crow1) * K + kc + cseg1);
            pwh0 = *(const uint4*)(Wh + (long)(n0 + crow0) * K + kc + cseg0);
            pwh1 = *(const uint4*)(Wh + (long)(n0 + crow1) * K + kc + cseg1);
            pwl0 = *(const uint4*)(Wl + (long)(n0 + crow0) * K + kc + cseg0);
            pwl1 = *(const uint4*)(Wl + (long)(n0 + crow1) * K + kc + cseg1);
        }
#pragma unroll
        for (int ks = 0; ks < 2; ks++) {
            int kb = ks * 16 + 2 * t;
            uint32_t fah[4][4], fal[4][4], fbh[4][2], fbl[4][2];
#pragma unroll
            for (int mi = 0; mi < 4; mi++) {
                int base = (wm + mi * 16 + g) * PADK + kb;
                fah[mi][0] = *(const uint32_t*)&sAh[base];
                fah[mi][1] = *(const uint32_t*)&sAh[base + 8 * PADK];
                fah[mi][2] = *(const uint32_t*)&sAh[base + 8];
                fah[mi][3] = *(const uint32_t*)&sAh[base + 8 * PADK + 8];
                fal[mi][0] = *(const uint32_t*)&sAl[base];
                fal[mi][1] = *(const uint32_t*)&sAl[base + 8 * PADK];
                fal[mi][2] = *(const uint32_t*)&sAl[base + 8];
                fal[mi][3] = *(const uint32_t*)&sAl[base + 8 * PADK + 8];
            }
#pragma unroll
            for (int nj = 0; nj < 4; nj++) {
                int base = (wn + nj * 8 + g) * PADK + kb;
                fbh[nj][0] = *(const uint32_t*)&sWh[base];
                fbh[nj][1] = *(const uint32_t*)&sWh[base + 8];
                fbl[nj][0] = *(const uint32_t*)&sWl[base];
                fbl[nj][1] = *(const uint32_t*)&sWl[base + 8];
            }
#pragma unroll
            for (int mi = 0; mi < 4; mi++)
#pragma unroll
                for (int nj = 0; nj < 4; nj++)
                    MMA(acc[mi][nj], fah[mi], fbh[nj]);
#pragma unroll
            for (int mi = 0; mi < 4; mi++)
#pragma unroll
                for (int nj = 0; nj < 4; nj++)
                    MMA(acc[mi][nj], fah[mi], fbl[nj]);
#pragma unroll
            for (int mi = 0; mi < 4; mi++)
#pragma unroll
                for (int nj = 0; nj < 4; nj++)
                    MMA(acc[mi][nj], fal[mi], fbh[nj]);
        }
        __syncthreads();
    }

    // epilogue
#pragma unroll
    for (int mi = 0; mi < 4; mi++) {
#pragma unroll
        for (int cr = 0; cr < 2; cr++) {
            int m = m0 + wm + mi * 16 + g + cr * 8;
#pragma unroll
            for (int nj = 0; nj < 4; nj++) {
                int n = n0 + wn + nj * 8 + 2 * t;
                float2 bb = *(const float2*)(bias + n);
                float v0 = acc[mi][nj][cr * 2 + 0] + bb.x;
                float v1 = acc[mi][nj][cr * 2 + 1] + bb.y;
                if (n < qlim) { v0 *= 0.25f; v1 *= 0.25f; }
                if (ACT == 1) { v0 = gelu_exact(v0); v1 = gelu_exact(v1); }
                if (RES) {
                    float2 r = *(const float2*)(res + (long)m * N + n);
                    v0 += r.x; v1 += r.y;
                }
                if (OSPLIT) {
                    split_pair(v0, v1, Ch + (long)m * N + n, Cl + (long)m * N + n);
                } else {
                    float2 o; o.x = v0; o.y = v1;
                    *(float2*)(Cf + (long)m * N + n) = o;
                }
            }
        }
    }
}

// ---------------- weight split -------------------------------------------------
__global__ void split_kernel(const float* __restrict__ s, bf16* __restrict__ hi,
                             bf16* __restrict__ lo, int n) {
    int i = blockIdx.x * blockDim.x + threadIdx.x;
    if (i < n) {
        float v = s[i];
        bf16 h = __float2bfloat16(v);
        hi[i] = h;
        lo[i] = __float2bfloat16(v - __bfloat162float(h));
    }
}

// ---------------- K1: LN1 + shift + window partition (-> split bf16) ------------
__global__ void ln_gather_kernel(const float* __restrict__ x,
                                 const float* __restrict__ g,
                                 const float* __restrict__ b) {
    int warp = (blockIdx.x * blockDim.x + threadIdx.x) >> 5;
    int lane = threadIdx.x & 31;
    if (warp >= NWIN * NN_) return;
    int bw = warp >> 7;
    int n  = warp & 127;
    int bb = bw >> 8;
    int wi = bw & 255;
    int wd = wi >> 6, wh = (wi >> 3) & 7, ww = wi & 7;
    int td = n >> 6,  th = (n >> 3) & 7, tw = n & 7;
    int gd = (wd * 2 + td + 1) & 7;
    int gh = (wh * 8 + th + 4) & 63;
    int gw = (ww * 8 + tw + 4) & 63;
    long src = (((long)(bb * D_ + gd) * 64 + gh) * 64 + gw) * C_;

    float4 v = *(const float4*)(x + src + lane * 4);
    float s  = v.x + v.y + v.z + v.w;
    float sq = v.x * v.x + v.y * v.y + v.z * v.z + v.w * v.w;
#pragma unroll
    for (int o = 16; o > 0; o >>= 1) {
        s  += __shfl_xor_sync(0xffffffffu, s, o);
        sq += __shfl_xor_sync(0xffffffffu, sq, o);
    }
    float mean = s * (1.0f / C_);
    float var  = sq * (1.0f / C_) - mean * mean;
    float inv  = rsqrtf(var + 1e-5f);
    float4 gg = *(const float4*)(g + lane * 4);
    float4 bv = *(const float4*)(b + lane * 4);
    long o = (long)warp * C_ + lane * 4;
    split_pair((v.x - mean) * inv * gg.x + bv.x, (v.y - mean) * inv * gg.y + bv.y,
               g_win_h + o, g_win_l + o);
    split_pair((v.z - mean) * inv * gg.z + bv.z, (v.w - mean) * inv * gg.w + bv.w,
               g_win_h + o + 2, g_win_l + o + 2);
}

// ---------------- K2: relative position bias table ([h][query][key]) -------------
__global__ void bias_kernel(const float* __restrict__ rpb) {
    int n = blockIdx.x;    // query
    int m = threadIdx.x;   // key
    int nd = n >> 6, nh = (n >> 3) & 7, nw = n & 7;
    int md = m >> 6, mh = (m >> 3) & 7, mw = m & 7;
    int rpi = (nd - md + 1) * 225 + (nh - mh + 7) * 15 + (nw - mw + 7);
#pragma unroll
    for (int h = 0; h < NH_; h++)
        g_bias[((long)h * NN_ + n) * NN_ + m] = rpb[rpi * NH_ + h];
}

// ---------------- K3: tensor-core attention, CTA=(window,head), 8 warps ----------
#define VPAD 136
__global__ void __launch_bounds__(256) attn_kernel() {
    __shared__ bf16 sVt_h[16 * VPAD];
    __shared__ bf16 sVt_l[16 * VPAD];
    __shared__ int  lab[NN_];

    int bw = blockIdx.x >> 3;
    int h  = blockIdx.x & 7;
    int tid = threadIdx.x, wid = tid >> 5, lane = tid & 31;
    int g = lane >> 2, t = lane & 3;
    long tokbase = (long)bw * 128;
    int hoff = h * 16;

    // stage V^T (dim-major) into smem, both hi and lo
    {
        int tok = tid >> 1;
        int d0  = (tid & 1) * 8;
        uint4 hv = *(const uint4*)(g_qkv_h + (tokbase + tok) * 384 + 256 + hoff + d0);
        uint4 lv = *(const uint4*)(g_qkv_l + (tokbase + tok) * 384 + 256 + hoff + d0);
        const bf16* hp = (const bf16*)&hv;
        const bf16* lp = (const bf16*)&lv;
#pragma unroll
        for (int d = 0; d < 8; d++) {
            sVt_h[(d0 + d) * VPAD + tok] = hp[d];
            sVt_l[(d0 + d) * VPAD + tok] = lp[d];
        }
    }
    if (tid < 128) {
        int wi = bw & 255;
        int sd = (wi >> 6) * 2 + (tid >> 6);
        int sh = ((wi >> 3) & 7) * 8 + ((tid >> 3) & 7);
        int sw = (wi & 7) * 8 + (tid & 7);
        int ld = sd < 6 ? 0 : (sd < 7 ? 1 : 2);
        int lh = sh < 56 ? 0 : (sh < 60 ? 1 : 2);
        int lw = sw < 56 ? 0 : (sw < 60 ? 1 : 2);
        lab[tid] = ld * 9 + lh * 3 + lw;
    }
    __syncthreads();

    // Q fragments (q pre-scaled by 0.25 in the QKV epilogue)
    int row0 = wid * 16;
    long rg  = (tokbase + row0 + g) * 384 + hoff;
    long rg8 = rg + 8 * 384;
    uint32_t qh[4], ql[4];
    qh[0] = *(const uint32_t*)(g_qkv_h + rg + 2 * t);
    qh[1] = *(const uint32_t*)(g_qkv_h + rg8 + 2 * t);
    qh[2] = *(const uint32_t*)(g_qkv_h + rg + 2 * t + 8);
    qh[3] = *(const uint32_t*)(g_qkv_h + rg8 + 2 * t + 8);
    ql[0] = *(const uint32_t*)(g_qkv_l + rg + 2 * t);
    ql[1] = *(const uint32_t*)(g_qkv_l + rg8 + 2 * t);
    ql[2] = *(const uint32_t*)(g_qkv_l + rg + 2 * t + 8);
    ql[3] = *(const uint32_t*)(g_qkv_l + rg8 + 2 * t + 8);

    // QK^T: acc[j] = scores for n-tile j (keys 8j..8j+7)
    float acc[16][4];
#pragma unroll
    for (int j = 0; j < 16; j++) {
        long kr = (tokbase + 8 * j + g) * 384 + 128 + hoff + 2 * t;
        uint32_t kb[2], klo[2];
        kb[0]  = *(const uint32_t*)(g_qkv_h + kr);
        kb[1]  = *(const uint32_t*)(g_qkv_h + kr + 8);
        klo[0] = *(const uint32_t*)(g_qkv_l + kr);
        klo[1] = *(const uint32_t*)(g_qkv_l + kr + 8);
        acc[j][0] = acc[j][1] = acc[j][2] = acc[j][3] = 0.0f;
        MMA(acc[j], qh, kb);
        MMA(acc[j], ql, kb);
        MMA(acc[j], qh, klo);
    }

    // bias + mask + exp + row sums
    int myl_g  = lab[row0 + g];
    int myl_g8 = lab[row0 + g + 8];
    const float* bptr = g_bias + (long)h * NN_ * NN_;
    float sum_g = 0.0f, sum_g8 = 0.0f;
#pragma unroll
    for (int j = 0; j < 16; j++) {
        int col = 8 * j + 2 * t;
        float2 bg  = *(const float2*)(bptr + (row0 + g) * NN_ + col);
        float2 bg8 = *(const float2*)(bptr + (row0 + g + 8) * NN_ + col);
        int l0 = lab[col], l1 = lab[col + 1];
        float e0 = (l0 == myl_g)  ? __expf(acc[j][0] + bg.x)  : 0.0f;
        float e1 = (l1 == myl_g)  ? __expf(acc[j][1] + bg.y)  : 0.0f;
        float e2 = (l0 == myl_g8) ? __expf(acc[j][2] + bg8.x) : 0.0f;
        float e3 = (l1 == myl_g8) ? __expf(acc[j][3] + bg8.y) : 0.0f;
        acc[j][0] = e0; acc[j][1] = e1; acc[j][2] = e2; acc[j][3] = e3;
        sum_g += e0 + e1; sum_g8 += e2 + e3;
    }
    sum_g  += __shfl_xor_sync(0xffffffffu, sum_g, 1);
    sum_g  += __shfl_xor_sync(0xffffffffu, sum_g, 2);
    sum_g8 += __shfl_xor_sync(0xffffffffu, sum_g8, 1);
    sum_g8 += __shfl_xor_sync(0xffffffffu, sum_g8, 2);
    float rs_g = 1.0f / sum_g, rs_g8 = 1.0f / sum_g8;

    // P @ V  (P fragments chained directly from acc, split hi/lo)
    float oacc[2][4];
#pragma unroll
    for (int nj = 0; nj < 2; nj++)
#pragma unroll
        for (int c = 0; c < 4; c++) oacc[nj][c] = 0.0f;

#pragma unroll
    for (int kt = 0; kt < 8; kt++) {
        float* p0 = acc[2 * kt];
        float* p1 = acc[2 * kt + 1];
        uint32_t ph[4], pl[4];
        ph[0] = pack_hi_bf16x2(p0[0], p0[1]);
        ph[1] = pack_hi_bf16x2(p0[2], p0[3]);
        ph[2] = pack_hi_bf16x2(p1[0], p1[1]);
        ph[3] = pack_hi_bf16x2(p1[2], p1[3]);
        bf162* phv = (bf162*)ph;
        pl[0] = pack_hi_bf16x2(p0[0] - __bfloat162float(phv[0].x),
                               p0[1] - __bfloat162float(phv[0].y));
        pl[1] = pack_hi_bf16x2(p0[2] - __bfloat162float(phv[1].x),
                               p0[3] - __bfloat162float(phv[1].y));
        pl[2] = pack_hi_bf16x2(p1[0] - __bfloat162float(phv[2].x),
                               p1[1] - __bfloat162float(phv[2].y));
        pl[3] = pack_hi_bf16x2(p1[2] - __bfloat162float(phv[3].x),
                               p1[3] - __bfloat162float(phv[3].y));
#pragma unroll
        for (int nj = 0; nj < 2; nj++) {
            int vb = (8 * nj + g) * VPAD + 16 * kt + 2 * t;
            uint32_t vh[2], vl[2];
            vh[0] = *(const uint32_t*)&sVt_h[vb];
            vh[1] = *(const uint32_t*)&sVt_h[vb + 8];
            vl[0] = *(const uint32_t*)&sVt_l[vb];
            vl[1] = *(const uint32_t*)&sVt_l[vb + 8];
            MMA(oacc[nj], ph, vh);
            MMA(oacc[nj], pl, vh);
            MMA(oacc[nj], ph, vl);
        }
    }

    // output: normalize, split, store
    long og  = (tokbase + row0 + g) * 128 + hoff;
    long og8 = og + 8 * 128;
#pragma unroll
    for (int nj = 0; nj < 2; nj++) {
        int dn = 8 * nj + 2 * t;
        split_pair(oacc[nj][0] * rs_g,  oacc[nj][1] * rs_g,
                   g_attn_h + og + dn,  g_attn_l + og + dn);
        split_pair(oacc[nj][2] * rs_g8, oacc[nj][3] * rs_g8,
                   g_attn_h + og8 + dn, g_attn_l + og8 + dn);
    }
}

// -------- K6: window-reverse + roll + residual + LN2 (-> x1 f32, xn2 split) ------
__global__ void scatter_ln2_kernel(const float* __restrict__ x,
                                   const float* __restrict__ g2,
                                   const float* __restrict__ b2) {
    int tk = (blockIdx.x * blockDim.x + threadIdx.x) >> 5;
    int lane = threadIdx.x & 31;
    if (tk >= NTOK) return;
    int w = tk & 63, h = (tk >> 6) & 63, d = (tk >> 12) & 7, bb = tk >> 15;
    int sd = (d + 7) & 7;
    int sh = (h + 60) & 63;
    int sw = (w + 60) & 63;
    int bw = bb * 256 + (sd >> 1) * 64 + (sh >> 3) * 8 + (sw >> 3);
    int n  = (sd & 1) * 64 + (sh & 7) * 8 + (sw & 7);

    float4 xv = *(const float4*)(x + (long)tk * C_ + lane * 4);
    float4 pv = *(const float4*)(g_projout + ((long)bw * NN_ + n) * C_ + lane * 4);
    float4 s1;
    s1.x = xv.x + pv.x; s1.y = xv.y + pv.y;
    s1.z = xv.z + pv.z; s1.w = xv.w + pv.w;
    *(float4*)(g_x1 + (long)tk * C_ + lane * 4) = s1;

    float s  = s1.x + s1.y + s1.z + s1.w;
    float sq = s1.x * s1.x + s1.y * s1.y + s1.z * s1.z + s1.w * s1.w;
#pragma unroll
    for (int o = 16; o > 0; o >>= 1) {
        s  += __shfl_xor_sync(0xffffffffu, s, o);
        sq += __shfl_xor_sync(0xffffffffu, sq, o);
    }
    float mean = s * (1.0f / C_);
    float var  = sq * (1.0f / C_) - mean * mean;
    float inv  = rsqrtf(var + 1e-5f);
    float4 gg = *(const float4*)(g2 + lane * 4);
    float4 bv = *(const float4*)(b2 + lane * 4);
    long o = (long)tk * C_ + lane * 4;
    split_pair((s1.x - mean) * inv * gg.x + bv.x, (s1.y - mean) * inv * gg.y + bv.y,
               g_xn2_h + o, g_xn2_l + o);
    split_pair((s1.z - mean) * inv * gg.z + bv.z, (s1.w - mean) * inv * gg.w + bv.w,
               g_xn2_h + o + 2, g_xn2_l + o + 2);
}

// ---------------------------------------------------------------------------
extern "C" void kernel_launch(void* const* d_in, const int* in_sizes, int n_in,
                              void* d_out, int out_size) {
    const float* x      = (const float*)d_in[0];
    const float* qkv_w  = (const float*)d_in[1];
    const float* qkv_b  = (const float*)d_in[2];
    const float* proj_w = (const float*)d_in[3];
    const float* proj_b = (const float*)d_in[4];
    const float* rpb    = (const float*)d_in[5];
    const float* ln1_g  = (const float*)d_in[6];
    const float* ln1_b  = (const float*)d_in[7];
    const float* ln2_g  = (const float*)d_in[8];
    const float* ln2_b  = (const float*)d_in[9];
    const float* fc1_w  = (const float*)d_in[10];
    const float* fc1_b  = (const float*)d_in[11];
    const float* fc2_w  = (const float*)d_in[12];
    const float* fc2_b  = (const float*)d_in[13];
    float* out = (float*)d_out;

    bf16 *p_win_h, *p_win_l, *p_qkv_h, *p_qkv_l, *p_attn_h, *p_attn_l;
    bf16 *p_xn2_h, *p_xn2_l, *p_hid_h, *p_hid_l;
    bf16 *p_qkvw_h, *p_qkvw_l, *p_projw_h, *p_projw_l;
    bf16 *p_fc1w_h, *p_fc1w_l, *p_fc2w_h, *p_fc2w_l;
    float *p_projout, *p_x1;
    cudaGetSymbolAddress((void**)&p_win_h,   g_win_h);
    cudaGetSymbolAddress((void**)&p_win_l,   g_win_l);
    cudaGetSymbolAddress((void**)&p_qkv_h,   g_qkv_h);
    cudaGetSymbolAddress((void**)&p_qkv_l,   g_qkv_l);
    cudaGetSymbolAddress((void**)&p_attn_h,  g_attn_h);
    cudaGetSymbolAddress((void**)&p_attn_l,  g_attn_l);
    cudaGetSymbolAddress((void**)&p_xn2_h,   g_xn2_h);
    cudaGetSymbolAddress((void**)&p_xn2_l,   g_xn2_l);
    cudaGetSymbolAddress((void**)&p_hid_h,   g_hid_h);
    cudaGetSymbolAddress((void**)&p_hid_l,   g_hid_l);
    cudaGetSymbolAddress((void**)&p_qkvw_h,  g_qkvw_h);
    cudaGetSymbolAddress((void**)&p_qkvw_l,  g_qkvw_l);
    cudaGetSymbolAddress((void**)&p_projw_h, g_projw_h);
    cudaGetSymbolAddress((void**)&p_projw_l, g_projw_l);
    cudaGetSymbolAddress((void**)&p_fc1w_h,  g_fc1w_h);
    cudaGetSymbolAddress((void**)&p_fc1w_l,  g_fc1w_l);
    cudaGetSymbolAddress((void**)&p_fc2w_h,  g_fc2w_h);
    cudaGetSymbolAddress((void**)&p_fc2w_l,  g_fc2w_l);
    cudaGetSymbolAddress((void**)&p_projout, g_projout);
    cudaGetSymbolAddress((void**)&p_x1,      g_x1);

    // 0) weight splits
    split_kernel<<<(384 * C_ + 255) / 256, 256>>>(qkv_w, p_qkvw_h, p_qkvw_l, 384 * C_);
    split_kernel<<<(C_ * C_ + 255) / 256, 256>>>(proj_w, p_projw_h, p_projw_l, C_ * C_);
    split_kernel<<<(MLPH * C_ + 255) / 256, 256>>>(fc1_w, p_fc1w_h, p_fc1w_l, MLPH * C_);
    split_kernel<<<(C_ * MLPH + 255) / 256, 256>>>(fc2_w, p_fc2w_h, p_fc2w_l, C_ * MLPH);
    bias_kernel<<<128, 128>>>(rpb);

    // 1) LN1 + shift + partition
    ln_gather_kernel<<<8192, 256>>>(x, ln1_g, ln1_b);
    // 2) QKV GEMM (q scaled by 0.25 for n<128), split output
    mma_gemm<0, false, true><<<dim3(3, 512), 256>>>(
        p_win_h, p_win_l, p_qkvw_h, p_qkvw_l, qkv_b, nullptr,
        nullptr, p_qkv_h, p_qkv_l, 384, 128, 128);
    // 3) attention (tensor cores)
    attn_kernel<<<NWIN * NH_, 256>>>();
    // 4) proj GEMM -> f32
    mma_gemm<0, false, false><<<dim3(1, 512), 256>>>(
        p_attn_h, p_attn_l, p_projw_h, p_projw_l, proj_b, nullptr,
        p_projout, nullptr, nullptr, 128, 128, 0);
    // 5) reverse + roll + residual + LN2
    scatter_ln2_kernel<<<8192, 256>>>(x, ln2_g, ln2_b);
    // 6) fc1 + GELU -> split
    mma_gemm<1, false, true><<<dim3(4, 512), 256>>>(
        p_xn2_h, p_xn2_l, p_fc1w_h, p_fc1w_l, fc1_b, nullptr,
        nullptr, p_hid_h, p_hid_l, 512, 128, 0);
    // 7) fc2 + residual -> out (f32)
    mma_gemm<0, true, false><<<dim3(1, 512), 256>>>(
        p_hid_h, p_hid_l, p_fc2w_h, p_fc2w_l, fc2_b, p_x1,
        out, nullptr, nullptr, 128, 512, 0);
}

// round 6
// speedup vs baseline: 3.5784x; 1.9352x over previous
#include <cuda_runtime.h>
#include <cuda_fp16.h>
#include <math.h>
#include <stdint.h>

// Problem constants
#define B_    2
#define D_    8
#define C_    128
#define NH_   8
#define NTOK  65536
#define NWIN  512
#define NN_   128
#define MLPH  512

// ---------------- scratch (device globals) -----------------------------------
__device__ half  g_win[NTOK * C_];
__device__ half  g_qkv[(long)NTOK * 384];
__device__ float g_bias[NH_ * NN_ * NN_];     // [h][n(query)][m(key)]
__device__ half  g_attn[NTOK * C_];
__device__ float g_projout[NTOK * C_];
__device__ float g_x1[NTOK * C_];
__device__ half  g_xn2[NTOK * C_];
__device__ half  g_hid[(long)NTOK * MLPH];
// fp16 weights
__device__ half  g_qkvw[384 * C_];
__device__ half  g_projw[C_ * C_];
__device__ half  g_fc1w[MLPH * C_];
__device__ half  g_fc2w[C_ * MLPH];

__device__ __forceinline__ float gelu_exact(float x) {
    return 0.5f * x * (1.0f + erff(x * 0.70710678118654752f));
}

// ---- mma.sync m16n8k16 f16 -> f32 ------------------------------------------------
#define MMA(d, a, b)                                                            \
    asm volatile("mma.sync.aligned.m16n8k16.row.col.f32.f16.f16.f32 "           \
        "{%0,%1,%2,%3}, {%4,%5,%6,%7}, {%8,%9}, {%0,%1,%2,%3};"                 \
        : "+f"((d)[0]), "+f"((d)[1]), "+f"((d)[2]), "+f"((d)[3])                \
        : "r"((a)[0]), "r"((a)[1]), "r"((a)[2]), "r"((a)[3]),                    \
          "r"((b)[0]), "r"((b)[1]))

__device__ __forceinline__ uint32_t packh2(float v0, float v1) {
    half2 h = __floats2half2_rn(v0, v1);
    return *(uint32_t*)&h;
}

// ==================  GEMM: fp16 inputs, fp32 accum  ===============================
// C[M,N] = act( A @ W^T + bias ) (+res). BM=128 BN=128 BK=32, 256 thr, warp 64x32.
#define PADK 40

template <int ACT, bool RES, bool OHALF>
__global__ void __launch_bounds__(256)
mma_gemm(const half* __restrict__ A, const half* __restrict__ W,
         const float* __restrict__ bias, const float* __restrict__ res,
         float* __restrict__ Cf, half* __restrict__ Chf,
         int N, int K, int qlim) {
    __shared__ half sA[128 * PADK];
    __shared__ half sW[128 * PADK];

    int tid = threadIdx.x, wid = tid >> 5, lane = tid & 31;
    int g = lane >> 2, t = lane & 3;
    int m0 = blockIdx.y * 128, n0 = blockIdx.x * 128;
    int wm = (wid & 1) * 64, wn = (wid >> 1) * 32;

    float acc[4][4][4];
#pragma unroll
    for (int i = 0; i < 4; i++)
#pragma unroll
        for (int j = 0; j < 4; j++)
#pragma unroll
            for (int c = 0; c < 4; c++) acc[i][j][c] = 0.0f;

    // copy: 512 uint4 per array per chunk -> 2/thread/array
    int crow0 = tid >> 2, cseg0 = (tid & 3) * 8;
    int crow1 = (tid + 256) >> 2, cseg1 = cseg0;

    uint4 pa0 = *(const uint4*)(A + (long)(m0 + crow0) * K + cseg0);
    uint4 pa1 = *(const uint4*)(A + (long)(m0 + crow1) * K + cseg1);
    uint4 pw0 = *(const uint4*)(W + (long)(n0 + crow0) * K + cseg0);
    uint4 pw1 = *(const uint4*)(W + (long)(n0 + crow1) * K + cseg1);

    int nch = K >> 5;
    for (int c = 0; c < nch; c++) {
        *(uint4*)(sA + crow0 * PADK + cseg0) = pa0;
        *(uint4*)(sA + crow1 * PADK + cseg1) = pa1;
        *(uint4*)(sW + crow0 * PADK + cseg0) = pw0;
        *(uint4*)(sW + crow1 * PADK + cseg1) = pw1;
        __syncthreads();
        if (c + 1 < nch) {
            int kc = (c + 1) << 5;
            pa0 = *(const uint4*)(A + (long)(m0 + crow0) * K + kc + cseg0);
            pa1 = *(const uint4*)(A + (long)(m0 + crow1) * K + kc + cseg1);
            pw0 = *(const uint4*)(W + (long)(n0 + crow0) * K + kc + cseg0);
            pw1 = *(const uint4*)(W + (long)(n0 + crow1) * K + kc + cseg1);
        }
#pragma unroll
        for (int ks = 0; ks < 2; ks++) {
            int kb = ks * 16 + 2 * t;
            uint32_t fa[4][4], fb[4][2];
#pragma unroll
            for (int mi = 0; mi < 4; mi++) {
                int base = (wm + mi * 16 + g) * PADK + kb;
                fa[mi][0] = *(const uint32_t*)&sA[base];
                fa[mi][1] = *(const uint32_t*)&sA[base + 8 * PADK];
                fa[mi][2] = *(const uint32_t*)&sA[base + 8];
                fa[mi][3] = *(const uint32_t*)&sA[base + 8 * PADK + 8];
            }
#pragma unroll
            for (int nj = 0; nj < 4; nj++) {
                int base = (wn + nj * 8 + g) * PADK + kb;
                fb[nj][0] = *(const uint32_t*)&sW[base];
                fb[nj][1] = *(const uint32_t*)&sW[base + 8];
            }
#pragma unroll
            for (int mi = 0; mi < 4; mi++)
#pragma unroll
                for (int nj = 0; nj < 4; nj++)
                    MMA(acc[mi][nj], fa[mi], fb[nj]);
        }
        __syncthreads();
    }

    // epilogue
#pragma unroll
    for (int mi = 0; mi < 4; mi++) {
#pragma unroll
        for (int cr = 0; cr < 2; cr++) {
            int m = m0 + wm + mi * 16 + g + cr * 8;
#pragma unroll
            for (int nj = 0; nj < 4; nj++) {
                int n = n0 + wn + nj * 8 + 2 * t;
                float2 bb = *(const float2*)(bias + n);
                float v0 = acc[mi][nj][cr * 2 + 0] + bb.x;
                float v1 = acc[mi][nj][cr * 2 + 1] + bb.y;
                if (n < qlim) { v0 *= 0.25f; v1 *= 0.25f; }
                if (ACT == 1) { v0 = gelu_exact(v0); v1 = gelu_exact(v1); }
                if (RES) {
                    float2 r = *(const float2*)(res + (long)m * N + n);
                    v0 += r.x; v1 += r.y;
                }
                if (OHALF) {
                    *(half2*)(Chf + (long)m * N + n) = __floats2half2_rn(v0, v1);
                } else {
                    float2 o; o.x = v0; o.y = v1;
                    *(float2*)(Cf + (long)m * N + n) = o;
                }
            }
        }
    }
}

// ---------------- weight convert (one launch) -----------------------------------
__global__ void convert_weights(const float* __restrict__ qkv_w,
                                const float* __restrict__ proj_w,
                                const float* __restrict__ fc1_w,
                                const float* __restrict__ fc2_w) {
    int i = blockIdx.x * blockDim.x + threadIdx.x;   // 0..65535
    if (i < 49152) g_qkvw[i] = __float2half(qkv_w[i]);
    if (i < 16384) g_projw[i] = __float2half(proj_w[i]);
    g_fc1w[i] = __float2half(fc1_w[i]);
    g_fc2w[i] = __float2half(fc2_w[i]);
}

// ---------------- K1: LN1 + cyclic shift + window partition (-> fp16) ------------
__global__ void ln_gather_kernel(const float* __restrict__ x,
                                 const float* __restrict__ g,
                                 const float* __restrict__ b) {
    int warp = (blockIdx.x * blockDim.x + threadIdx.x) >> 5;
    int lane = threadIdx.x & 31;
    if (warp >= NWIN * NN_) return;
    int bw = warp >> 7;
    int n  = warp & 127;
    int bb = bw >> 8;
    int wi = bw & 255;
    int wd = wi >> 6, wh = (wi >> 3) & 7, ww = wi & 7;
    int td = n >> 6,  th = (n >> 3) & 7, tw = n & 7;
    int gd = (wd * 2 + td + 1) & 7;
    int gh = (wh * 8 + th + 4) & 63;
    int gw = (ww * 8 + tw + 4) & 63;
    long src = (((long)(bb * D_ + gd) * 64 + gh) * 64 + gw) * C_;

    float4 v = *(const float4*)(x + src + lane * 4);
    float s  = v.x + v.y + v.z + v.w;
    float sq = v.x * v.x + v.y * v.y + v.z * v.z + v.w * v.w;
#pragma unroll
    for (int o = 16; o > 0; o >>= 1) {
        s  += __shfl_xor_sync(0xffffffffu, s, o);
        sq += __shfl_xor_sync(0xffffffffu, sq, o);
    }
    float mean = s * (1.0f / C_);
    float var  = sq * (1.0f / C_) - mean * mean;
    float inv  = rsqrtf(var + 1e-5f);
    float4 gg = *(const float4*)(g + lane * 4);
    float4 bv = *(const float4*)(b + lane * 4);
    long o = (long)warp * C_ + lane * 4;
    *(half2*)(g_win + o)     = __floats2half2_rn((v.x - mean) * inv * gg.x + bv.x,
                                                 (v.y - mean) * inv * gg.y + bv.y);
    *(half2*)(g_win + o + 2) = __floats2half2_rn((v.z - mean) * inv * gg.z + bv.z,
                                                 (v.w - mean) * inv * gg.w + bv.w);
}

// ---------------- K2: relative position bias table ([h][query][key]) -------------
__global__ void bias_kernel(const float* __restrict__ rpb) {
    int n = blockIdx.x;    // query
    int m = threadIdx.x;   // key
    int nd = n >> 6, nh = (n >> 3) & 7, nw = n & 7;
    int md = m >> 6, mh = (m >> 3) & 7, mw = m & 7;
    int rpi = (nd - md + 1) * 225 + (nh - mh + 7) * 15 + (nw - mw + 7);
#pragma unroll
    for (int h = 0; h < NH_; h++)
        g_bias[((long)h * NN_ + n) * NN_ + m] = rpb[rpi * NH_ + h];
}

// ---------------- K3: tensor-core attention, CTA=(window,head), 8 warps ----------
#define VPAD 136
__global__ void __launch_bounds__(256) attn_kernel() {
    __shared__ half sVt[16 * VPAD];
    __shared__ int  lab[NN_];

    int bw = blockIdx.x >> 3;
    int h  = blockIdx.x & 7;
    int tid = threadIdx.x, wid = tid >> 5, lane = tid & 31;
    int g = lane >> 2, t = lane & 3;
    long tokbase = (long)bw * 128;
    int hoff = h * 16;

    // stage V^T (dim-major) into smem
    {
        int tok = tid >> 1;
        int d0  = (tid & 1) * 8;
        uint4 hv = *(const uint4*)(g_qkv + (tokbase + tok) * 384 + 256 + hoff + d0);
        const half* hp = (const half*)&hv;
#pragma unroll
        for (int d = 0; d < 8; d++)
            sVt[(d0 + d) * VPAD + tok] = hp[d];
    }
    if (tid < 128) {
        int wi = bw & 255;
        int sd = (wi >> 6) * 2 + (tid >> 6);
        int sh = ((wi >> 3) & 7) * 8 + ((tid >> 3) & 7);
        int sw = (wi & 7) * 8 + (tid & 7);
        int ld = sd < 6 ? 0 : (sd < 7 ? 1 : 2);
        int lh = sh < 56 ? 0 : (sh < 60 ? 1 : 2);
        int lw = sw < 56 ? 0 : (sw < 60 ? 1 : 2);
        lab[tid] = ld * 9 + lh * 3 + lw;
    }
    __syncthreads();

    // Q fragments (q pre-scaled by 0.25 in the QKV epilogue)
    int row0 = wid * 16;
    long rg  = (tokbase + row0 + g) * 384 + hoff;
    long rg8 = rg + 8 * 384;
    uint32_t qf[4];
    qf[0] = *(const uint32_t*)(g_qkv + rg + 2 * t);
    qf[1] = *(const uint32_t*)(g_qkv + rg8 + 2 * t);
    qf[2] = *(const uint32_t*)(g_qkv + rg + 2 * t + 8);
    qf[3] = *(const uint32_t*)(g_qkv + rg8 + 2 * t + 8);

    // QK^T
    float acc[16][4];
#pragma unroll
    for (int j = 0; j < 16; j++) {
        long kr = (tokbase + 8 * j + g) * 384 + 128 + hoff + 2 * t;
        uint32_t kf[2];
        kf[0] = *(const uint32_t*)(g_qkv + kr);
        kf[1] = *(const uint32_t*)(g_qkv + kr + 8);
        acc[j][0] = acc[j][1] = acc[j][2] = acc[j][3] = 0.0f;
        MMA(acc[j], qf, kf);
    }

    // bias + mask + exp + row sums
    int myl_g  = lab[row0 + g];
    int myl_g8 = lab[row0 + g + 8];
    const float* bptr = g_bias + (long)h * NN_ * NN_;
    float sum_g = 0.0f, sum_g8 = 0.0f;
#pragma unroll
    for (int j = 0; j < 16; j++) {
        int col = 8 * j + 2 * t;
        float2 bg  = *(const float2*)(bptr + (row0 + g) * NN_ + col);
        float2 bg8 = *(const float2*)(bptr + (row0 + g + 8) * NN_ + col);
        int l0 = lab[col], l1 = lab[col + 1];
        float e0 = (l0 == myl_g)  ? __expf(acc[j][0] + bg.x)  : 0.0f;
        float e1 = (l1 == myl_g)  ? __expf(acc[j][1] + bg.y)  : 0.0f;
        float e2 = (l0 == myl_g8) ? __expf(acc[j][2] + bg8.x) : 0.0f;
        float e3 = (l1 == myl_g8) ? __expf(acc[j][3] + bg8.y) : 0.0f;
        acc[j][0] = e0; acc[j][1] = e1; acc[j][2] = e2; acc[j][3] = e3;
        sum_g += e0 + e1; sum_g8 += e2 + e3;
    }
    sum_g  += __shfl_xor_sync(0xffffffffu, sum_g, 1);
    sum_g  += __shfl_xor_sync(0xffffffffu, sum_g, 2);
    sum_g8 += __shfl_xor_sync(0xffffffffu, sum_g8, 1);
    sum_g8 += __shfl_xor_sync(0xffffffffu, sum_g8, 2);
    float rs_g = 1.0f / sum_g, rs_g8 = 1.0f / sum_g8;

    // P @ V (P fragments chained directly from acc)
    float oacc[2][4];
#pragma unroll
    for (int nj = 0; nj < 2; nj++)
#pragma unroll
        for (int c = 0; c < 4; c++) oacc[nj][c] = 0.0f;

#pragma unroll
    for (int kt = 0; kt < 8; kt++) {
        float* p0 = acc[2 * kt];
        float* p1 = acc[2 * kt + 1];
        uint32_t pf[4];
        pf[0] = packh2(p0[0], p0[1]);
        pf[1] = packh2(p0[2], p0[3]);
        pf[2] = packh2(p1[0], p1[1]);
        pf[3] = packh2(p1[2], p1[3]);
#pragma unroll
        for (int nj = 0; nj < 2; nj++) {
            int vb = (8 * nj + g) * VPAD + 16 * kt + 2 * t;
            uint32_t vf[2];
            vf[0] = *(const uint32_t*)&sVt[vb];
            vf[1] = *(const uint32_t*)&sVt[vb + 8];
            MMA(oacc[nj], pf, vf);
        }
    }

    // output: normalize, store fp16
    long og  = (tokbase + row0 + g) * 128 + hoff;
    long og8 = og + 8 * 128;
#pragma unroll
    for (int nj = 0; nj < 2; nj++) {
        int dn = 8 * nj + 2 * t;
        *(half2*)(g_attn + og + dn)  = __floats2half2_rn(oacc[nj][0] * rs_g,
                                                         oacc[nj][1] * rs_g);
        *(half2*)(g_attn + og8 + dn) = __floats2half2_rn(oacc[nj][2] * rs_g8,
                                                         oacc[nj][3] * rs_g8);
    }
}

// -------- K6: window-reverse + roll + residual + LN2 (-> x1 f32, xn2 fp16) -------
__global__ void scatter_ln2_kernel(const float* __restrict__ x,
                                   const float* __restrict__ g2,
                                   const float* __restrict__ b2) {
    int tk = (blockIdx.x * blockDim.x + threadIdx.x) >> 5;
    int lane = threadIdx.x & 31;
    if (tk >= NTOK) return;
    int w = tk & 63, h = (tk >> 6) & 63, d = (tk >> 12) & 7, bb = tk >> 15;
    int sd = (d + 7) & 7;
    int sh = (h + 60) & 63;
    int sw = (w + 60) & 63;
    int bw = bb * 256 + (sd >> 1) * 64 + (sh >> 3) * 8 + (sw >> 3);
    int n  = (sd & 1) * 64 + (sh & 7) * 8 + (sw & 7);

    float4 xv = *(const float4*)(x + (long)tk * C_ + lane * 4);
    float4 pv = *(const float4*)(g_projout + ((long)bw * NN_ + n) * C_ + lane * 4);
    float4 s1;
    s1.x = xv.x + pv.x; s1.y = xv.y + pv.y;
    s1.z = xv.z + pv.z; s1.w = xv.w + pv.w;
    *(float4*)(g_x1 + (long)tk * C_ + lane * 4) = s1;

    float s  = s1.x + s1.y + s1.z + s1.w;
    float sq = s1.x * s1.x + s1.y * s1.y + s1.z * s1.z + s1.w * s1.w;
#pragma unroll
    for (int o = 16; o > 0; o >>= 1) {
        s  += __shfl_xor_sync(0xffffffffu, s, o);
        sq += __shfl_xor_sync(0xffffffffu, sq, o);
    }
    float mean = s * (1.0f / C_);
    float var  = sq * (1.0f / C_) - mean * mean;
    float inv  = rsqrtf(var + 1e-5f);
    float4 gg = *(const float4*)(g2 + lane * 4);
    float4 bv = *(const float4*)(b2 + lane * 4);
    long o = (long)tk * C_ + lane * 4;
    *(half2*)(g_xn2 + o)     = __floats2half2_rn((s1.x - mean) * inv * gg.x + bv.x,
                                                 (s1.y - mean) * inv * gg.y + bv.y);
    *(half2*)(g_xn2 + o + 2) = __floats2half2_rn((s1.z - mean) * inv * gg.z + bv.z,
                                                 (s1.w - mean) * inv * gg.w + bv.w);
}

// ---------------------------------------------------------------------------
extern "C" void kernel_launch(void* const* d_in, const int* in_sizes, int n_in,
                              void* d_out, int out_size) {
    const float* x      = (const float*)d_in[0];
    const float* qkv_w  = (const float*)d_in[1];
    const float* qkv_b  = (const float*)d_in[2];
    const float* proj_w = (const float*)d_in[3];
    const float* proj_b = (const float*)d_in[4];
    const float* rpb    = (const float*)d_in[5];
    const float* ln1_g  = (const float*)d_in[6];
    const float* ln1_b  = (const float*)d_in[7];
    const float* ln2_g  = (const float*)d_in[8];
    const float* ln2_b  = (const float*)d_in[9];
    const float* fc1_w  = (const float*)d_in[10];
    const float* fc1_b  = (const float*)d_in[11];
    const float* fc2_w  = (const float*)d_in[12];
    const float* fc2_b  = (const float*)d_in[13];
    float* out = (float*)d_out;

    half *p_win, *p_qkv, *p_attn, *p_xn2, *p_hid;
    half *p_qkvw, *p_projw, *p_fc1w, *p_fc2w;
    float *p_projout, *p_x1;
    cudaGetSymbolAddress((void**)&p_win,     g_win);
    cudaGetSymbolAddress((void**)&p_qkv,     g_qkv);
    cudaGetSymbolAddress((void**)&p_attn,    g_attn);
    cudaGetSymbolAddress((void**)&p_xn2,     g_xn2);
    cudaGetSymbolAddress((void**)&p_hid,     g_hid);
    cudaGetSymbolAddress((void**)&p_qkvw,    g_qkvw);
    cudaGetSymbolAddress((void**)&p_projw,   g_projw);
    cudaGetSymbolAddress((void**)&p_fc1w,    g_fc1w);
    cudaGetSymbolAddress((void**)&p_fc2w,    g_fc2w);
    cudaGetSymbolAddress((void**)&p_projout, g_projout);
    cudaGetSymbolAddress((void**)&p_x1,      g_x1);

    // 0) weight convert + bias table
    convert_weights<<<256, 256>>>(qkv_w, proj_w, fc1_w, fc2_w);
    bias_kernel<<<128, 128>>>(rpb);

    // 1) LN1 + shift + partition
    ln_gather_kernel<<<8192, 256>>>(x, ln1_g, ln1_b);
    // 2) QKV GEMM (q scaled by 0.25 for n<128) -> fp16
    mma_gemm<0, false, true><<<dim3(3, 512), 256>>>(
        p_win, p_qkvw, qkv_b, nullptr, nullptr, p_qkv, 384, 128, 128);
    // 3) attention (tensor cores)
    attn_kernel<<<NWIN * NH_, 256>>>();
    // 4) proj GEMM -> f32
    mma_gemm<0, false, false><<<dim3(1, 512), 256>>>(
        p_attn, p_projw, proj_b, nullptr, p_projout, nullptr, 128, 128, 0);
    // 5) reverse + roll + residual + LN2
    scatter_ln2_kernel<<<8192, 256>>>(x, ln2_g, ln2_b);
    // 6) fc1 + GELU -> fp16
    mma_gemm<1, false, true><<<dim3(4, 512), 256>>>(
        p_xn2, p_fc1w, fc1_b, nullptr, nullptr, p_hid, 512, 128, 0);
    // 7) fc2 + residual -> out (f32)
    mma_gemm<0, true, false><<<dim3(1, 512), 256>>>(
        p_hid, p_fc2w, fc2_b, p_x1, out, nullptr, 128, 512, 0);
}

// round 7
// speedup vs baseline: 3.7679x; 1.0530x over previous
#include <cuda_runtime.h>
#include <cuda_fp16.h>
#include <math.h>
#include <stdint.h>

// Problem constants
#define B_    2
#define D_    8
#define C_    128
#define NH_   8
#define NTOK  65536
#define NWIN  512
#define NN_   128
#define MLPH  512

// ---------------- scratch (device globals) -----------------------------------
__device__ half  g_win[NTOK * C_];
__device__ half  g_qkvh[24LL * NTOK * 16];    // [part(3)][head(8)][tok][16]
__device__ float g_bias[NH_ * NN_ * NN_];     // [h][n(query)][m(key)]
__device__ half  g_attn[NTOK * C_];
__device__ float g_projout[NTOK * C_];
__device__ float g_x1[NTOK * C_];
__device__ half  g_xn2[NTOK * C_];
__device__ half  g_hid[(long)NTOK * MLPH];
// fp16 weights
__device__ half  g_qkvw[384 * C_];
__device__ half  g_projw[C_ * C_];
__device__ half  g_fc1w[MLPH * C_];
__device__ half  g_fc2w[C_ * MLPH];

__device__ __forceinline__ float gelu_exact(float x) {
    return 0.5f * x * (1.0f + erff(x * 0.70710678118654752f));
}

// ---- mma.sync m16n8k16 f16 -> f32 ------------------------------------------------
#define MMA(d, a, b)                                                            \
    asm volatile("mma.sync.aligned.m16n8k16.row.col.f32.f16.f16.f32 "           \
        "{%0,%1,%2,%3}, {%4,%5,%6,%7}, {%8,%9}, {%0,%1,%2,%3};"                 \
        : "+f"((d)[0]), "+f"((d)[1]), "+f"((d)[2]), "+f"((d)[3])                \
        : "r"((a)[0]), "r"((a)[1]), "r"((a)[2]), "r"((a)[3]),                    \
          "r"((b)[0]), "r"((b)[1]))

__device__ __forceinline__ uint32_t packh2(float v0, float v1) {
    half2 h = __floats2half2_rn(v0, v1);
    return *(uint32_t*)&h;
}
__device__ __forceinline__ uint32_t smem_u32(const void* p) {
    uint32_t a;
    asm("{ .reg .u64 t; cvta.to.shared.u64 t, %1; cvt.u32.u64 %0, t; }" : "=r"(a) : "l"(p));
    return a;
}
__device__ __forceinline__ void cpa16(uint32_t d, const void* s) {
    asm volatile("cp.async.cg.shared.global [%0], [%1], 16;" :: "r"(d), "l"(s));
}
#define CP_COMMIT() asm volatile("cp.async.commit_group;" ::: "memory")
#define CP_WAIT0()  asm volatile("cp.async.wait_group 0;" ::: "memory")

// ==================  GEMM: fp16, cp.async full-K(128) chunks  =====================
// C[M,N] = act(A @ W^T + bias)(+res). BM=BN=128, BK=128, 256 thr, warp 64x32.
// OMODE: 0 = f32 row-major, 1 = fp16 row-major, 2 = fp16 head-major (QKV)
#define PADK 136

template <int ACT, bool RES, int OMODE>
__global__ void __launch_bounds__(256)
mma_gemm(const half* __restrict__ A, const half* __restrict__ W,
         const float* __restrict__ bias, const float* __restrict__ res,
         float* __restrict__ Cf, half* __restrict__ Chf,
         int N, int K) {
    extern __shared__ half smem[];
    half* sA = smem;
    half* sW = smem + 128 * PADK;
    uint32_t sAu = smem_u32(sA), sWu = smem_u32(sW);

    int tid = threadIdx.x, wid = tid >> 5, lane = tid & 31;
    int g = lane >> 2, t = lane & 3;
    int m0 = blockIdx.y * 128, n0 = blockIdx.x * 128;
    int wm = (wid & 1) * 64, wn = (wid >> 1) * 32;

    float acc[4][4][4];
#pragma unroll
    for (int i = 0; i < 4; i++)
#pragma unroll
        for (int j = 0; j < 4; j++)
#pragma unroll
            for (int c = 0; c < 4; c++) acc[i][j][c] = 0.0f;

    // per-chunk copy: 2048 uint4 per tile, 8 per thread per tile
    // idx = i*256 + tid; row = idx>>4; seg = idx&15
    for (int kc = 0; kc < K; kc += 128) {
#pragma unroll
        for (int i = 0; i < 8; i++) {
            int idx = i * 256 + tid;
            int row = idx >> 4, seg = idx & 15;
            cpa16(sAu + (row * PADK + seg * 8) * 2,
                  A + (long)(m0 + row) * K + kc + seg * 8);
            cpa16(sWu + (row * PADK + seg * 8) * 2,
                  W + (long)(n0 + row) * K + kc + seg * 8);
        }
        CP_COMMIT();
        CP_WAIT0();
        __syncthreads();

#pragma unroll
        for (int ks = 0; ks < 8; ks++) {
            int kb = ks * 16 + 2 * t;
            uint32_t fa[4][4], fb[4][2];
#pragma unroll
            for (int mi = 0; mi < 4; mi++) {
                int base = (wm + mi * 16 + g) * PADK + kb;
                fa[mi][0] = *(const uint32_t*)&sA[base];
                fa[mi][1] = *(const uint32_t*)&sA[base + 8 * PADK];
                fa[mi][2] = *(const uint32_t*)&sA[base + 8];
                fa[mi][3] = *(const uint32_t*)&sA[base + 8 * PADK + 8];
            }
#pragma unroll
            for (int nj = 0; nj < 4; nj++) {
                int base = (wn + nj * 8 + g) * PADK + kb;
                fb[nj][0] = *(const uint32_t*)&sW[base];
                fb[nj][1] = *(const uint32_t*)&sW[base + 8];
            }
#pragma unroll
            for (int mi = 0; mi < 4; mi++)
#pragma unroll
                for (int nj = 0; nj < 4; nj++)
                    MMA(acc[mi][nj], fa[mi], fb[nj]);
        }
        if (kc + 128 < K) __syncthreads();
    }

    // epilogue
#pragma unroll
    for (int mi = 0; mi < 4; mi++) {
#pragma unroll
        for (int cr = 0; cr < 2; cr++) {
            int m = m0 + wm + mi * 16 + g + cr * 8;
#pragma unroll
            for (int nj = 0; nj < 4; nj++) {
                int n = n0 + wn + nj * 8 + 2 * t;
                float2 bb = *(const float2*)(bias + n);
                float v0 = acc[mi][nj][cr * 2 + 0] + bb.x;
                float v1 = acc[mi][nj][cr * 2 + 1] + bb.y;
                if (OMODE == 2 && n < 128) { v0 *= 0.25f; v1 *= 0.25f; }
                if (ACT == 1) { v0 = gelu_exact(v0); v1 = gelu_exact(v1); }
                if (RES) {
                    float2 r = *(const float2*)(res + (long)m * N + n);
                    v0 += r.x; v1 += r.y;
                }
                if (OMODE == 2) {
                    int p = n >> 7, hh = (n >> 4) & 7, d = n & 15;
                    long addr = ((long)(p * 8 + hh) * NTOK + m) * 16 + d;
                    *(half2*)(Chf + addr) = __floats2half2_rn(v0, v1);
                } else if (OMODE == 1) {
                    *(half2*)(Chf + (long)m * N + n) = __floats2half2_rn(v0, v1);
                } else {
                    float2 o; o.x = v0; o.y = v1;
                    *(float2*)(Cf + (long)m * N + n) = o;
                }
            }
        }
    }
}

// ---------------- weight convert (one launch) -----------------------------------
__global__ void convert_weights(const float* __restrict__ qkv_w,
                                const float* __restrict__ proj_w,
                                const float* __restrict__ fc1_w,
                                const float* __restrict__ fc2_w) {
    int i = blockIdx.x * blockDim.x + threadIdx.x;   // 0..65535
    if (i < 49152) g_qkvw[i] = __float2half(qkv_w[i]);
    if (i < 16384) g_projw[i] = __float2half(proj_w[i]);
    g_fc1w[i] = __float2half(fc1_w[i]);
    g_fc2w[i] = __float2half(fc2_w[i]);
}

// ---------------- K1: LN1 + cyclic shift + window partition (-> fp16) ------------
__global__ void ln_gather_kernel(const float* __restrict__ x,
                                 const float* __restrict__ g,
                                 const float* __restrict__ b) {
    int warp = (blockIdx.x * blockDim.x + threadIdx.x) >> 5;
    int lane = threadIdx.x & 31;
    if (warp >= NWIN * NN_) return;
    int bw = warp >> 7;
    int n  = warp & 127;
    int bb = bw >> 8;
    int wi = bw & 255;
    int wd = wi >> 6, wh = (wi >> 3) & 7, ww = wi & 7;
    int td = n >> 6,  th = (n >> 3) & 7, tw = n & 7;
    int gd = (wd * 2 + td + 1) & 7;
    int gh = (wh * 8 + th + 4) & 63;
    int gw = (ww * 8 + tw + 4) & 63;
    long src = (((long)(bb * D_ + gd) * 64 + gh) * 64 + gw) * C_;

    float4 v = *(const float4*)(x + src + lane * 4);
    float s  = v.x + v.y + v.z + v.w;
    float sq = v.x * v.x + v.y * v.y + v.z * v.z + v.w * v.w;
#pragma unroll
    for (int o = 16; o > 0; o >>= 1) {
        s  += __shfl_xor_sync(0xffffffffu, s, o);
        sq += __shfl_xor_sync(0xffffffffu, sq, o);
    }
    float mean = s * (1.0f / C_);
    float var  = sq * (1.0f / C_) - mean * mean;
    float inv  = rsqrtf(var + 1e-5f);
    float4 gg = *(const float4*)(g + lane * 4);
    float4 bv = *(const float4*)(b + lane * 4);
    long o = (long)warp * C_ + lane * 4;
    *(half2*)(g_win + o)     = __floats2half2_rn((v.x - mean) * inv * gg.x + bv.x,
                                                 (v.y - mean) * inv * gg.y + bv.y);
    *(half2*)(g_win + o + 2) = __floats2half2_rn((v.z - mean) * inv * gg.z + bv.z,
                                                 (v.w - mean) * inv * gg.w + bv.w);
}

// ---------------- K2: relative position bias table ([h][query][key]) -------------
__global__ void bias_kernel(const float* __restrict__ rpb) {
    int n = blockIdx.x;    // query
    int m = threadIdx.x;   // key
    int nd = n >> 6, nh = (n >> 3) & 7, nw = n & 7;
    int md = m >> 6, mh = (m >> 3) & 7, mw = m & 7;
    int rpi = (nd - md + 1) * 225 + (nh - mh + 7) * 15 + (nw - mw + 7);
#pragma unroll
    for (int h = 0; h < NH_; h++)
        g_bias[((long)h * NN_ + n) * NN_ + m] = rpb[rpi * NH_ + h];
}

// ---------------- K3: tensor-core attention, CTA=(window,head), 8 warps ----------
#define VPAD 136
__global__ void __launch_bounds__(256) attn_kernel() {
    __shared__ half sVt[16 * VPAD];
    __shared__ int  lab[NN_];

    int bw = blockIdx.x >> 3;
    int h  = blockIdx.x & 7;
    int tid = threadIdx.x, wid = tid >> 5, lane = tid & 31;
    int g = lane >> 2, t = lane & 3;
    long tokbase = (long)bw * 128;
    const half* Qp = g_qkvh + ((long)h * NTOK + tokbase) * 16;
    const half* Kp = g_qkvh + ((long)(8 + h) * NTOK + tokbase) * 16;
    const half* Vp = g_qkvh + ((long)(16 + h) * NTOK + tokbase) * 16;

    // stage V^T (dim-major) into smem — fully coalesced reads
    {
        int tok = tid >> 1;
        int d0  = (tid & 1) * 8;
        uint4 hv = *(const uint4*)(Vp + tok * 16 + d0);
        const half* hp = (const half*)&hv;
#pragma unroll
        for (int d = 0; d < 8; d++)
            sVt[(d0 + d) * VPAD + tok] = hp[d];
    }
    if (tid < 128) {
        int wi = bw & 255;
        int sd = (wi >> 6) * 2 + (tid >> 6);
        int sh = ((wi >> 3) & 7) * 8 + ((tid >> 3) & 7);
        int sw = (wi & 7) * 8 + (tid & 7);
        int ld = sd < 6 ? 0 : (sd < 7 ? 1 : 2);
        int lh = sh < 56 ? 0 : (sh < 60 ? 1 : 2);
        int lw = sw < 56 ? 0 : (sw < 60 ? 1 : 2);
        lab[tid] = ld * 9 + lh * 3 + lw;
    }
    __syncthreads();

    // Q fragments (q pre-scaled by 0.25 in the QKV epilogue)
    int row0 = wid * 16;
    uint32_t qf[4];
    qf[0] = *(const uint32_t*)(Qp + (row0 + g) * 16 + 2 * t);
    qf[1] = *(const uint32_t*)(Qp + (row0 + g + 8) * 16 + 2 * t);
    qf[2] = *(const uint32_t*)(Qp + (row0 + g) * 16 + 2 * t + 8);
    qf[3] = *(const uint32_t*)(Qp + (row0 + g + 8) * 16 + 2 * t + 8);

    // QK^T
    float acc[16][4];
#pragma unroll
    for (int j = 0; j < 16; j++) {
        uint32_t kf[2];
        kf[0] = *(const uint32_t*)(Kp + (8 * j + g) * 16 + 2 * t);
        kf[1] = *(const uint32_t*)(Kp + (8 * j + g) * 16 + 2 * t + 8);
        acc[j][0] = acc[j][1] = acc[j][2] = acc[j][3] = 0.0f;
        MMA(acc[j], qf, kf);
    }

    // bias + mask + exp + row sums
    int myl_g  = lab[row0 + g];
    int myl_g8 = lab[row0 + g + 8];
    const float* bptr = g_bias + (long)h * NN_ * NN_;
    float sum_g = 0.0f, sum_g8 = 0.0f;
#pragma unroll
    for (int j = 0; j < 16; j++) {
        int col = 8 * j + 2 * t;
        float2 bg  = *(const float2*)(bptr + (row0 + g) * NN_ + col);
        float2 bg8 = *(const float2*)(bptr + (row0 + g + 8) * NN_ + col);
        int l0 = lab[col], l1 = lab[col + 1];
        float e0 = (l0 == myl_g)  ? __expf(acc[j][0] + bg.x)  : 0.0f;
        float e1 = (l1 == myl_g)  ? __expf(acc[j][1] + bg.y)  : 0.0f;
        float e2 = (l0 == myl_g8) ? __expf(acc[j][2] + bg8.x) : 0.0f;
        float e3 = (l1 == myl_g8) ? __expf(acc[j][3] + bg8.y) : 0.0f;
        acc[j][0] = e0; acc[j][1] = e1; acc[j][2] = e2; acc[j][3] = e3;
        sum_g += e0 + e1; sum_g8 += e2 + e3;
    }
    sum_g  += __shfl_xor_sync(0xffffffffu, sum_g, 1);
    sum_g  += __shfl_xor_sync(0xffffffffu, sum_g, 2);
    sum_g8 += __shfl_xor_sync(0xffffffffu, sum_g8, 1);
    sum_g8 += __shfl_xor_sync(0xffffffffu, sum_g8, 2);
    float rs_g = 1.0f / sum_g, rs_g8 = 1.0f / sum_g8;

    // P @ V (P fragments chained from acc)
    float oacc[2][4];
#pragma unroll
    for (int nj = 0; nj < 2; nj++)
#pragma unroll
        for (int c = 0; c < 4; c++) oacc[nj][c] = 0.0f;

#pragma unroll
    for (int kt = 0; kt < 8; kt++) {
        float* p0 = acc[2 * kt];
        float* p1 = acc[2 * kt + 1];
        uint32_t pf[4];
        pf[0] = packh2(p0[0], p0[1]);
        pf[1] = packh2(p0[2], p0[3]);
        pf[2] = packh2(p1[0], p1[1]);
        pf[3] = packh2(p1[2], p1[3]);
#pragma unroll
        for (int nj = 0; nj < 2; nj++) {
            int vb = (8 * nj + g) * VPAD + 16 * kt + 2 * t;
            uint32_t vf[2];
            vf[0] = *(const uint32_t*)&sVt[vb];
            vf[1] = *(const uint32_t*)&sVt[vb + 8];
            MMA(oacc[nj], pf, vf);
        }
    }

    // output: normalize, store fp16 row-major [tok][128]
    long og  = (tokbase + row0 + g) * 128 + h * 16;
    long og8 = og + 8 * 128;
#pragma unroll
    for (int nj = 0; nj < 2; nj++) {
        int dn = 8 * nj + 2 * t;
        *(half2*)(g_attn + og + dn)  = __floats2half2_rn(oacc[nj][0] * rs_g,
                                                         oacc[nj][1] * rs_g);
        *(half2*)(g_attn + og8 + dn) = __floats2half2_rn(oacc[nj][2] * rs_g8,
                                                         oacc[nj][3] * rs_g8);
    }
}

// -------- K6: window-reverse + roll + residual + LN2 (-> x1 f32, xn2 fp16) -------
__global__ void scatter_ln2_kernel(const float* __restrict__ x,
                                   const float* __restrict__ g2,
                                   const float* __restrict__ b2) {
    int tk = (blockIdx.x * blockDim.x + threadIdx.x) >> 5;
    int lane = threadIdx.x & 31;
    if (tk >= NTOK) return;
    int w = tk & 63, h = (tk >> 6) & 63, d = (tk >> 12) & 7, bb = tk >> 15;
    int sd = (d + 7) & 7;
    int sh = (h + 60) & 63;
    int sw = (w + 60) & 63;
    int bw = bb * 256 + (sd >> 1) * 64 + (sh >> 3) * 8 + (sw >> 3);
    int n  = (sd & 1) * 64 + (sh & 7) * 8 + (sw & 7);

    float4 xv = *(const float4*)(x + (long)tk * C_ + lane * 4);
    float4 pv = *(const float4*)(g_projout + ((long)bw * NN_ + n) * C_ + lane * 4);
    float4 s1;
    s1.x = xv.x + pv.x; s1.y = xv.y + pv.y;
    s1.z = xv.z + pv.z; s1.w = xv.w + pv.w;
    *(float4*)(g_x1 + (long)tk * C_ + lane * 4) = s1;

    float s  = s1.x + s1.y + s1.z + s1.w;
    float sq = s1.x * s1.x + s1.y * s1.y + s1.z * s1.z + s1.w * s1.w;
#pragma unroll
    for (int o = 16; o > 0; o >>= 1) {
        s  += __shfl_xor_sync(0xffffffffu, s, o);
        sq += __shfl_xor_sync(0xffffffffu, sq, o);
    }
    float mean = s * (1.0f / C_);
    float var  = sq * (1.0f / C_) - mean * mean;
    float inv  = rsqrtf(var + 1e-5f);
    float4 gg = *(const float4*)(g2 + lane * 4);
    float4 bv = *(const float4*)(b2 + lane * 4);
    long o = (long)tk * C_ + lane * 4;
    *(half2*)(g_xn2 + o)     = __floats2half2_rn((s1.x - mean) * inv * gg.x + bv.x,
                                                 (s1.y - mean) * inv * gg.y + bv.y);
    *(half2*)(g_xn2 + o + 2) = __floats2half2_rn((s1.z - mean) * inv * gg.z + bv.z,
                                                 (s1.w - mean) * inv * gg.w + bv.w);
}

// ---------------------------------------------------------------------------
extern "C" void kernel_launch(void* const* d_in, const int* in_sizes, int n_in,
                              void* d_out, int out_size) {
    const float* x      = (const float*)d_in[0];
    const float* qkv_w  = (const float*)d_in[1];
    const float* qkv_b  = (const float*)d_in[2];
    const float* proj_w = (const float*)d_in[3];
    const float* proj_b = (const float*)d_in[4];
    const float* rpb    = (const float*)d_in[5];
    const float* ln1_g  = (const float*)d_in[6];
    const float* ln1_b  = (const float*)d_in[7];
    const float* ln2_g  = (const float*)d_in[8];
    const float* ln2_b  = (const float*)d_in[9];
    const float* fc1_w  = (const float*)d_in[10];
    const float* fc1_b  = (const float*)d_in[11];
    const float* fc2_w  = (const float*)d_in[12];
    const float* fc2_b  = (const float*)d_in[13];
    float* out = (float*)d_out;

    half *p_win, *p_qkvh, *p_attn, *p_xn2, *p_hid;
    half *p_qkvw, *p_projw, *p_fc1w, *p_fc2w;
    float *p_projout, *p_x1;
    cudaGetSymbolAddress((void**)&p_win,     g_win);
    cudaGetSymbolAddress((void**)&p_qkvh,    g_qkvh);
    cudaGetSymbolAddress((void**)&p_attn,    g_attn);
    cudaGetSymbolAddress((void**)&p_xn2,     g_xn2);
    cudaGetSymbolAddress((void**)&p_hid,     g_hid);
    cudaGetSymbolAddress((void**)&p_qkvw,    g_qkvw);
    cudaGetSymbolAddress((void**)&p_projw,   g_projw);
    cudaGetSymbolAddress((void**)&p_fc1w,    g_fc1w);
    cudaGetSymbolAddress((void**)&p_fc2w,    g_fc2w);
    cudaGetSymbolAddress((void**)&p_projout, g_projout);
    cudaGetSymbolAddress((void**)&p_x1,      g_x1);

    const int SMEM = 2 * 128 * PADK * 2;   // 69632 B
    cudaFuncSetAttribute(mma_gemm<0, false, 2>, cudaFuncAttributeMaxDynamicSharedMemorySize, SMEM);
    cudaFuncSetAttribute(mma_gemm<0, false, 0>, cudaFuncAttributeMaxDynamicSharedMemorySize, SMEM);
    cudaFuncSetAttribute(mma_gemm<1, false, 1>, cudaFuncAttributeMaxDynamicSharedMemorySize, SMEM);
    cudaFuncSetAttribute(mma_gemm<0, true, 0>,  cudaFuncAttributeMaxDynamicSharedMemorySize, SMEM);

    // 0) weight convert + bias table
    convert_weights<<<256, 256>>>(qkv_w, proj_w, fc1_w, fc2_w);
    bias_kernel<<<128, 128>>>(rpb);

    // 1) LN1 + shift + partition
    ln_gather_kernel<<<8192, 256>>>(x, ln1_g, ln1_b);
    // 2) QKV GEMM -> head-major fp16 (q pre-scaled)
    mma_gemm<0, false, 2><<<dim3(3, 512), 256, SMEM>>>(
        p_win, p_qkvw, qkv_b, nullptr, nullptr, p_qkvh, 384, 128);
    // 3) attention (tensor cores)
    attn_kernel<<<NWIN * NH_, 256>>>();
    // 4) proj GEMM -> f32
    mma_gemm<0, false, 0><<<dim3(1, 512), 256, SMEM>>>(
        p_attn, p_projw, proj_b, nullptr, p_projout, nullptr, 128, 128);
    // 5) reverse + roll + residual + LN2
    scatter_ln2_kernel<<<8192, 256>>>(x, ln2_g, ln2_b);
    // 6) fc1 + GELU -> fp16
    mma_gemm<1, false, 1><<<dim3(4, 512), 256, SMEM>>>(
        p_xn2, p_fc1w, fc1_b, nullptr, nullptr, p_hid, 512, 128);
    // 7) fc2 + residual -> out (f32)
    mma_gemm<0, true, 0><<<dim3(1, 512), 256, SMEM>>>(
        p_hid, p_fc2w, fc2_b, p_x1, out, nullptr, 128, 512);
}

// round 8
// speedup vs baseline: 3.9301x; 1.0431x over previous
#include <cuda_runtime.h>
#include <cuda_fp16.h>
#include <math.h>
#include <stdint.h>

// Problem constants
#define B_    2
#define D_    8
#define C_    128
#define NH_   8
#define NTOK  65536
#define NWIN  512
#define NN_   128
#define MLPH  512

// ---------------- scratch (device globals) -----------------------------------
__device__ half  g_win[NTOK * C_];
__device__ half  g_qkvh[24LL * NTOK * 16];    // [part(3)][head(8)][tok][16]
__device__ float g_bias[NH_ * NN_ * NN_];     // [h][n(query)][m(key)]
__device__ half  g_attn[NTOK * C_];
__device__ float g_projout[NTOK * C_];
__device__ float g_x1[NTOK * C_];
__device__ half  g_xn2[NTOK * C_];
__device__ half  g_hid[(long)NTOK * MLPH];
// fp16 weights
__device__ half  g_qkvw[384 * C_];
__device__ half  g_projw[C_ * C_];
__device__ half  g_fc1w[MLPH * C_];
__device__ half  g_fc2w[C_ * MLPH];

__device__ __forceinline__ float gelu_exact(float x) {
    return 0.5f * x * (1.0f + erff(x * 0.70710678118654752f));
}

// ---- mma.sync m16n8k16 f16 -> f32 ------------------------------------------------
#define MMA(d, a, b)                                                            \
    asm volatile("mma.sync.aligned.m16n8k16.row.col.f32.f16.f16.f32 "           \
        "{%0,%1,%2,%3}, {%4,%5,%6,%7}, {%8,%9}, {%0,%1,%2,%3};"                 \
        : "+f"((d)[0]), "+f"((d)[1]), "+f"((d)[2]), "+f"((d)[3])                \
        : "r"((a)[0]), "r"((a)[1]), "r"((a)[2]), "r"((a)[3]),                    \
          "r"((b)[0]), "r"((b)[1]))

#define LDMX4(r, addr)                                                          \
    asm volatile("ldmatrix.sync.aligned.m8n8.x4.shared.b16 {%0,%1,%2,%3}, [%4];"\
        : "=r"((r)[0]), "=r"((r)[1]), "=r"((r)[2]), "=r"((r)[3]) : "r"(addr))
#define LDMX2(r, addr)                                                          \
    asm volatile("ldmatrix.sync.aligned.m8n8.x2.shared.b16 {%0,%1}, [%2];"      \
        : "=r"((r)[0]), "=r"((r)[1]) : "r"(addr))

__device__ __forceinline__ uint32_t packh2(float v0, float v1) {
    half2 h = __floats2half2_rn(v0, v1);
    return *(uint32_t*)&h;
}
__device__ __forceinline__ uint32_t smem_u32(const void* p) {
    uint32_t a;
    asm("{ .reg .u64 t; cvta.to.shared.u64 t, %1; cvt.u32.u64 %0, t; }" : "=r"(a) : "l"(p));
    return a;
}
__device__ __forceinline__ void cpa16(uint32_t d, const void* s) {
    asm volatile("cp.async.cg.shared.global [%0], [%1], 16;" :: "r"(d), "l"(s));
}
#define CP_COMMIT() asm volatile("cp.async.commit_group;" ::: "memory")
#define CP_WAIT0()  asm volatile("cp.async.wait_group 0;" ::: "memory")
#define CP_WAIT1()  asm volatile("cp.async.wait_group 1;" ::: "memory")

// ==================  GEMM: fp16, double-buffered BK=64 pipeline  ==================
// C[M,N] = act(A @ W^T + bias)(+res). BM=BN=128, 256 thr, warp 64x32.
// OMODE: 0 = f32 row-major, 1 = fp16 row-major, 2 = fp16 head-major (QKV)
#define PADK 72
#define BUFB (128 * PADK * 2)     // bytes per stage per tile

template <int ACT, bool RES, int OMODE>
__global__ void __launch_bounds__(256)
mma_gemm(const half* __restrict__ A, const half* __restrict__ W,
         const float* __restrict__ bias, const float* __restrict__ res,
         float* __restrict__ Cf, half* __restrict__ Chf,
         int N, int K) {
    extern __shared__ half smem[];
    half* sA = smem;                       // 2 stages
    half* sW = smem + 2 * 128 * PADK;      // 2 stages
    uint32_t sAu = smem_u32(sA), sWu = smem_u32(sW);

    int tid = threadIdx.x, wid = tid >> 5, lane = tid & 31;
    int g = lane >> 2, t = lane & 3;
    int m0 = blockIdx.y * 128, n0 = blockIdx.x * 128;
    int wm = (wid & 1) * 64, wn = (wid >> 1) * 32;

    float acc[4][4][4];
#pragma unroll
    for (int i = 0; i < 4; i++)
#pragma unroll
        for (int j = 0; j < 4; j++)
#pragma unroll
            for (int c = 0; c < 4; c++) acc[i][j][c] = 0.0f;

    // copy mapping: per tile 1024 uint4 -> 4/thread; idx=i*256+tid
    int crow = tid >> 3, cseg = (tid & 7) * 8;

    auto issue = [&](int kc, int buf) {
#pragma unroll
        for (int i = 0; i < 4; i++) {
            int row = crow + i * 32;
            uint32_t so = (uint32_t)buf * BUFB + (row * PADK + cseg) * 2;
            cpa16(sAu + so, A + (long)(m0 + row) * K + kc + cseg);
            cpa16(sWu + so, W + (long)(n0 + row) * K + kc + cseg);
        }
        CP_COMMIT();
    };

    // ldmatrix per-lane base addresses
    int lrow = lane & 7, lsel = lane >> 3;
    uint32_t aBase = sAu + ((wm + (lsel & 1) * 8 + lrow) * PADK + (lsel >> 1) * 8) * 2;
    uint32_t bBase = sWu + ((wn + lrow) * PADK + (lsel & 1) * 8) * 2;

    int nch = K >> 6;
    issue(0, 0);
    for (int c = 0; c < nch; c++) {
        if (c + 1 < nch) { issue((c + 1) << 6, (c + 1) & 1); CP_WAIT1(); }
        else             { CP_WAIT0(); }
        __syncthreads();
        uint32_t bofs = (uint32_t)(c & 1) * BUFB;
#pragma unroll
        for (int ks = 0; ks < 4; ks++) {
            uint32_t kb2 = ks * 32;        // 16 halves = 32 bytes
            uint32_t fa[4][4], fb[4][2];
#pragma unroll
            for (int mi = 0; mi < 4; mi++)
                LDMX4(fa[mi], aBase + bofs + mi * (16 * PADK * 2) + kb2);
#pragma unroll
            for (int nj = 0; nj < 4; nj++)
                LDMX2(fb[nj], bBase + bofs + nj * (8 * PADK * 2) + kb2);
#pragma unroll
            for (int mi = 0; mi < 4; mi++)
#pragma unroll
                for (int nj = 0; nj < 4; nj++)
                    MMA(acc[mi][nj], fa[mi], fb[nj]);
        }
        __syncthreads();
    }

    // epilogue
#pragma unroll
    for (int mi = 0; mi < 4; mi++) {
#pragma unroll
        for (int cr = 0; cr < 2; cr++) {
            int m = m0 + wm + mi * 16 + g + cr * 8;
#pragma unroll
            for (int nj = 0; nj < 4; nj++) {
                int n = n0 + wn + nj * 8 + 2 * t;
                float2 bb = *(const float2*)(bias + n);
                float v0 = acc[mi][nj][cr * 2 + 0] + bb.x;
                float v1 = acc[mi][nj][cr * 2 + 1] + bb.y;
                if (OMODE == 2 && n < 128) { v0 *= 0.25f; v1 *= 0.25f; }
                if (ACT == 1) { v0 = gelu_exact(v0); v1 = gelu_exact(v1); }
                if (RES) {
                    float2 r = *(const float2*)(res + (long)m * N + n);
                    v0 += r.x; v1 += r.y;
                }
                if (OMODE == 2) {
                    int p = n >> 7, hh = (n >> 4) & 7, d = n & 15;
                    long addr = ((long)(p * 8 + hh) * NTOK + m) * 16 + d;
                    *(half2*)(Chf + addr) = __floats2half2_rn(v0, v1);
                } else if (OMODE == 1) {
                    *(half2*)(Chf + (long)m * N + n) = __floats2half2_rn(v0, v1);
                } else {
                    float2 o; o.x = v0; o.y = v1;
                    *(float2*)(Cf + (long)m * N + n) = o;
                }
            }
        }
    }
}

// ---------------- weight convert (one launch) -----------------------------------
__global__ void convert_weights(const float* __restrict__ qkv_w,
                                const float* __restrict__ proj_w,
                                const float* __restrict__ fc1_w,
                                const float* __restrict__ fc2_w) {
    int i = blockIdx.x * blockDim.x + threadIdx.x;   // 0..65535
    if (i < 49152) g_qkvw[i] = __float2half(qkv_w[i]);
    if (i < 16384) g_projw[i] = __float2half(proj_w[i]);
    g_fc1w[i] = __float2half(fc1_w[i]);
    g_fc2w[i] = __float2half(fc2_w[i]);
}

// ---------------- K1: LN1 + cyclic shift + window partition (-> fp16) ------------
__global__ void ln_gather_kernel(const float* __restrict__ x,
                                 const float* __restrict__ g,
                                 const float* __restrict__ b) {
    int warp = (blockIdx.x * blockDim.x + threadIdx.x) >> 5;
    int lane = threadIdx.x & 31;
    if (warp >= NWIN * NN_) return;
    int bw = warp >> 7;
    int n  = warp & 127;
    int bb = bw >> 8;
    int wi = bw & 255;
    int wd = wi >> 6, wh = (wi >> 3) & 7, ww = wi & 7;
    int td = n >> 6,  th = (n >> 3) & 7, tw = n & 7;
    int gd = (wd * 2 + td + 1) & 7;
    int gh = (wh * 8 + th + 4) & 63;
    int gw = (ww * 8 + tw + 4) & 63;
    long src = (((long)(bb * D_ + gd) * 64 + gh) * 64 + gw) * C_;

    float4 v = *(const float4*)(x + src + lane * 4);
    float s  = v.x + v.y + v.z + v.w;
    float sq = v.x * v.x + v.y * v.y + v.z * v.z + v.w * v.w;
#pragma unroll
    for (int o = 16; o > 0; o >>= 1) {
        s  += __shfl_xor_sync(0xffffffffu, s, o);
        sq += __shfl_xor_sync(0xffffffffu, sq, o);
    }
    float mean = s * (1.0f / C_);
    float var  = sq * (1.0f / C_) - mean * mean;
    float inv  = rsqrtf(var + 1e-5f);
    float4 gg = *(const float4*)(g + lane * 4);
    float4 bv = *(const float4*)(b + lane * 4);
    long o = (long)warp * C_ + lane * 4;
    *(half2*)(g_win + o)     = __floats2half2_rn((v.x - mean) * inv * gg.x + bv.x,
                                                 (v.y - mean) * inv * gg.y + bv.y);
    *(half2*)(g_win + o + 2) = __floats2half2_rn((v.z - mean) * inv * gg.z + bv.z,
                                                 (v.w - mean) * inv * gg.w + bv.w);
}

// ---------------- K2: relative position bias table ([h][query][key]) -------------
__global__ void bias_kernel(const float* __restrict__ rpb) {
    int n = blockIdx.x;    // query
    int m = threadIdx.x;   // key
    int nd = n >> 6, nh = (n >> 3) & 7, nw = n & 7;
    int md = m >> 6, mh = (m >> 3) & 7, mw = m & 7;
    int rpi = (nd - md + 1) * 225 + (nh - mh + 7) * 15 + (nw - mw + 7);
#pragma unroll
    for (int h = 0; h < NH_; h++)
        g_bias[((long)h * NN_ + n) * NN_ + m] = rpb[rpi * NH_ + h];
}

// ---------------- K3: tensor-core attention, CTA=(window,head), 8 warps ----------
#define VPAD 136
__global__ void __launch_bounds__(256) attn_kernel() {
    __shared__ half sVt[16 * VPAD];
    __shared__ int  lab[NN_];

    int bw = blockIdx.x >> 3;
    int h  = blockIdx.x & 7;
    int tid = threadIdx.x, wid = tid >> 5, lane = tid & 31;
    int g = lane >> 2, t = lane & 3;
    long tokbase = (long)bw * 128;
    const half* Qp = g_qkvh + ((long)h * NTOK + tokbase) * 16;
    const half* Kp = g_qkvh + ((long)(8 + h) * NTOK + tokbase) * 16;
    const half* Vp = g_qkvh + ((long)(16 + h) * NTOK + tokbase) * 16;

    // stage V^T (dim-major) into smem — fully coalesced reads
    {
        int tok = tid >> 1;
        int d0  = (tid & 1) * 8;
        uint4 hv = *(const uint4*)(Vp + tok * 16 + d0);
        const half* hp = (const half*)&hv;
#pragma unroll
        for (int d = 0; d < 8; d++)
            sVt[(d0 + d) * VPAD + tok] = hp[d];
    }
    if (tid < 128) {
        int wi = bw & 255;
        int sd = (wi >> 6) * 2 + (tid >> 6);
        int sh = ((wi >> 3) & 7) * 8 + ((tid >> 3) & 7);
        int sw = (wi & 7) * 8 + (tid & 7);
        int ld = sd < 6 ? 0 : (sd < 7 ? 1 : 2);
        int lh = sh < 56 ? 0 : (sh < 60 ? 1 : 2);
        int lw = sw < 56 ? 0 : (sw < 60 ? 1 : 2);
        lab[tid] = ld * 9 + lh * 3 + lw;
    }
    __syncthreads();

    // Q fragments (q pre-scaled by 0.25 in the QKV epilogue)
    int row0 = wid * 16;
    uint32_t qf[4];
    qf[0] = *(const uint32_t*)(Qp + (row0 + g) * 16 + 2 * t);
    qf[1] = *(const uint32_t*)(Qp + (row0 + g + 8) * 16 + 2 * t);
    qf[2] = *(const uint32_t*)(Qp + (row0 + g) * 16 + 2 * t + 8);
    qf[3] = *(const uint32_t*)(Qp + (row0 + g + 8) * 16 + 2 * t + 8);

    // QK^T
    float acc[16][4];
#pragma unroll
    for (int j = 0; j < 16; j++) {
        uint32_t kf[2];
        kf[0] = *(const uint32_t*)(Kp + (8 * j + g) * 16 + 2 * t);
        kf[1] = *(const uint32_t*)(Kp + (8 * j + g) * 16 + 2 * t + 8);
        acc[j][0] = acc[j][1] = acc[j][2] = acc[j][3] = 0.0f;
        MMA(acc[j], qf, kf);
    }

    // bias + mask + exp + row sums
    int myl_g  = lab[row0 + g];
    int myl_g8 = lab[row0 + g + 8];
    const float* bptr = g_bias + (long)h * NN_ * NN_;
    float sum_g = 0.0f, sum_g8 = 0.0f;
#pragma unroll
    for (int j = 0; j < 16; j++) {
        int col = 8 * j + 2 * t;
        float2 bg  = *(const float2*)(bptr + (row0 + g) * NN_ + col);
        float2 bg8 = *(const float2*)(bptr + (row0 + g + 8) * NN_ + col);
        int l0 = lab[col], l1 = lab[col + 1];
        float e0 = (l0 == myl_g)  ? __expf(acc[j][0] + bg.x)  : 0.0f;
        float e1 = (l1 == myl_g)  ? __expf(acc[j][1] + bg.y)  : 0.0f;
        float e2 = (l0 == myl_g8) ? __expf(acc[j][2] + bg8.x) : 0.0f;
        float e3 = (l1 == myl_g8) ? __expf(acc[j][3] + bg8.y) : 0.0f;
        acc[j][0] = e0; acc[j][1] = e1; acc[j][2] = e2; acc[j][3] = e3;
        sum_g += e0 + e1; sum_g8 += e2 + e3;
    }
    sum_g  += __shfl_xor_sync(0xffffffffu, sum_g, 1);
    sum_g  += __shfl_xor_sync(0xffffffffu, sum_g, 2);
    sum_g8 += __shfl_xor_sync(0xffffffffu, sum_g8, 1);
    sum_g8 += __shfl_xor_sync(0xffffffffu, sum_g8, 2);
    float rs_g = 1.0f / sum_g, rs_g8 = 1.0f / sum_g8;

    // P @ V (P fragments chained from acc)
    float oacc[2][4];
#pragma unroll
    for (int nj = 0; nj < 2; nj++)
#pragma unroll
        for (int c = 0; c < 4; c++) oacc[nj][c] = 0.0f;

#pragma unroll
    for (int kt = 0; kt < 8; kt++) {
        float* p0 = acc[2 * kt];
        float* p1 = acc[2 * kt + 1];
        uint32_t pf[4];
        pf[0] = packh2(p0[0], p0[1]);
        pf[1] = packh2(p0[2], p0[3]);
        pf[2] = packh2(p1[0], p1[1]);
        pf[3] = packh2(p1[2], p1[3]);
#pragma unroll
        for (int nj = 0; nj < 2; nj++) {
            int vb = (8 * nj + g) * VPAD + 16 * kt + 2 * t;
            uint32_t vf[2];
            vf[0] = *(const uint32_t*)&sVt[vb];
            vf[1] = *(const uint32_t*)&sVt[vb + 8];
            MMA(oacc[nj], pf, vf);
        }
    }

    // output: normalize, store fp16 row-major [tok][128]
    long og  = (tokbase + row0 + g) * 128 + h * 16;
    long og8 = og + 8 * 128;
#pragma unroll
    for (int nj = 0; nj < 2; nj++) {
        int dn = 8 * nj + 2 * t;
        *(half2*)(g_attn + og + dn)  = __floats2half2_rn(oacc[nj][0] * rs_g,
                                                         oacc[nj][1] * rs_g);
        *(half2*)(g_attn + og8 + dn) = __floats2half2_rn(oacc[nj][2] * rs_g8,
                                                         oacc[nj][3] * rs_g8);
    }
}

// -------- K6: window-reverse + roll + residual + LN2 (-> x1 f32, xn2 fp16) -------
__global__ void scatter_ln2_kernel(const float* __restrict__ x,
                                   const float* __restrict__ g2,
                                   const float* __restrict__ b2) {
    int tk = (blockIdx.x * blockDim.x + threadIdx.x) >> 5;
    int lane = threadIdx.x & 31;
    if (tk >= NTOK) return;
    int w = tk & 63, h = (tk >> 6) & 63, d = (tk >> 12) & 7, bb = tk >> 15;
    int sd = (d + 7) & 7;
    int sh = (h + 60) & 63;
    int sw = (w + 60) & 63;
    int bw = bb * 256 + (sd >> 1) * 64 + (sh >> 3) * 8 + (sw >> 3);
    int n  = (sd & 1) * 64 + (sh & 7) * 8 + (sw & 7);

    float4 xv = *(const float4*)(x + (long)tk * C_ + lane * 4);
    float4 pv = *(const float4*)(g_projout + ((long)bw * NN_ + n) * C_ + lane * 4);
    float4 s1;
    s1.x = xv.x + pv.x; s1.y = xv.y + pv.y;
    s1.z = xv.z + pv.z; s1.w = xv.w + pv.w;
    *(float4*)(g_x1 + (long)tk * C_ + lane * 4) = s1;

    float s  = s1.x + s1.y + s1.z + s1.w;
    float sq = s1.x * s1.x + s1.y * s1.y + s1.z * s1.z + s1.w * s1.w;
#pragma unroll
    for (int o = 16; o > 0; o >>= 1) {
        s  += __shfl_xor_sync(0xffffffffu, s, o);
        sq += __shfl_xor_sync(0xffffffffu, sq, o);
    }
    float mean = s * (1.0f / C_);
    float var  = sq * (1.0f / C_) - mean * mean;
    float inv  = rsqrtf(var + 1e-5f);
    float4 gg = *(const float4*)(g2 + lane * 4);
    float4 bv = *(const float4*)(b2 + lane * 4);
    long o = (long)tk * C_ + lane * 4;
    *(half2*)(g_xn2 + o)     = __floats2half2_rn((s1.x - mean) * inv * gg.x + bv.x,
                                                 (s1.y - mean) * inv * gg.y + bv.y);
    *(half2*)(g_xn2 + o + 2) = __floats2half2_rn((s1.z - mean) * inv * gg.z + bv.z,
                                                 (s1.w - mean) * inv * gg.w + bv.w);
}

// ---------------------------------------------------------------------------
extern "C" void kernel_launch(void* const* d_in, const int* in_sizes, int n_in,
                              void* d_out, int out_size) {
    const float* x      = (const float*)d_in[0];
    const float* qkv_w  = (const float*)d_in[1];
    const float* qkv_b  = (const float*)d_in[2];
    const float* proj_w = (const float*)d_in[3];
    const float* proj_b = (const float*)d_in[4];
    const float* rpb    = (const float*)d_in[5];
    const float* ln1_g  = (const float*)d_in[6];
    const float* ln1_b  = (const float*)d_in[7];
    const float* ln2_g  = (const float*)d_in[8];
    const float* ln2_b  = (const float*)d_in[9];
    const float* fc1_w  = (const float*)d_in[10];
    const float* fc1_b  = (const float*)d_in[11];
    const float* fc2_w  = (const float*)d_in[12];
    const float* fc2_b  = (const float*)d_in[13];
    float* out = (float*)d_out;

    half *p_win, *p_qkvh, *p_attn, *p_xn2, *p_hid;
    half *p_qkvw, *p_projw, *p_fc1w, *p_fc2w;
    float *p_projout, *p_x1;
    cudaGetSymbolAddress((void**)&p_win,     g_win);
    cudaGetSymbolAddress((void**)&p_qkvh,    g_qkvh);
    cudaGetSymbolAddress((void**)&p_attn,    g_attn);
    cudaGetSymbolAddress((void**)&p_xn2,     g_xn2);
    cudaGetSymbolAddress((void**)&p_hid,     g_hid);
    cudaGetSymbolAddress((void**)&p_qkvw,    g_qkvw);
    cudaGetSymbolAddress((void**)&p_projw,   g_projw);
    cudaGetSymbolAddress((void**)&p_fc1w,    g_fc1w);
    cudaGetSymbolAddress((void**)&p_fc2w,    g_fc2w);
    cudaGetSymbolAddress((void**)&p_projout, g_projout);
    cudaGetSymbolAddress((void**)&p_x1,      g_x1);

    const int SMEM = 4 * 128 * PADK * 2;   // 73728 B (2 tiles x 2 stages)
    cudaFuncSetAttribute(mma_gemm<0, false, 2>, cudaFuncAttributeMaxDynamicSharedMemorySize, SMEM);
    cudaFuncSetAttribute(mma_gemm<0, false, 0>, cudaFuncAttributeMaxDynamicSharedMemorySize, SMEM);
    cudaFuncSetAttribute(mma_gemm<1, false, 1>, cudaFuncAttributeMaxDynamicSharedMemorySize, SMEM);
    cudaFuncSetAttribute(mma_gemm<0, true, 0>,  cudaFuncAttributeMaxDynamicSharedMemorySize, SMEM);

    // 0) weight convert + bias table
    convert_weights<<<256, 256>>>(qkv_w, proj_w, fc1_w, fc2_w);
    bias_kernel<<<128, 128>>>(rpb);

    // 1) LN1 + shift + partition
    ln_gather_kernel<<<8192, 256>>>(x, ln1_g, ln1_b);
    // 2) QKV GEMM -> head-major fp16 (q pre-scaled)
    mma_gemm<0, false, 2><<<dim3(3, 512), 256, SMEM>>>(
        p_win, p_qkvw, qkv_b, nullptr, nullptr, p_qkvh, 384, 128);
    // 3) attention (tensor cores)
    attn_kernel<<<NWIN * NH_, 256>>>();
    // 4) proj GEMM -> f32
    mma_gemm<0, false, 0><<<dim3(1, 512), 256, SMEM>>>(
        p_attn, p_projw, proj_b, nullptr, p_projout, nullptr, 128, 128);
    // 5) reverse + roll + residual + LN2
    scatter_ln2_kernel<<<8192, 256>>>(x, ln2_g, ln2_b);
    // 6) fc1 + GELU -> fp16
    mma_gemm<1, false, 1><<<dim3(4, 512), 256, SMEM>>>(
        p_xn2, p_fc1w, fc1_b, nullptr, nullptr, p_hid, 512, 128);
    // 7) fc2 + residual -> out (f32)
    mma_gemm<0, true, 0><<<dim3(1, 512), 256, SMEM>>>(
        p_hid, p_fc2w, fc2_b, p_x1, out, nullptr, 128, 512);
}

// round 9
// speedup vs baseline: 4.5383x; 1.1547x over previous
#include <cuda_runtime.h>
#include <cuda_fp16.h>
#include <math.h>
#include <stdint.h>

// Problem constants
#define B_    2
#define D_    8
#define C_    128
#define NH_   8
#define NTOK  65536
#define NWIN  512
#define NN_   128
#define MLPH  512

// ---------------- scratch (device globals) -----------------------------------
__device__ half  g_win[NTOK * C_];
__device__ half  g_qkvh[24LL * NTOK * 16];    // [part(3)][head(8)][tok][16]
__device__ float g_bias[NH_ * NN_ * NN_];     // [h][n(query)][m(key)]
__device__ half  g_attn[NTOK * C_];
__device__ float g_projout[NTOK * C_];
__device__ float g_x1[NTOK * C_];
__device__ half  g_xn2[NTOK * C_];
__device__ half  g_hid[(long)NTOK * MLPH];
// fp16 weights
__device__ half  g_qkvw[384 * C_];
__device__ half  g_projw[C_ * C_];
__device__ half  g_fc1w[MLPH * C_];
__device__ half  g_fc2w[C_ * MLPH];

__device__ __forceinline__ float gelu_exact(float x) {
    return 0.5f * x * (1.0f + erff(x * 0.70710678118654752f));
}

// ---- mma.sync m16n8k16 f16 -> f32 ------------------------------------------------
#define MMA(d, a, b)                                                            \
    asm volatile("mma.sync.aligned.m16n8k16.row.col.f32.f16.f16.f32 "           \
        "{%0,%1,%2,%3}, {%4,%5,%6,%7}, {%8,%9}, {%0,%1,%2,%3};"                 \
        : "+f"((d)[0]), "+f"((d)[1]), "+f"((d)[2]), "+f"((d)[3])                \
        : "r"((a)[0]), "r"((a)[1]), "r"((a)[2]), "r"((a)[3]),                    \
          "r"((b)[0]), "r"((b)[1]))

#define LDMX4(r, addr)                                                          \
    asm volatile("ldmatrix.sync.aligned.m8n8.x4.shared.b16 {%0,%1,%2,%3}, [%4];"\
        : "=r"((r)[0]), "=r"((r)[1]), "=r"((r)[2]), "=r"((r)[3]) : "r"(addr))
#define LDMX2(r, addr)                                                          \
    asm volatile("ldmatrix.sync.aligned.m8n8.x2.shared.b16 {%0,%1}, [%2];"      \
        : "=r"((r)[0]), "=r"((r)[1]) : "r"(addr))

__device__ __forceinline__ uint32_t packh2(float v0, float v1) {
    half2 h = __floats2half2_rn(v0, v1);
    return *(uint32_t*)&h;
}
__device__ __forceinline__ uint32_t smem_u32(const void* p) {
    uint32_t a;
    asm("{ .reg .u64 t; cvta.to.shared.u64 t, %1; cvt.u32.u64 %0, t; }" : "=r"(a) : "l"(p));
    return a;
}
__device__ __forceinline__ void cpa16(uint32_t d, const void* s) {
    asm volatile("cp.async.cg.shared.global [%0], [%1], 16;" :: "r"(d), "l"(s));
}
#define CP_COMMIT() asm volatile("cp.async.commit_group;" ::: "memory")
#define CP_WAIT0()  asm volatile("cp.async.wait_group 0;" ::: "memory")
#define CP_WAIT1()  asm volatile("cp.async.wait_group 1;" ::: "memory")

// ==================  GEMM: fp16, double-buffered BK=64 pipeline  ==================
// C[M,N] = act(A @ W^T + bias)(+res). BM=BN=128, 256 thr, warp 64x32, 2 CTAs/SM.
// OMODE: 0 = f32 row-major, 1 = fp16 row-major, 2 = fp16 head-major (QKV)
#define PADK 72
#define BUFB (128 * PADK * 2)     // bytes per stage per tile

template <int ACT, bool RES, int OMODE>
__global__ void __launch_bounds__(256, 2)
mma_gemm(const half* __restrict__ A, const half* __restrict__ W,
         const float* __restrict__ bias, const float* __restrict__ res,
         float* __restrict__ Cf, half* __restrict__ Chf,
         int N, int K) {
    extern __shared__ half smem[];
    half* sA = smem;                       // 2 stages
    half* sW = smem + 2 * 128 * PADK;      // 2 stages
    uint32_t sAu = smem_u32(sA), sWu = smem_u32(sW);

    int tid = threadIdx.x, wid = tid >> 5, lane = tid & 31;
    int g = lane >> 2, t = lane & 3;
    int m0 = blockIdx.y * 128, n0 = blockIdx.x * 128;
    int wm = (wid & 1) * 64, wn = (wid >> 1) * 32;

    float acc[4][4][4];
#pragma unroll
    for (int i = 0; i < 4; i++)
#pragma unroll
        for (int j = 0; j < 4; j++)
#pragma unroll
            for (int c = 0; c < 4; c++) acc[i][j][c] = 0.0f;

    // copy mapping: per tile 1024 uint4 -> 4/thread
    int crow = tid >> 3, cseg = (tid & 7) * 8;

    auto issue = [&](int kc, int buf) {
#pragma unroll
        for (int i = 0; i < 4; i++) {
            int row = crow + i * 32;
            uint32_t so = (uint32_t)buf * BUFB + (row * PADK + cseg) * 2;
            cpa16(sAu + so, A + (long)(m0 + row) * K + kc + cseg);
            cpa16(sWu + so, W + (long)(n0 + row) * K + kc + cseg);
        }
        CP_COMMIT();
    };

    // ldmatrix per-lane base addresses
    int lrow = lane & 7, lsel = lane >> 3;
    uint32_t aBase = sAu + ((wm + (lsel & 1) * 8 + lrow) * PADK + (lsel >> 1) * 8) * 2;
    uint32_t bBase = sWu + ((wn + lrow) * PADK + (lsel & 1) * 8) * 2;

    int nch = K >> 6;
    issue(0, 0);
    for (int c = 0; c < nch; c++) {
        if (c + 1 < nch) { issue((c + 1) << 6, (c + 1) & 1); CP_WAIT1(); }
        else             { CP_WAIT0(); }
        __syncthreads();
        uint32_t bofs = (uint32_t)(c & 1) * BUFB;
#pragma unroll
        for (int ks = 0; ks < 4; ks++) {
            uint32_t kb2 = ks * 32;        // 16 halves = 32 bytes
            uint32_t fa[4][4], fb[4][2];
#pragma unroll
            for (int mi = 0; mi < 4; mi++)
                LDMX4(fa[mi], aBase + bofs + mi * (16 * PADK * 2) + kb2);
#pragma unroll
            for (int nj = 0; nj < 4; nj++)
                LDMX2(fb[nj], bBase + bofs + nj * (8 * PADK * 2) + kb2);
#pragma unroll
            for (int mi = 0; mi < 4; mi++)
#pragma unroll
                for (int nj = 0; nj < 4; nj++)
                    MMA(acc[mi][nj], fa[mi], fb[nj]);
        }
        __syncthreads();
    }

    // epilogue
#pragma unroll
    for (int mi = 0; mi < 4; mi++) {
#pragma unroll
        for (int cr = 0; cr < 2; cr++) {
            int m = m0 + wm + mi * 16 + g + cr * 8;
#pragma unroll
            for (int nj = 0; nj < 4; nj++) {
                int n = n0 + wn + nj * 8 + 2 * t;
                float2 bb = *(const float2*)(bias + n);
                float v0 = acc[mi][nj][cr * 2 + 0] + bb.x;
                float v1 = acc[mi][nj][cr * 2 + 1] + bb.y;
                if (OMODE == 2 && n < 128) { v0 *= 0.25f; v1 *= 0.25f; }
                if (ACT == 1) { v0 = gelu_exact(v0); v1 = gelu_exact(v1); }
                if (RES) {
                    float2 r = *(const float2*)(res + (long)m * N + n);
                    v0 += r.x; v1 += r.y;
                }
                if (OMODE == 2) {
                    int p = n >> 7, hh = (n >> 4) & 7, d = n & 15;
                    long addr = ((long)(p * 8 + hh) * NTOK + m) * 16 + d;
                    *(half2*)(Chf + addr) = __floats2half2_rn(v0, v1);
                } else if (OMODE == 1) {
                    *(half2*)(Chf + (long)m * N + n) = __floats2half2_rn(v0, v1);
                } else {
                    float2 o; o.x = v0; o.y = v1;
                    *(float2*)(Cf + (long)m * N + n) = o;
                }
            }
        }
    }
}

// ---------------- weight convert (one launch) -----------------------------------
__global__ void convert_weights(const float* __restrict__ qkv_w,
                                const float* __restrict__ proj_w,
                                const float* __restrict__ fc1_w,
                                const float* __restrict__ fc2_w) {
    int i = blockIdx.x * blockDim.x + threadIdx.x;   // 0..65535
    if (i < 49152) g_qkvw[i] = __float2half(qkv_w[i]);
    if (i < 16384) g_projw[i] = __float2half(proj_w[i]);
    g_fc1w[i] = __float2half(fc1_w[i]);
    g_fc2w[i] = __float2half(fc2_w[i]);
}

// ---------------- K1: LN1 + cyclic shift + window partition (-> fp16) ------------
__global__ void ln_gather_kernel(const float* __restrict__ x,
                                 const float* __restrict__ g,
                                 const float* __restrict__ b) {
    int warp = (blockIdx.x * blockDim.x + threadIdx.x) >> 5;
    int lane = threadIdx.x & 31;
    if (warp >= NWIN * NN_) return;
    int bw = warp >> 7;
    int n  = warp & 127;
    int bb = bw >> 8;
    int wi = bw & 255;
    int wd = wi >> 6, wh = (wi >> 3) & 7, ww = wi & 7;
    int td = n >> 6,  th = (n >> 3) & 7, tw = n & 7;
    int gd = (wd * 2 + td + 1) & 7;
    int gh = (wh * 8 + th + 4) & 63;
    int gw = (ww * 8 + tw + 4) & 63;
    long src = (((long)(bb * D_ + gd) * 64 + gh) * 64 + gw) * C_;

    float4 v = *(const float4*)(x + src + lane * 4);
    float s  = v.x + v.y + v.z + v.w;
    float sq = v.x * v.x + v.y * v.y + v.z * v.z + v.w * v.w;
#pragma unroll
    for (int o = 16; o > 0; o >>= 1) {
        s  += __shfl_xor_sync(0xffffffffu, s, o);
        sq += __shfl_xor_sync(0xffffffffu, sq, o);
    }
    float mean = s * (1.0f / C_);
    float var  = sq * (1.0f / C_) - mean * mean;
    float inv  = rsqrtf(var + 1e-5f);
    float4 gg = *(const float4*)(g + lane * 4);
    float4 bv = *(const float4*)(b + lane * 4);
    long o = (long)warp * C_ + lane * 4;
    *(half2*)(g_win + o)     = __floats2half2_rn((v.x - mean) * inv * gg.x + bv.x,
                                                 (v.y - mean) * inv * gg.y + bv.y);
    *(half2*)(g_win + o + 2) = __floats2half2_rn((v.z - mean) * inv * gg.z + bv.z,
                                                 (v.w - mean) * inv * gg.w + bv.w);
}

// ---------------- K2: relative position bias table ([h][query][key]) -------------
__global__ void bias_kernel(const float* __restrict__ rpb) {
    int n = blockIdx.x;    // query
    int m = threadIdx.x;   // key
    int nd = n >> 6, nh = (n >> 3) & 7, nw = n & 7;
    int md = m >> 6, mh = (m >> 3) & 7, mw = m & 7;
    int rpi = (nd - md + 1) * 225 + (nh - mh + 7) * 15 + (nw - mw + 7);
#pragma unroll
    for (int h = 0; h < NH_; h++)
        g_bias[((long)h * NN_ + n) * NN_ + m] = rpb[rpi * NH_ + h];
}

// ---------------- K3: tensor-core attention, CTA=(window,head), 8 warps ----------
#define VPAD 136
__global__ void __launch_bounds__(256) attn_kernel() {
    __shared__ half sVt[16 * VPAD];
    __shared__ int  lab[NN_];

    int bw = blockIdx.x >> 3;
    int h  = blockIdx.x & 7;
    int tid = threadIdx.x, wid = tid >> 5, lane = tid & 31;
    int g = lane >> 2, t = lane & 3;
    long tokbase = (long)bw * 128;
    const half* Qp = g_qkvh + ((long)h * NTOK + tokbase) * 16;
    const half* Kp = g_qkvh + ((long)(8 + h) * NTOK + tokbase) * 16;
    const half* Vp = g_qkvh + ((long)(16 + h) * NTOK + tokbase) * 16;

    // stage V^T (dim-major) into smem — fully coalesced reads
    {
        int tok = tid >> 1;
        int d0  = (tid & 1) * 8;
        uint4 hv = *(const uint4*)(Vp + tok * 16 + d0);
        const half* hp = (const half*)&hv;
#pragma unroll
        for (int d = 0; d < 8; d++)
            sVt[(d0 + d) * VPAD + tok] = hp[d];
    }
    if (tid < 128) {
        int wi = bw & 255;
        int sd = (wi >> 6) * 2 + (tid >> 6);
        int sh = ((wi >> 3) & 7) * 8 + ((tid >> 3) & 7);
        int sw = (wi & 7) * 8 + (tid & 7);
        int ld = sd < 6 ? 0 : (sd < 7 ? 1 : 2);
        int lh = sh < 56 ? 0 : (sh < 60 ? 1 : 2);
        int lw = sw < 56 ? 0 : (sw < 60 ? 1 : 2);
        lab[tid] = ld * 9 + lh * 3 + lw;
    }
    __syncthreads();

    // Q fragments (q pre-scaled by 0.25 in the QKV epilogue)
    int row0 = wid * 16;
    uint32_t qf[4];
    qf[0] = *(const uint32_t*)(Qp + (row0 + g) * 16 + 2 * t);
    qf[1] = *(const uint32_t*)(Qp + (row0 + g + 8) * 16 + 2 * t);
    qf[2] = *(const uint32_t*)(Qp + (row0 + g) * 16 + 2 * t + 8);
    qf[3] = *(const uint32_t*)(Qp + (row0 + g + 8) * 16 + 2 * t + 8);

    // QK^T
    float acc[16][4];
#pragma unroll
    for (int j = 0; j < 16; j++) {
        uint32_t kf[2];
        kf[0] = *(const uint32_t*)(Kp + (8 * j + g) * 16 + 2 * t);
        kf[1] = *(const uint32_t*)(Kp + (8 * j + g) * 16 + 2 * t + 8);
        acc[j][0] = acc[j][1] = acc[j][2] = acc[j][3] = 0.0f;
        MMA(acc[j], qf, kf);
    }

    // bias + mask + exp + row sums
    int myl_g  = lab[row0 + g];
    int myl_g8 = lab[row0 + g + 8];
    const float* bptr = g_bias + (long)h * NN_ * NN_;
    float sum_g = 0.0f, sum_g8 = 0.0f;
#pragma unroll
    for (int j = 0; j < 16; j++) {
        int col = 8 * j + 2 * t;
        float2 bg  = *(const float2*)(bptr + (row0 + g) * NN_ + col);
        float2 bg8 = *(const float2*)(bptr + (row0 + g + 8) * NN_ + col);
        int l0 = lab[col], l1 = lab[col + 1];
        float e0 = (l0 == myl_g)  ? __expf(acc[j][0] + bg.x)  : 0.0f;
        float e1 = (l1 == myl_g)  ? __expf(acc[j][1] + bg.y)  : 0.0f;
        float e2 = (l0 == myl_g8) ? __expf(acc[j][2] + bg8.x) : 0.0f;
        float e3 = (l1 == myl_g8) ? __expf(acc[j][3] + bg8.y) : 0.0f;
        acc[j][0] = e0; acc[j][1] = e1; acc[j][2] = e2; acc[j][3] = e3;
        sum_g += e0 + e1; sum_g8 += e2 + e3;
    }
    sum_g  += __shfl_xor_sync(0xffffffffu, sum_g, 1);
    sum_g  += __shfl_xor_sync(0xffffffffu, sum_g, 2);
    sum_g8 += __shfl_xor_sync(0xffffffffu, sum_g8, 1);
    sum_g8 += __shfl_xor_sync(0xffffffffu, sum_g8, 2);
    float rs_g = 1.0f / sum_g, rs_g8 = 1.0f / sum_g8;

    // P @ V (P fragments chained from acc)
    float oacc[2][4];
#pragma unroll
    for (int nj = 0; nj < 2; nj++)
#pragma unroll
        for (int c = 0; c < 4; c++) oacc[nj][c] = 0.0f;

#pragma unroll
    for (int kt = 0; kt < 8; kt++) {
        float* p0 = acc[2 * kt];
        float* p1 = acc[2 * kt + 1];
        uint32_t pf[4];
        pf[0] = packh2(p0[0], p0[1]);
        pf[1] = packh2(p0[2], p0[3]);
        pf[2] = packh2(p1[0], p1[1]);
        pf[3] = packh2(p1[2], p1[3]);
#pragma unroll
        for (int nj = 0; nj < 2; nj++) {
            int vb = (8 * nj + g) * VPAD + 16 * kt + 2 * t;
            uint32_t vf[2];
            vf[0] = *(const uint32_t*)&sVt[vb];
            vf[1] = *(const uint32_t*)&sVt[vb + 8];
            MMA(oacc[nj], pf, vf);
        }
    }

    // output: normalize, store fp16 row-major [tok][128]
    long og  = (tokbase + row0 + g) * 128 + h * 16;
    long og8 = og + 8 * 128;
#pragma unroll
    for (int nj = 0; nj < 2; nj++) {
        int dn = 8 * nj + 2 * t;
        *(half2*)(g_attn + og + dn)  = __floats2half2_rn(oacc[nj][0] * rs_g,
                                                         oacc[nj][1] * rs_g);
        *(half2*)(g_attn + og8 + dn) = __floats2half2_rn(oacc[nj][2] * rs_g8,
                                                         oacc[nj][3] * rs_g8);
    }
}

// -------- K6: window-reverse + roll + residual + LN2 (-> x1 f32, xn2 fp16) -------
__global__ void scatter_ln2_kernel(const float* __restrict__ x,
                                   const float* __restrict__ g2,
                                   const float* __restrict__ b2) {
    int tk = (blockIdx.x * blockDim.x + threadIdx.x) >> 5;
    int lane = threadIdx.x & 31;
    if (tk >= NTOK) return;
    int w = tk & 63, h = (tk >> 6) & 63, d = (tk >> 12) & 7, bb = tk >> 15;
    int sd = (d + 7) & 7;
    int sh = (h + 60) & 63;
    int sw = (w + 60) & 63;
    int bw = bb * 256 + (sd >> 1) * 64 + (sh >> 3) * 8 + (sw >> 3);
    int n  = (sd & 1) * 64 + (sh & 7) * 8 + (sw & 7);

    float4 xv = *(const float4*)(x + (long)tk * C_ + lane * 4);
    float4 pv = *(const float4*)(g_projout + ((long)bw * NN_ + n) * C_ + lane * 4);
    float4 s1;
    s1.x = xv.x + pv.x; s1.y = xv.y + pv.y;
    s1.z = xv.z + pv.z; s1.w = xv.w + pv.w;
    *(float4*)(g_x1 + (long)tk * C_ + lane * 4) = s1;

    float s  = s1.x + s1.y + s1.z + s1.w;
    float sq = s1.x * s1.x + s1.y * s1.y + s1.z * s1.z + s1.w * s1.w;
#pragma unroll
    for (int o = 16; o > 0; o >>= 1) {
        s  += __shfl_xor_sync(0xffffffffu, s, o);
        sq += __shfl_xor_sync(0xffffffffu, sq, o);
    }
    float mean = s * (1.0f / C_);
    float var  = sq * (1.0f / C_) - mean * mean;
    float inv  = rsqrtf(var + 1e-5f);
    float4 gg = *(const float4*)(g2 + lane * 4);
    float4 bv = *(const float4*)(b2 + lane * 4);
    long o = (long)tk * C_ + lane * 4;
    *(half2*)(g_xn2 + o)     = __floats2half2_rn((s1.x - mean) * inv * gg.x + bv.x,
                                                 (s1.y - mean) * inv * gg.y + bv.y);
    *(half2*)(g_xn2 + o + 2) = __floats2half2_rn((s1.z - mean) * inv * gg.z + bv.z,
                                                 (s1.w - mean) * inv * gg.w + bv.w);
}

// ---------------------------------------------------------------------------
extern "C" void kernel_launch(void* const* d_in, const int* in_sizes, int n_in,
                              void* d_out, int out_size) {
    const float* x      = (const float*)d_in[0];
    const float* qkv_w  = (const float*)d_in[1];
    const float* qkv_b  = (const float*)d_in[2];
    const float* proj_w = (const float*)d_in[3];
    const float* proj_b = (const float*)d_in[4];
    const float* rpb    = (const float*)d_in[5];
    const float* ln1_g  = (const float*)d_in[6];
    const float* ln1_b  = (const float*)d_in[7];
    const float* ln2_g  = (const float*)d_in[8];
    const float* ln2_b  = (const float*)d_in[9];
    const float* fc1_w  = (const float*)d_in[10];
    const float* fc1_b  = (const float*)d_in[11];
    const float* fc2_w  = (const float*)d_in[12];
    const float* fc2_b  = (const float*)d_in[13];
    float* out = (float*)d_out;

    half *p_win, *p_qkvh, *p_attn, *p_xn2, *p_hid;
    half *p_qkvw, *p_projw, *p_fc1w, *p_fc2w;
    float *p_projout, *p_x1;
    cudaGetSymbolAddress((void**)&p_win,     g_win);
    cudaGetSymbolAddress((void**)&p_qkvh,    g_qkvh);
    cudaGetSymbolAddress((void**)&p_attn,    g_attn);
    cudaGetSymbolAddress((void**)&p_xn2,     g_xn2);
    cudaGetSymbolAddress((void**)&p_hid,     g_hid);
    cudaGetSymbolAddress((void**)&p_qkvw,    g_qkvw);
    cudaGetSymbolAddress((void**)&p_projw,   g_projw);
    cudaGetSymbolAddress((void**)&p_fc1w,    g_fc1w);
    cudaGetSymbolAddress((void**)&p_fc2w,    g_fc2w);
    cudaGetSymbolAddress((void**)&p_projout, g_projout);
    cudaGetSymbolAddress((void**)&p_x1,      g_x1);

    const int SMEM = 4 * 128 * PADK * 2;   // 73728 B (2 tiles x 2 stages)
    cudaFuncSetAttribute(mma_gemm<0, false, 2>, cudaFuncAttributeMaxDynamicSharedMemorySize, SMEM);
    cudaFuncSetAttribute(mma_gemm<0, false, 0>, cudaFuncAttributeMaxDynamicSharedMemorySize, SMEM);
    cudaFuncSetAttribute(mma_gemm<1, false, 1>, cudaFuncAttributeMaxDynamicSharedMemorySize, SMEM);
    cudaFuncSetAttribute(mma_gemm<0, true, 0>,  cudaFuncAttributeMaxDynamicSharedMemorySize, SMEM);

    // 0) weight convert + bias table
    convert_weights<<<256, 256>>>(qkv_w, proj_w, fc1_w, fc2_w);
    bias_kernel<<<128, 128>>>(rpb);

    // 1) LN1 + shift + partition
    ln_gather_kernel<<<8192, 256>>>(x, ln1_g, ln1_b);
    // 2) QKV GEMM -> head-major fp16 (q pre-scaled)
    mma_gemm<0, false, 2><<<dim3(3, 512), 256, SMEM>>>(
        p_win, p_qkvw, qkv_b, nullptr, nullptr, p_qkvh, 384, 128);
    // 3) attention (tensor cores)
    attn_kernel<<<NWIN * NH_, 256>>>();
    // 4) proj GEMM -> f32
    mma_gemm<0, false, 0><<<dim3(1, 512), 256, SMEM>>>(
        p_attn, p_projw, proj_b, nullptr, p_projout, nullptr, 128, 128);
    // 5) reverse + roll + residual + LN2
    scatter_ln2_kernel<<<8192, 256>>>(x, ln2_g, ln2_b);
    // 6) fc1 + GELU -> fp16
    mma_gemm<1, false, 1><<<dim3(4, 512), 256, SMEM>>>(
        p_xn2, p_fc1w, fc1_b, nullptr, nullptr, p_hid, 512, 128);
    // 7) fc2 + residual -> out (f32)
    mma_gemm<0, true, 0><<<dim3(1, 512), 256, SMEM>>>(
        p_hid, p_fc2w, fc2_b, p_x1, out, nullptr, 128, 512);
}

// round 10
// speedup vs baseline: 4.5441x; 1.0013x over previous
#include <cuda_runtime.h>
#include <cuda_fp16.h>
#include <math.h>
#include <stdint.h>

// Problem constants
#define B_    2
#define D_    8
#define C_    128
#define NH_   8
#define NTOK  65536
#define NWIN  512
#define NN_   128
#define MLPH  512

// ---------------- scratch (device globals) -----------------------------------
__device__ half  g_win[NTOK * C_];
__device__ half  g_qkvh[24LL * NTOK * 16];    // [part(3)][head(8)][tok][16]
__device__ float g_bias[NH_ * NN_ * NN_];     // [h][n(query)][m(key)]
__device__ half  g_attn[NTOK * C_];
__device__ float g_projout[NTOK * C_];
__device__ float g_x1[NTOK * C_];
__device__ half  g_xn2[NTOK * C_];
__device__ half  g_hid[(long)NTOK * MLPH];
// fp16 weights
__device__ half  g_qkvw[384 * C_];
__device__ half  g_projw[C_ * C_];
__device__ half  g_fc1w[MLPH * C_];
__device__ half  g_fc2w[C_ * MLPH];

__device__ __forceinline__ float gelu_exact(float x) {
    return 0.5f * x * (1.0f + erff(x * 0.70710678118654752f));
}

// ---- mma.sync m16n8k16 f16 -> f32 ------------------------------------------------
#define MMA(d, a, b)                                                            \
    asm volatile("mma.sync.aligned.m16n8k16.row.col.f32.f16.f16.f32 "           \
        "{%0,%1,%2,%3}, {%4,%5,%6,%7}, {%8,%9}, {%0,%1,%2,%3};"                 \
        : "+f"((d)[0]), "+f"((d)[1]), "+f"((d)[2]), "+f"((d)[3])                \
        : "r"((a)[0]), "r"((a)[1]), "r"((a)[2]), "r"((a)[3]),                    \
          "r"((b)[0]), "r"((b)[1]))

#define LDMX4(r, addr)                                                          \
    asm volatile("ldmatrix.sync.aligned.m8n8.x4.shared.b16 {%0,%1,%2,%3}, [%4];"\
        : "=r"((r)[0]), "=r"((r)[1]), "=r"((r)[2]), "=r"((r)[3]) : "r"(addr))
#define LDMX2(r, addr)                                                          \
    asm volatile("ldmatrix.sync.aligned.m8n8.x2.shared.b16 {%0,%1}, [%2];"      \
        : "=r"((r)[0]), "=r"((r)[1]) : "r"(addr))

__device__ __forceinline__ uint32_t packh2(float v0, float v1) {
    half2 h = __floats2half2_rn(v0, v1);
    return *(uint32_t*)&h;
}
__device__ __forceinline__ uint32_t smem_u32(const void* p) {
    uint32_t a;
    asm("{ .reg .u64 t; cvta.to.shared.u64 t, %1; cvt.u32.u64 %0, t; }" : "=r"(a) : "l"(p));
    return a;
}
__device__ __forceinline__ void cpa16(uint32_t d, const void* s) {
    asm volatile("cp.async.cg.shared.global [%0], [%1], 16;" :: "r"(d), "l"(s));
}
#define CP_COMMIT() asm volatile("cp.async.commit_group;" ::: "memory")
#define CP_WAIT0()  asm volatile("cp.async.wait_group 0;" ::: "memory")
#define CP_WAIT1()  asm volatile("cp.async.wait_group 1;" ::: "memory")

// ==================  GEMM: fp16, double-buffered BK=64 pipeline  ==================
// C[M,N] = act(A @ W^T + bias)(+res). BM=BN=128, 256 thr, warp 64x32, 2 CTAs/SM.
// OMODE: 0 = f32 row-major, 1 = fp16 row-major, 2 = fp16 head-major (QKV)
#define PADK 72
#define BUFB (128 * PADK * 2)     // bytes per stage per tile

template <int ACT, bool RES, int OMODE>
__global__ void __launch_bounds__(256, 2)
mma_gemm(const half* __restrict__ A, const half* __restrict__ W,
         const float* __restrict__ bias, const float* __restrict__ res,
         float* __restrict__ Cf, half* __restrict__ Chf,
         int N, int K) {
    extern __shared__ half smem[];
    half* sA = smem;                       // 2 stages
    half* sW = smem + 2 * 128 * PADK;      // 2 stages
    uint32_t sAu = smem_u32(sA), sWu = smem_u32(sW);

    int tid = threadIdx.x, wid = tid >> 5, lane = tid & 31;
    int g = lane >> 2, t = lane & 3;
    int m0 = blockIdx.y * 128, n0 = blockIdx.x * 128;
    int wm = (wid & 1) * 64, wn = (wid >> 1) * 32;

    float acc[4][4][4];
#pragma unroll
    for (int i = 0; i < 4; i++)
#pragma unroll
        for (int j = 0; j < 4; j++)
#pragma unroll
            for (int c = 0; c < 4; c++) acc[i][j][c] = 0.0f;

    // copy mapping: per tile 1024 uint4 -> 4/thread
    int crow = tid >> 3, cseg = (tid & 7) * 8;

    auto issue = [&](int kc, int buf) {
#pragma unroll
        for (int i = 0; i < 4; i++) {
            int row = crow + i * 32;
            uint32_t so = (uint32_t)buf * BUFB + (row * PADK + cseg) * 2;
            cpa16(sAu + so, A + (long)(m0 + row) * K + kc + cseg);
            cpa16(sWu + so, W + (long)(n0 + row) * K + kc + cseg);
        }
        CP_COMMIT();
    };

    // ldmatrix per-lane base addresses
    int lrow = lane & 7, lsel = lane >> 3;
    uint32_t aBase = sAu + ((wm + (lsel & 1) * 8 + lrow) * PADK + (lsel >> 1) * 8) * 2;
    uint32_t bBase = sWu + ((wn + lrow) * PADK + (lsel & 1) * 8) * 2;

    int nch = K >> 6;
    issue(0, 0);
    for (int c = 0; c < nch; c++) {
        if (c + 1 < nch) { issue((c + 1) << 6, (c + 1) & 1); CP_WAIT1(); }
        else             { CP_WAIT0(); }
        __syncthreads();
        uint32_t bofs = (uint32_t)(c & 1) * BUFB;
#pragma unroll
        for (int ks = 0; ks < 4; ks++) {
            uint32_t kb2 = ks * 32;        // 16 halves = 32 bytes
            uint32_t fa[4][4], fb[4][2];
#pragma unroll
            for (int mi = 0; mi < 4; mi++)
                LDMX4(fa[mi], aBase + bofs + mi * (16 * PADK * 2) + kb2);
#pragma unroll
            for (int nj = 0; nj < 4; nj++)
                LDMX2(fb[nj], bBase + bofs + nj * (8 * PADK * 2) + kb2);
#pragma unroll
            for (int mi = 0; mi < 4; mi++)
#pragma unroll
                for (int nj = 0; nj < 4; nj++)
                    MMA(acc[mi][nj], fa[mi], fb[nj]);
        }
        __syncthreads();
    }

    // epilogue
#pragma unroll
    for (int mi = 0; mi < 4; mi++) {
#pragma unroll
        for (int cr = 0; cr < 2; cr++) {
            int m = m0 + wm + mi * 16 + g + cr * 8;
#pragma unroll
            for (int nj = 0; nj < 4; nj++) {
                int n = n0 + wn + nj * 8 + 2 * t;
                float2 bb = *(const float2*)(bias + n);
                float v0 = acc[mi][nj][cr * 2 + 0] + bb.x;
                float v1 = acc[mi][nj][cr * 2 + 1] + bb.y;
                if (OMODE == 2 && n < 128) { v0 *= 0.25f; v1 *= 0.25f; }
                if (ACT == 1) { v0 = gelu_exact(v0); v1 = gelu_exact(v1); }
                if (RES) {
                    float2 r = *(const float2*)(res + (long)m * N + n);
                    v0 += r.x; v1 += r.y;
                }
                if (OMODE == 2) {
                    int p = n >> 7, hh = (n >> 4) & 7, d = n & 15;
                    long addr = ((long)(p * 8 + hh) * NTOK + m) * 16 + d;
                    *(half2*)(Chf + addr) = __floats2half2_rn(v0, v1);
                } else if (OMODE == 1) {
                    *(half2*)(Chf + (long)m * N + n) = __floats2half2_rn(v0, v1);
                } else {
                    float2 o; o.x = v0; o.y = v1;
                    *(float2*)(Cf + (long)m * N + n) = o;
                }
            }
        }
    }
}

// ---------------- weight convert (one launch) -----------------------------------
__global__ void convert_weights(const float* __restrict__ qkv_w,
                                const float* __restrict__ proj_w,
                                const float* __restrict__ fc1_w,
                                const float* __restrict__ fc2_w) {
    int i = blockIdx.x * blockDim.x + threadIdx.x;   // 0..65535
    if (i < 49152) g_qkvw[i] = __float2half(qkv_w[i]);
    if (i < 16384) g_projw[i] = __float2half(proj_w[i]);
    g_fc1w[i] = __float2half(fc1_w[i]);
    g_fc2w[i] = __float2half(fc2_w[i]);
}

// ---------------- K1: LN1 + cyclic shift + window partition (-> fp16) ------------
__global__ void ln_gather_kernel(const float* __restrict__ x,
                                 const float* __restrict__ g,
                                 const float* __restrict__ b) {
    int warp = (blockIdx.x * blockDim.x + threadIdx.x) >> 5;
    int lane = threadIdx.x & 31;
    if (warp >= NWIN * NN_) return;
    int bw = warp >> 7;
    int n  = warp & 127;
    int bb = bw >> 8;
    int wi = bw & 255;
    int wd = wi >> 6, wh = (wi >> 3) & 7, ww = wi & 7;
    int td = n >> 6,  th = (n >> 3) & 7, tw = n & 7;
    int gd = (wd * 2 + td + 1) & 7;
    int gh = (wh * 8 + th + 4) & 63;
    int gw = (ww * 8 + tw + 4) & 63;
    long src = (((long)(bb * D_ + gd) * 64 + gh) * 64 + gw) * C_;

    float4 v = *(const float4*)(x + src + lane * 4);
    float s  = v.x + v.y + v.z + v.w;
    float sq = v.x * v.x + v.y * v.y + v.z * v.z + v.w * v.w;
#pragma unroll
    for (int o = 16; o > 0; o >>= 1) {
        s  += __shfl_xor_sync(0xffffffffu, s, o);
        sq += __shfl_xor_sync(0xffffffffu, sq, o);
    }
    float mean = s * (1.0f / C_);
    float var  = sq * (1.0f / C_) - mean * mean;
    float inv  = rsqrtf(var + 1e-5f);
    float4 gg = *(const float4*)(g + lane * 4);
    float4 bv = *(const float4*)(b + lane * 4);
    long o = (long)warp * C_ + lane * 4;
    *(half2*)(g_win + o)     = __floats2half2_rn((v.x - mean) * inv * gg.x + bv.x,
                                                 (v.y - mean) * inv * gg.y + bv.y);
    *(half2*)(g_win + o + 2) = __floats2half2_rn((v.z - mean) * inv * gg.z + bv.z,
                                                 (v.w - mean) * inv * gg.w + bv.w);
}

// ---------------- K2: relative position bias table ([h][query][key]) -------------
__global__ void bias_kernel(const float* __restrict__ rpb) {
    int n = blockIdx.x;    // query
    int m = threadIdx.x;   // key
    int nd = n >> 6, nh = (n >> 3) & 7, nw = n & 7;
    int md = m >> 6, mh = (m >> 3) & 7, mw = m & 7;
    int rpi = (nd - md + 1) * 225 + (nh - mh + 7) * 15 + (nw - mw + 7);
#pragma unroll
    for (int h = 0; h < NH_; h++)
        g_bias[((long)h * NN_ + n) * NN_ + m] = rpb[rpi * NH_ + h];
}

// ---------------- K3: tensor-core attention, CTA=(window,head), 8 warps ----------
#define VPAD 136
__global__ void __launch_bounds__(256) attn_kernel() {
    __shared__ half sVt[16 * VPAD];
    __shared__ int  lab[NN_];

    int bw = blockIdx.x >> 3;
    int h  = blockIdx.x & 7;
    int tid = threadIdx.x, wid = tid >> 5, lane = tid & 31;
    int g = lane >> 2, t = lane & 3;
    long tokbase = (long)bw * 128;
    const half* Qp = g_qkvh + ((long)h * NTOK + tokbase) * 16;
    const half* Kp = g_qkvh + ((long)(8 + h) * NTOK + tokbase) * 16;
    const half* Vp = g_qkvh + ((long)(16 + h) * NTOK + tokbase) * 16;

    // stage V^T (dim-major) into smem — fully coalesced reads
    {
        int tok = tid >> 1;
        int d0  = (tid & 1) * 8;
        uint4 hv = *(const uint4*)(Vp + tok * 16 + d0);
        const half* hp = (const half*)&hv;
#pragma unroll
        for (int d = 0; d < 8; d++)
            sVt[(d0 + d) * VPAD + tok] = hp[d];
    }
    if (tid < 128) {
        int wi = bw & 255;
        int sd = (wi >> 6) * 2 + (tid >> 6);
        int sh = ((wi >> 3) & 7) * 8 + ((tid >> 3) & 7);
        int sw = (wi & 7) * 8 + (tid & 7);
        int ld = sd < 6 ? 0 : (sd < 7 ? 1 : 2);
        int lh = sh < 56 ? 0 : (sh < 60 ? 1 : 2);
        int lw = sw < 56 ? 0 : (sw < 60 ? 1 : 2);
        lab[tid] = ld * 9 + lh * 3 + lw;
    }
    __syncthreads();

    // Q fragments (q pre-scaled by 0.25 in the QKV epilogue)
    int row0 = wid * 16;
    uint32_t qf[4];
    qf[0] = *(const uint32_t*)(Qp + (row0 + g) * 16 + 2 * t);
    qf[1] = *(const uint32_t*)(Qp + (row0 + g + 8) * 16 + 2 * t);
    qf[2] = *(const uint32_t*)(Qp + (row0 + g) * 16 + 2 * t + 8);
    qf[3] = *(const uint32_t*)(Qp + (row0 + g + 8) * 16 + 2 * t + 8);

    // QK^T
    float acc[16][4];
#pragma unroll
    for (int j = 0; j < 16; j++) {
        uint32_t kf[2];
        kf[0] = *(const uint32_t*)(Kp + (8 * j + g) * 16 + 2 * t);
        kf[1] = *(const uint32_t*)(Kp + (8 * j + g) * 16 + 2 * t + 8);
        acc[j][0] = acc[j][1] = acc[j][2] = acc[j][3] = 0.0f;
        MMA(acc[j], qf, kf);
    }

    // bias + mask + exp + row sums
    int myl_g  = lab[row0 + g];
    int myl_g8 = lab[row0 + g + 8];
    const float* bptr = g_bias + (long)h * NN_ * NN_;
    float sum_g = 0.0f, sum_g8 = 0.0f;
#pragma unroll
    for (int j = 0; j < 16; j++) {
        int col = 8 * j + 2 * t;
        float2 bg  = *(const float2*)(bptr + (row0 + g) * NN_ + col);
        float2 bg8 = *(const float2*)(bptr + (row0 + g + 8) * NN_ + col);
        int l0 = lab[col], l1 = lab[col + 1];
        float e0 = (l0 == myl_g)  ? __expf(acc[j][0] + bg.x)  : 0.0f;
        float e1 = (l1 == myl_g)  ? __expf(acc[j][1] + bg.y)  : 0.0f;
        float e2 = (l0 == myl_g8) ? __expf(acc[j][2] + bg8.x) : 0.0f;
        float e3 = (l1 == myl_g8) ? __expf(acc[j][3] + bg8.y) : 0.0f;
        acc[j][0] = e0; acc[j][1] = e1; acc[j][2] = e2; acc[j][3] = e3;
        sum_g += e0 + e1; sum_g8 += e2 + e3;
    }
    sum_g  += __shfl_xor_sync(0xffffffffu, sum_g, 1);
    sum_g  += __shfl_xor_sync(0xffffffffu, sum_g, 2);
    sum_g8 += __shfl_xor_sync(0xffffffffu, sum_g8, 1);
    sum_g8 += __shfl_xor_sync(0xffffffffu, sum_g8, 2);
    float rs_g = 1.0f / sum_g, rs_g8 = 1.0f / sum_g8;

    // P @ V (P fragments chained from acc)
    float oacc[2][4];
#pragma unroll
    for (int nj = 0; nj < 2; nj++)
#pragma unroll
        for (int c = 0; c < 4; c++) oacc[nj][c] = 0.0f;

#pragma unroll
    for (int kt = 0; kt < 8; kt++) {
        float* p0 = acc[2 * kt];
        float* p1 = acc[2 * kt + 1];
        uint32_t pf[4];
        pf[0] = packh2(p0[0], p0[1]);
        pf[1] = packh2(p0[2], p0[3]);
        pf[2] = packh2(p1[0], p1[1]);
        pf[3] = packh2(p1[2], p1[3]);
#pragma unroll
        for (int nj = 0; nj < 2; nj++) {
            int vb = (8 * nj + g) * VPAD + 16 * kt + 2 * t;
            uint32_t vf[2];
            vf[0] = *(const uint32_t*)&sVt[vb];
            vf[1] = *(const uint32_t*)&sVt[vb + 8];
            MMA(oacc[nj], pf, vf);
        }
    }

    // output: normalize, store fp16 row-major [tok][128]
    long og  = (tokbase + row0 + g) * 128 + h * 16;
    long og8 = og + 8 * 128;
#pragma unroll
    for (int nj = 0; nj < 2; nj++) {
        int dn = 8 * nj + 2 * t;
        *(half2*)(g_attn + og + dn)  = __floats2half2_rn(oacc[nj][0] * rs_g,
                                                         oacc[nj][1] * rs_g);
        *(half2*)(g_attn + og8 + dn) = __floats2half2_rn(oacc[nj][2] * rs_g8,
                                                         oacc[nj][3] * rs_g8);
    }
}

// -------- K6: window-reverse + roll + residual + LN2 (-> x1 f32, xn2 fp16) -------
__global__ void scatter_ln2_kernel(const float* __restrict__ x,
                                   const float* __restrict__ g2,
                                   const float* __restrict__ b2) {
    int tk = (blockIdx.x * blockDim.x + threadIdx.x) >> 5;
    int lane = threadIdx.x & 31;
    if (tk >= NTOK) return;
    int w = tk & 63, h = (tk >> 6) & 63, d = (tk >> 12) & 7, bb = tk >> 15;
    int sd = (d + 7) & 7;
    int sh = (h + 60) & 63;
    int sw = (w + 60) & 63;
    int bw = bb * 256 + (sd >> 1) * 64 + (sh >> 3) * 8 + (sw >> 3);
    int n  = (sd & 1) * 64 + (sh & 7) * 8 + (sw & 7);

    float4 xv = *(const float4*)(x + (long)tk * C_ + lane * 4);
    float4 pv = *(const float4*)(g_projout + ((long)bw * NN_ + n) * C_ + lane * 4);
    float4 s1;
    s1.x = xv.x + pv.x; s1.y = xv.y + pv.y;
    s1.z = xv.z + pv.z; s1.w = xv.w + pv.w;
    *(float4*)(g_x1 + (long)tk * C_ + lane * 4) = s1;

    float s  = s1.x + s1.y + s1.z + s1.w;
    float sq = s1.x * s1.x + s1.y * s1.y + s1.z * s1.z + s1.w * s1.w;
#pragma unroll
    for (int o = 16; o > 0; o >>= 1) {
        s  += __shfl_xor_sync(0xffffffffu, s, o);
        sq += __shfl_xor_sync(0xffffffffu, sq, o);
    }
    float mean = s * (1.0f / C_);
    float var  = sq * (1.0f / C_) - mean * mean;
    float inv  = rsqrtf(var + 1e-5f);
    float4 gg = *(const float4*)(g2 + lane * 4);
    float4 bv = *(const float4*)(b2 + lane * 4);
    long o = (long)tk * C_ + lane * 4;
    *(half2*)(g_xn2 + o)     = __floats2half2_rn((s1.x - mean) * inv * gg.x + bv.x,
                                                 (s1.y - mean) * inv * gg.y + bv.y);
    *(half2*)(g_xn2 + o + 2) = __floats2half2_rn((s1.z - mean) * inv * gg.z + bv.z,
                                                 (s1.w - mean) * inv * gg.w + bv.w);
}

// ---------------------------------------------------------------------------
extern "C" void kernel_launch(void* const* d_in, const int* in_sizes, int n_in,
                              void* d_out, int out_size) {
    const float* x      = (const float*)d_in[0];
    const float* qkv_w  = (const float*)d_in[1];
    const float* qkv_b  = (const float*)d_in[2];
    const float* proj_w = (const float*)d_in[3];
    const float* proj_b = (const float*)d_in[4];
    const float* rpb    = (const float*)d_in[5];
    const float* ln1_g  = (const float*)d_in[6];
    const float* ln1_b  = (const float*)d_in[7];
    const float* ln2_g  = (const float*)d_in[8];
    const float* ln2_b  = (const float*)d_in[9];
    const float* fc1_w  = (const float*)d_in[10];
    const float* fc1_b  = (const float*)d_in[11];
    const float* fc2_w  = (const float*)d_in[12];
    const float* fc2_b  = (const float*)d_in[13];
    float* out = (float*)d_out;

    half *p_win, *p_qkvh, *p_attn, *p_xn2, *p_hid;
    half *p_qkvw, *p_projw, *p_fc1w, *p_fc2w;
    float *p_projout, *p_x1;
    cudaGetSymbolAddress((void**)&p_win,     g_win);
    cudaGetSymbolAddress((void**)&p_qkvh,    g_qkvh);
    cudaGetSymbolAddress((void**)&p_attn,    g_attn);
    cudaGetSymbolAddress((void**)&p_xn2,     g_xn2);
    cudaGetSymbolAddress((void**)&p_hid,     g_hid);
    cudaGetSymbolAddress((void**)&p_qkvw,    g_qkvw);
    cudaGetSymbolAddress((void**)&p_projw,   g_projw);
    cudaGetSymbolAddress((void**)&p_fc1w,    g_fc1w);
    cudaGetSymbolAddress((void**)&p_fc2w,    g_fc2w);
    cudaGetSymbolAddress((void**)&p_projout, g_projout);
    cudaGetSymbolAddress((void**)&p_x1,      g_x1);

    const int SMEM = 4 * 128 * PADK * 2;   // 73728 B (2 tiles x 2 stages)
    cudaFuncSetAttribute(mma_gemm<0, false, 2>, cudaFuncAttributeMaxDynamicSharedMemorySize, SMEM);
    cudaFuncSetAttribute(mma_gemm<0, false, 0>, cudaFuncAttributeMaxDynamicSharedMemorySize, SMEM);
    cudaFuncSetAttribute(mma_gemm<1, false, 1>, cudaFuncAttributeMaxDynamicSharedMemorySize, SMEM);
    cudaFuncSetAttribute(mma_gemm<0, true, 0>,  cudaFuncAttributeMaxDynamicSharedMemorySize, SMEM);

    // 0) weight convert + bias table
    convert_weights<<<256, 256>>>(qkv_w, proj_w, fc1_w, fc2_w);
    bias_kernel<<<128, 128>>>(rpb);

    // 1) LN1 + shift + partition
    ln_gather_kernel<<<8192, 256>>>(x, ln1_g, ln1_b);
    // 2) QKV GEMM -> head-major fp16 (q pre-scaled)
    mma_gemm<0, false, 2><<<dim3(3, 512), 256, SMEM>>>(
        p_win, p_qkvw, qkv_b, nullptr, nullptr, p_qkvh, 384, 128);
    // 3) attention (tensor cores)
    attn_kernel<<<NWIN * NH_, 256>>>();
    // 4) proj GEMM -> f32
    mma_gemm<0, false, 0><<<dim3(1, 512), 256, SMEM>>>(
        p_attn, p_projw, proj_b, nullptr, p_projout, nullptr, 128, 128);
    // 5) reverse + roll + residual + LN2
    scatter_ln2_kernel<<<8192, 256>>>(x, ln2_g, ln2_b);
    // 6) fc1 + GELU -> fp16
    mma_gemm<1, false, 1><<<dim3(4, 512), 256, SMEM>>>(
        p_xn2, p_fc1w, fc1_b, nullptr, nullptr, p_hid, 512, 128);
    // 7) fc2 + residual -> out (f32)
    mma_gemm<0, true, 0><<<dim3(1, 512), 256, SMEM>>>(
        p_hid, p_fc2w, fc2_b, p_x1, out, nullptr, 128, 512);
}